// round 9
// baseline (speedup 1.0000x reference)
#include <cuda_runtime.h>
#include <cuda_bf16.h>
#include <math.h>
#include <stdint.h>

// B=4, T=1024, C=2048, NH=16, HS=128, NLQ=512, NLKV=512, DHR=64
// scale = 1/sqrt(192)

// tcgen05 is arch-SPECIFIC (sm_103a / sm_100a). The harness also builds a
// compute_103 PTX pass where those instructions are illegal; compile an empty
// stub there. The sm_103a SASS (exact match, preferred by the loader) has the
// real body.
#if !defined(__CUDA_ARCH__) || defined(__CUDA_ARCH_SPECIFIC__) || \
    defined(__CUDA_ARCH_FEAT_SM103_ALL) || defined(__CUDA_ARCH_FEAT_SM100_ALL) || \
    defined(__CUDA_ARCH_FEAT_SM101_ALL)
#define HAS_TC 1
#else
#define HAS_TC 0
#endif

// ---------------- scratch (device globals; [2][..] = bf16 hi/lo planes) --------
__device__ __nv_bfloat16 g_x2[2][4096L * 2048];
__device__ __nv_bfloat16 g_wcat2[2][640L * 2048];     // [W_dq ; W_kr ; pad]
__device__ __nv_bfloat16 g_wdkv2[2][512L * 2048];
__device__ __nv_bfloat16 g_wqr2[2][1024L * 512];
__device__ __nv_bfloat16 g_wuqT2[2][2048L * 512];     // Wuq_flat^T
__device__ __nv_bfloat16 g_wuk2[2][2048L * 512];
__device__ __nv_bfloat16 g_wuvT2[2][512L * 2048];     // Wuv_flat^T
__device__ __nv_bfloat16 g_wo2[2][2048L * 2048];
__device__ __nv_bfloat16 g_mt2[2][2048L * 512];       // M^T = Wo @ Wuv
__device__ __nv_bfloat16 g_cqx2[2][4096L * 640];      // [c_q | c_kr | pad]
__device__ float         g_cqx_f[4096L * 640];
__device__ float         g_cqr[4096L * 1024];
__device__ __nv_bfloat16 g_qh2[2][64L * 1024 * 192];  // per-head [q_c | q_r]
__device__ __nv_bfloat16 g_kh2[2][64L * 1024 * 192];  // per-head [k_c | k_r]
__device__ __nv_bfloat16 g_kcat2[2][4096L * 512];     // c_kv
__device__ __nv_bfloat16 g_vt2[2][64L * 128 * 1024];  // V^T per (b,h)
__device__ float         g_logits[64L * 1024 * 1024];
__device__ __nv_bfloat16 g_p2[2][64L * 1024 * 1024];  // P hi/lo

// ---------------- PTX helpers ---------------------------------------------------
__device__ __forceinline__ uint32_t elect1() {
    uint32_t p;
    asm volatile("{\n\t.reg .pred p;\n\telect.sync _|p, 0xFFFFFFFF;\n\t"
                 "selp.b32 %0, 1, 0, p;\n\t}" : "=r"(p));
    return p;
}
__device__ __forceinline__ uint32_t s2u(const void* p) {
    uint32_t a;
    asm("{ .reg .u64 t; cvta.to.shared.u64 t, %1; cvt.u32.u64 %0, t; }" : "=r"(a) : "l"(p));
    return a;
}
#define TC_ALLOC(sm, n)  asm volatile("tcgen05.alloc.cta_group::1.sync.aligned.shared::cta.b32 [%0], %1;" :: "r"(sm), "r"(n) : "memory")
#define TC_DEALLOC(t, n) asm volatile("tcgen05.dealloc.cta_group::1.sync.aligned.b32 %0, %1;" :: "r"(t), "r"(n))
#define TC_RELINQ()      asm volatile("tcgen05.relinquish_alloc_permit.cta_group::1.sync.aligned;")
#define TC_COMMIT(mb)    asm volatile("tcgen05.commit.cta_group::1.mbarrier::arrive::one.shared::cluster.b64 [%0];" :: "r"(mb) : "memory")
#define TC_FENCE_AFTER() asm volatile("tcgen05.fence::after_thread_sync;" ::: "memory")
#define TC_WAIT_LD()     asm volatile("tcgen05.wait::ld.sync.aligned;" ::: "memory")
#define FENCE_PROXY()    asm volatile("fence.proxy.async.shared::cta;" ::: "memory")
#define MB_INIT(mb, c)   asm volatile("mbarrier.init.shared.b64 [%0], %1;" :: "r"(mb), "r"(c) : "memory")
#define MB_WAIT(mb, ph) do { \
    asm volatile("{\n\t.reg .pred P1;\n\tWL_%=:\n\t" \
        "mbarrier.try_wait.parity.acquire.cta.shared::cta.b64 P1, [%0], %1, 0x989680;\n\t" \
        "@P1 bra.uni WD_%=;\n\tbra.uni WL_%=;\n\tWD_%=:\n\t}" \
        :: "r"(mb), "r"((uint32_t)(ph)) : "memory"); \
} while (0)
#define CP16(dst, src)   asm volatile("cp.async.cg.shared.global [%0], [%1], 16;" :: "r"(dst), "l"(src))
#define CP_COMMIT()      asm volatile("cp.async.commit_group;")
#define CP_WAIT(n)       asm volatile("cp.async.wait_group %0;" :: "n"(n))

#define TCLD32(r, a) \
    asm volatile("tcgen05.ld.sync.aligned.32x32b.x32.b32 " \
        "{%0,%1,%2,%3,%4,%5,%6,%7,%8,%9,%10,%11,%12,%13,%14,%15," \
        "%16,%17,%18,%19,%20,%21,%22,%23,%24,%25,%26,%27,%28,%29,%30,%31}, [%32];" \
        : "=r"((r)[0]),"=r"((r)[1]),"=r"((r)[2]),"=r"((r)[3]),"=r"((r)[4]),"=r"((r)[5]), \
          "=r"((r)[6]),"=r"((r)[7]),"=r"((r)[8]),"=r"((r)[9]),"=r"((r)[10]),"=r"((r)[11]), \
          "=r"((r)[12]),"=r"((r)[13]),"=r"((r)[14]),"=r"((r)[15]),"=r"((r)[16]),"=r"((r)[17]), \
          "=r"((r)[18]),"=r"((r)[19]),"=r"((r)[20]),"=r"((r)[21]),"=r"((r)[22]),"=r"((r)[23]), \
          "=r"((r)[24]),"=r"((r)[25]),"=r"((r)[26]),"=r"((r)[27]),"=r"((r)[28]),"=r"((r)[29]), \
          "=r"((r)[30]),"=r"((r)[31]) : "r"(a))

#if HAS_TC
__device__ __forceinline__ void mma_bf16_ss(uint32_t d, uint64_t a, uint64_t b,
                                            uint32_t idesc, bool en) {
    uint32_t e = en ? 1u : 0u;
    asm volatile("{\n\t.reg .pred p;\n\tsetp.ne.u32 p, %5, 0;\n\t"
        "tcgen05.mma.cta_group::1.kind::f16 [%0], %1, %2, %3, {%4, %4, %4, %4}, p;\n\t}"
        :: "r"(d), "l"(a), "l"(b), "r"(idesc), "r"(0u), "r"(e) : "memory");
}
#endif

// idesc: dtype F32, atype/btype BF16, N=128, M=128
#define IDESC 0x8200490u
// SW128 K-major descriptor base: layout=2, version=1, SBO=64, LBO=1
#define DESC_BASE ((2ULL << 61) | (1ULL << 46) | (64ULL << 32) | (1ULL << 16))
__device__ __forceinline__ uint64_t mkdesc(uint32_t addr) {
    return DESC_BASE | ((uint64_t)(addr >> 4) & 0x3FFF);
}
__device__ __forceinline__ uint32_t sw128(uint32_t b) { return b ^ ((b >> 3) & 0x70); }

__device__ __forceinline__ void bsplit(float v, __nv_bfloat16& h, __nv_bfloat16& l) {
    h = __float2bfloat16_rn(v);
    l = __float2bfloat16_rn(v - __bfloat162float(h));
}

// ---------------- tcgen05 GEMM: D = A @ B^T (A: MxK, B: NxK, both K-major) ------
// bf16 2-term split: D = Ah*Bh + Ah*Bl + Al*Bh, fp32 accum in TMEM.
// Tile 128x128, K-chunk 64, 2-stage cp.async double buffer, 256 threads.
// MODE: 0 plain, 1 causal tile-skip (n0>m0), 2 causal K-limit (Keff=m0+128).
#define SM_DATA 1024
#define PLANE_B 16384           // 128 rows x 64 bf16 = 16KB per plane
#define STAGE_B (4 * PLANE_B)   // Ah, Al, Bh, Bl
#define GSMEM (SM_DATA + 2 * STAGE_B)   // 132096 B

template <int MODE, bool WF32, bool WB16, bool HEADC>
__global__ void __launch_bounds__(256, 1) gemm_t5(
        const __nv_bfloat16* __restrict__ A, long long aPl,
        const __nv_bfloat16* __restrict__ B, long long bPl,
        float* __restrict__ Cf, __nv_bfloat16* __restrict__ Cb, long long cPl,
        int K, int lda, int ldb, int ldc,
        long long sAq, long long sAr, long long sBq, long long sBr,
        long long sCq, long long sCr, int zdiv, long long sHC) {
#if HAS_TC
    const int m0 = blockIdx.y * 128;
    const int n0 = blockIdx.x * 128;
    if (MODE == 1 && n0 > m0) return;

    const int z = blockIdx.z;
    const int zq = z / zdiv, zr = z % zdiv;
    A += (long long)zq * sAq + (long long)zr * sAr;
    B += (long long)zq * sBq + (long long)zr * sBr;
    if (WF32) Cf += (long long)zq * sCq + (long long)zr * sCr + (HEADC ? (long long)blockIdx.x * sHC : 0);
    if (WB16) Cb += (long long)zq * sCq + (long long)zr * sCr + (HEADC ? (long long)blockIdx.x * sHC : 0);

    const int Keff = (MODE == 2) ? ((m0 + 128 < K) ? m0 + 128 : K) : K;
    const int nt = Keff >> 6;

    extern __shared__ __align__(1024) char smem[];
    const uint32_t smb = s2u(smem);
    const uint32_t mb0 = smb + 16, mb1 = smb + 24;

    const int tid = threadIdx.x;
    const int warp = tid >> 5;
    const int lane = tid & 31;

    if (warp == 0) TC_ALLOC(smb, 128);
    if (tid == 0) { MB_INIT(mb0, 1); MB_INIT(mb1, 1); }
    __syncthreads();
    uint32_t tmem;
    asm volatile("ld.shared.b32 %0, [%1];" : "=r"(tmem) : "r"(smb));

    auto issue_load = [&](int t) {
        const uint32_t st = smb + SM_DATA + (t & 1) * STAGE_B;
        const int k0 = t << 6;
#pragma unroll
        for (int i = 0; i < 16; i++) {
            int idx = tid + i * 256;        // 0..4095 chunks of 16B
            int plane = idx >> 10;          // 0:Ah 1:Al 2:Bh 3:Bl
            int c = idx & 1023;
            int r = c >> 3, cc = c & 7;
            uint32_t dst = st + plane * PLANE_B + sw128(r * 128 + cc * 16);
            const __nv_bfloat16* src;
            if (plane < 2) src = A + (long long)plane * aPl + (long long)(m0 + r) * lda + k0 + cc * 8;
            else           src = B + (long long)(plane - 2) * bPl + (long long)(n0 + r) * ldb + k0 + cc * 8;
            CP16(dst, src);
        }
        CP_COMMIT();
    };

    issue_load(0);
    if (nt > 1) issue_load(1);

    int ph0 = 0, ph1 = 0;
    for (int t = 0; t < nt; t++) {
        const int s = t & 1;
        if (t + 1 < nt) CP_WAIT(1); else CP_WAIT(0);
        __syncthreads();
        FENCE_PROXY();
        if (warp == 0 && elect1()) {
            const uint32_t st = smb + SM_DATA + s * STAGE_B;
            uint64_t dAh = mkdesc(st);
            uint64_t dAl = mkdesc(st + PLANE_B);
            uint64_t dBh = mkdesc(st + 2 * PLANE_B);
            uint64_t dBl = mkdesc(st + 3 * PLANE_B);
#pragma unroll
            for (int k = 0; k < 4; k++)
                mma_bf16_ss(tmem, dAh + 2 * k, dBh + 2 * k, IDESC, !(t == 0 && k == 0));
#pragma unroll
            for (int k = 0; k < 4; k++)
                mma_bf16_ss(tmem, dAh + 2 * k, dBl + 2 * k, IDESC, true);
#pragma unroll
            for (int k = 0; k < 4; k++)
                mma_bf16_ss(tmem, dAl + 2 * k, dBh + 2 * k, IDESC, true);
            TC_COMMIT(s ? mb1 : mb0);
        }
        if (t + 2 < nt) {
            if (s) { MB_WAIT(mb1, ph1); ph1 ^= 1; }
            else   { MB_WAIT(mb0, ph0); ph0 ^= 1; }
            issue_load(t + 2);
        }
    }
    if (nt >= 2) {
        const int s = (nt - 2) & 1;
        if (s) { MB_WAIT(mb1, ph1); ph1 ^= 1; }
        else   { MB_WAIT(mb0, ph0); ph0 ^= 1; }
    }
    {
        const int s = (nt - 1) & 1;
        if (s) { MB_WAIT(mb1, ph1); ph1 ^= 1; }
        else   { MB_WAIT(mb0, ph0); ph0 ^= 1; }
    }
    TC_FENCE_AFTER();

    // epilogue: warps 0-3 cols 0..63, warps 4-7 cols 64..127; rows (warp&3)*32+lane
    {
        const int row = m0 + (warp & 3) * 32 + lane;
        const int cb = (warp >> 2) * 64;
        uint32_t dr[32];
#pragma unroll
        for (int half = 0; half < 2; half++) {
            TCLD32(dr, tmem + cb + half * 32);
            TC_WAIT_LD();
            const int coff = (HEADC ? 0 : n0) + cb + half * 32;
#pragma unroll
            for (int c = 0; c < 32; c++) {
                float v = __uint_as_float(dr[c]);
                if (WF32) Cf[(long long)row * ldc + coff + c] = v;
                if (WB16) {
                    __nv_bfloat16 h, l; bsplit(v, h, l);
                    Cb[(long long)row * ldc + coff + c] = h;
                    Cb[(long long)row * ldc + coff + c + cPl] = l;
                }
            }
        }
    }
    __syncthreads();
    if (warp == 0) { TC_RELINQ(); TC_DEALLOC(tmem, 128); }
#endif  // HAS_TC
}

// ---------------- prep kernels ---------------------------------------------------
__global__ void split_copy(const float* __restrict__ in, __nv_bfloat16* __restrict__ out,
                           long long oPl, int n) {
    int i = blockIdx.x * blockDim.x + threadIdx.x;
    if (i >= n) return;
    __nv_bfloat16 h, l; bsplit(in[i], h, l);
    out[i] = h; out[i + oPl] = l;
}

__global__ void transpose_split(const float* __restrict__ in, __nv_bfloat16* __restrict__ out,
                                long long oPl, int R, int C) {
    __shared__ float tile[32][33];
    int bx = blockIdx.x * 32, by = blockIdx.y * 32;
    int tx = threadIdx.x, ty = threadIdx.y;
#pragma unroll
    for (int i = 0; i < 4; i++)
        tile[ty + i * 8][tx] = in[(long long)(by + ty + i * 8) * C + bx + tx];
    __syncthreads();
#pragma unroll
    for (int i = 0; i < 4; i++) {
        int c = bx + ty + i * 8, r = by + tx;
        __nv_bfloat16 h, l; bsplit(tile[tx][ty + i * 8], h, l);
        out[(long long)c * R + r] = h;
        out[(long long)c * R + r + oPl] = l;
    }
}

__global__ void build_wcat_split(const float* __restrict__ Wdq, const float* __restrict__ Wkr,
                                 __nv_bfloat16* __restrict__ out, long long oPl) {
    int i = blockIdx.x * blockDim.x + threadIdx.x;   // 640*2048
    if (i >= 640 * 2048) return;
    int row = i >> 11;
    float v = 0.0f;
    if (row < 512) v = Wdq[i];
    else if (row < 576) v = Wkr[(row - 512) * 2048 + (i & 2047)];
    __nv_bfloat16 h, l; bsplit(v, h, l);
    out[i] = h; out[i + oPl] = l;
}

// ---------------- rope (split-write into qh/kh tails) ----------------------------
__global__ void rope_q_kernel(const float* __restrict__ cqr, const float* __restrict__ fc,
                              const float* __restrict__ fs, __nv_bfloat16* __restrict__ qh,
                              long long qPl) {
    int idx = blockIdx.x * blockDim.x + threadIdx.x;  // B*T*NH*32
    if (idx >= 4 * 1024 * 16 * 32) return;
    int j = idx & 31;
    int h = (idx >> 5) & 15;
    int t = (idx >> 9) & 1023;
    int b = idx >> 19;
    long long src = (((long long)(b * 1024 + t)) * 1024) + h * 64 + 2 * j;
    float re = cqr[src], im = cqr[src + 1];
    float c = fc[t * 32 + j], s = fs[t * 32 + j];
    float o0 = re * c - im * s, o1 = re * s + im * c;
    long long dst = (((long long)(b * 16 + h)) * 1024 + t) * 192 + 128 + 2 * j;
    __nv_bfloat16 h0, l0, h1, l1; bsplit(o0, h0, l0); bsplit(o1, h1, l1);
    qh[dst] = h0; qh[dst + qPl] = l0;
    qh[dst + 1] = h1; qh[dst + 1 + qPl] = l1;
}

__global__ void rope_k_kernel(const float* __restrict__ cqx_f, const float* __restrict__ fc,
                              const float* __restrict__ fs, __nv_bfloat16* __restrict__ kh,
                              long long kPl) {
    int idx = blockIdx.x * blockDim.x + threadIdx.x;  // B*T*32
    if (idx >= 4 * 1024 * 32) return;
    int j = idx & 31;
    int t = (idx >> 5) & 1023;
    int b = idx >> 15;
    long long src = ((long long)(b * 1024 + t)) * 640 + 512 + 2 * j;
    float re = cqx_f[src], im = cqx_f[src + 1];
    float c = fc[t * 32 + j], s = fs[t * 32 + j];
    float o0 = re * c - im * s, o1 = re * s + im * c;
    __nv_bfloat16 h0, l0, h1, l1; bsplit(o0, h0, l0); bsplit(o1, h1, l1);
#pragma unroll
    for (int h = 0; h < 16; h++) {
        long long dst = (((long long)(b * 16 + h)) * 1024 + t) * 192 + 128 + 2 * j;
        kh[dst] = h0; kh[dst + kPl] = l0;
        kh[dst + 1] = h1; kh[dst + 1 + kPl] = l1;
    }
}

// ---------------- softmax: logits(f32) -> P hi/lo planes -------------------------
__global__ void __launch_bounds__(256) softmax_kernel(const float* __restrict__ L,
                                                      __nv_bfloat16* __restrict__ P,
                                                      long long pPl) {
    const int r = blockIdx.x;           // (b*NH + h)*T + t
    const int t = r & 1023;
    const float* row = L + (long long)r * 1024;
    __nv_bfloat16* prow = P + (long long)r * 1024;
    const float scale = 0.07216878364870323f;
    const int tid = threadIdx.x;        // 256
    const int lane = tid & 31, wid = tid >> 5;
    __shared__ float buf[1024];
    __shared__ float red[8];

    float m = -INFINITY;
#pragma unroll
    for (int i = 0; i < 4; i++) {
        int s = tid + i * 256;
        float v = (s <= t) ? row[s] * scale : -INFINITY;
        buf[s] = v;
        m = fmaxf(m, v);
    }
#pragma unroll
    for (int o = 16; o; o >>= 1) m = fmaxf(m, __shfl_xor_sync(~0u, m, o));
    if (lane == 0) red[wid] = m;
    __syncthreads();
    m = red[0];
#pragma unroll
    for (int w = 1; w < 8; w++) m = fmaxf(m, red[w]);

    float sum = 0.0f;
#pragma unroll
    for (int i = 0; i < 4; i++) {
        int s = tid + i * 256;
        float e = __expf(buf[s] - m);
        buf[s] = e;
        sum += e;
    }
#pragma unroll
    for (int o = 16; o; o >>= 1) sum += __shfl_xor_sync(~0u, sum, o);
    if (lane == 0) red[wid] = sum;
    __syncthreads();
    sum = red[0];
#pragma unroll
    for (int w = 1; w < 8; w++) sum += red[w];
    const float inv = 1.0f / sum;

    const int kmax = ((t >> 7) + 1) << 7;   // PV reads cols [0, m0+128)
#pragma unroll
    for (int i = 0; i < 4; i++) {
        int s = tid + i * 256;
        if (s < kmax) {
            float p = (s <= t) ? buf[s] * inv : 0.0f;
            __nv_bfloat16 h, l; bsplit(p, h, l);
            prow[s] = h; prow[s + pPl] = l;
        }
    }
}

// ---------------- launcher -------------------------------------------------------
extern "C" void kernel_launch(void* const* d_in, const int* in_sizes, int n_in,
                              void* d_out, int out_size) {
    (void)in_sizes; (void)n_in; (void)out_size;
    const float* x     = (const float*)d_in[0];
    const float* W_dq  = (const float*)d_in[1];
    const float* W_uq  = (const float*)d_in[2];
    const float* W_dkv = (const float*)d_in[3];
    const float* W_uk  = (const float*)d_in[4];
    const float* W_uv  = (const float*)d_in[5];
    const float* W_o   = (const float*)d_in[6];
    const float* W_qr  = (const float*)d_in[7];
    const float* W_kr  = (const float*)d_in[8];
    const float* fc    = (const float*)d_in[9];
    const float* fs    = (const float*)d_in[10];
    float* out = (float*)d_out;

    __nv_bfloat16 *x2, *wcat2, *wdkv2, *wqr2, *wuqT2, *wuk2, *wuvT2, *wo2, *mt2;
    __nv_bfloat16 *cqx2, *qh2, *kh2, *kcat2, *vt2, *p2;
    float *cqx_f, *cqr, *logits;
    cudaGetSymbolAddress((void**)&x2,     g_x2);
    cudaGetSymbolAddress((void**)&wcat2,  g_wcat2);
    cudaGetSymbolAddress((void**)&wdkv2,  g_wdkv2);
    cudaGetSymbolAddress((void**)&wqr2,   g_wqr2);
    cudaGetSymbolAddress((void**)&wuqT2,  g_wuqT2);
    cudaGetSymbolAddress((void**)&wuk2,   g_wuk2);
    cudaGetSymbolAddress((void**)&wuvT2,  g_wuvT2);
    cudaGetSymbolAddress((void**)&wo2,    g_wo2);
    cudaGetSymbolAddress((void**)&mt2,    g_mt2);
    cudaGetSymbolAddress((void**)&cqx2,   g_cqx2);
    cudaGetSymbolAddress((void**)&cqx_f,  g_cqx_f);
    cudaGetSymbolAddress((void**)&cqr,    g_cqr);
    cudaGetSymbolAddress((void**)&qh2,    g_qh2);
    cudaGetSymbolAddress((void**)&kh2,    g_kh2);
    cudaGetSymbolAddress((void**)&kcat2,  g_kcat2);
    cudaGetSymbolAddress((void**)&vt2,    g_vt2);
    cudaGetSymbolAddress((void**)&p2,     g_p2);
    cudaGetSymbolAddress((void**)&logits, g_logits);

    const long long XPL   = 4096LL * 2048;
    const long long WCPL  = 640LL * 2048;
    const long long WDPL  = 512LL * 2048;
    const long long WQRPL = 1024LL * 512;
    const long long WUQPL = 2048LL * 512;
    const long long WUKPL = 2048LL * 512;
    const long long WUVPL = 512LL * 2048;
    const long long WOPL  = 2048LL * 2048;
    const long long MTPL  = 2048LL * 512;
    const long long CQXPL = 4096LL * 640;
    const long long HPL   = 64LL * 1024 * 192;
    const long long KCPL  = 4096LL * 512;
    const long long VTPL  = 64LL * 128 * 1024;
    const long long PPL   = 64LL * 1024 * 1024;
    const long long HZ    = 1024LL * 192;
    const long long VTZ   = 128LL * 1024;
    const long long LZ    = 1024LL * 1024;

    cudaFuncSetAttribute(gemm_t5<0, true,  true,  false>, cudaFuncAttributeMaxDynamicSharedMemorySize, GSMEM);
    cudaFuncSetAttribute(gemm_t5<0, false, true,  false>, cudaFuncAttributeMaxDynamicSharedMemorySize, GSMEM);
    cudaFuncSetAttribute(gemm_t5<0, true,  false, false>, cudaFuncAttributeMaxDynamicSharedMemorySize, GSMEM);
    cudaFuncSetAttribute(gemm_t5<0, false, true,  true >, cudaFuncAttributeMaxDynamicSharedMemorySize, GSMEM);
    cudaFuncSetAttribute(gemm_t5<1, true,  false, false>, cudaFuncAttributeMaxDynamicSharedMemorySize, GSMEM);
    cudaFuncSetAttribute(gemm_t5<2, true,  false, false>, cudaFuncAttributeMaxDynamicSharedMemorySize, GSMEM);

    dim3 blk(256);

    // --- prep: split / transpose ---
    split_copy<<<(8388608 + 255) / 256, 256>>>(x,     x2,    XPL,   8388608);
    split_copy<<<(1048576 + 255) / 256, 256>>>(W_dkv, wdkv2, WDPL,  1048576);
    split_copy<<<(524288  + 255) / 256, 256>>>(W_qr,  wqr2,  WQRPL, 524288);
    split_copy<<<(1048576 + 255) / 256, 256>>>(W_uk,  wuk2,  WUKPL, 1048576);
    split_copy<<<(4194304 + 255) / 256, 256>>>(W_o,   wo2,   WOPL,  4194304);
    transpose_split<<<dim3(64, 16), dim3(32, 8)>>>(W_uq, wuqT2, WUQPL, 512, 2048);
    transpose_split<<<dim3(16, 64), dim3(32, 8)>>>(W_uv, wuvT2, WUVPL, 2048, 512);
    build_wcat_split<<<(640 * 2048 + 255) / 256, 256>>>(W_dq, W_kr, wcat2, WCPL);

    // 1) cqx (4096x640) = x @ Wcat^T      [f32 + planes]
    gemm_t5<0, true, true, false><<<dim3(5, 32, 1), blk, GSMEM>>>(
        x2, XPL, wcat2, WCPL, cqx_f, cqx2, CQXPL,
        2048, 2048, 2048, 640, 0, 0, 0, 0, 0, 0, 1, 0);

    // 2) c_kv (4096x512) = x @ W_dkv^T    [planes]
    gemm_t5<0, false, true, false><<<dim3(4, 32, 1), blk, GSMEM>>>(
        x2, XPL, wdkv2, WDPL, nullptr, kcat2, KCPL,
        2048, 2048, 2048, 512, 0, 0, 0, 0, 0, 0, 1, 0);

    // 3) MT (2048x512) = Wo @ WuvT^T      [planes]
    gemm_t5<0, false, true, false><<<dim3(4, 16, 1), blk, GSMEM>>>(
        wo2, WOPL, wuvT2, WUVPL, nullptr, mt2, MTPL,
        2048, 2048, 2048, 512, 0, 0, 0, 0, 0, 0, 1, 0);

    // 4) c_qr (4096x1024) = c_q @ W_qr^T  [f32]
    gemm_t5<0, true, false, false><<<dim3(8, 32, 1), blk, GSMEM>>>(
        cqx2, CQXPL, wqr2, WQRPL, cqr, nullptr, 0,
        512, 640, 512, 1024, 0, 0, 0, 0, 0, 0, 1, 0);

    // 5) q per head (1024x2048 head-sliced): qh[:, 0:128] = c_q[b] @ WuqT^T
    gemm_t5<0, false, true, true><<<dim3(16, 8, 4), blk, GSMEM>>>(
        cqx2, CQXPL, wuqT2, WUQPL, nullptr, qh2, HPL,
        512, 640, 512, 192,
        1024LL * 640, 0, 0, 0, 16LL * HZ, 0, 1, HZ);

    // 6) k per head: kh[:, 0:128] = c_kv[b] @ W_uk^T
    gemm_t5<0, false, true, true><<<dim3(16, 8, 4), blk, GSMEM>>>(
        kcat2, KCPL, wuk2, WUKPL, nullptr, kh2, HPL,
        512, 512, 512, 192,
        1024LL * 512, 0, 0, 0, 16LL * HZ, 0, 1, HZ);

    // 7) rope tails (split-write)
    rope_q_kernel<<<8192, 256>>>(cqr, fc, fs, qh2, HPL);
    rope_k_kernel<<<512, 256>>>(cqx_f, fc, fs, kh2, HPL);

    // 8) VT[b,h] (128x1024) = MT[h-slice] @ c_kv[b]^T   [planes]
    gemm_t5<0, false, true, false><<<dim3(8, 1, 64), blk, GSMEM>>>(
        mt2, MTPL, kcat2, KCPL, nullptr, vt2, VTPL,
        512, 512, 512, 1024,
        0, 128LL * 512, 1024LL * 512, 0, 16LL * VTZ, VTZ, 16, 0);

    // 9) logits[b,h] (1024x1024) = qh @ kh^T (K=192), causal tile-skip   [f32]
    gemm_t5<1, true, false, false><<<dim3(8, 8, 64), blk, GSMEM>>>(
        qh2, HPL, kh2, HPL, logits, nullptr, 0,
        192, 192, 192, 1024,
        16LL * HZ, HZ, 16LL * HZ, HZ, 16LL * LZ, LZ, 16, 0);

    // 10) softmax -> P planes
    softmax_kernel<<<65536, 256>>>(logits, p2, PPL);

    // 11) out[b,:,h*128:+128] = P[b,h] @ VT[b,h]^T (K-limit)   [f32]
    gemm_t5<2, true, false, false><<<dim3(1, 8, 64), blk, GSMEM>>>(
        p2, PPL, vt2, VTPL, out, nullptr, 0,
        1024, 1024, 1024, 2048,
        16LL * LZ, LZ, 16LL * VTZ, VTZ, 1024LL * 2048, 128, 16, 0);
}

// round 10
// speedup vs baseline: 1.1944x; 1.1944x over previous
#include <cuda_runtime.h>
#include <cuda_bf16.h>
#include <math.h>
#include <stdint.h>

// B=4, T=1024, C=2048, NH=16, HS=128, NLQ=512, NLKV=512, DHR=64
// scale = 1/sqrt(192)

#if !defined(__CUDA_ARCH__) || defined(__CUDA_ARCH_SPECIFIC__) || \
    defined(__CUDA_ARCH_FEAT_SM103_ALL) || defined(__CUDA_ARCH_FEAT_SM100_ALL) || \
    defined(__CUDA_ARCH_FEAT_SM101_ALL)
#define HAS_TC 1
#else
#define HAS_TC 0
#endif

// ---------------- scratch (device globals; [2][..] = bf16 hi/lo planes) --------
__device__ __nv_bfloat16 g_x2[2][4096L * 2048];
__device__ __nv_bfloat16 g_wcat2[2][640L * 2048];     // [W_dq ; W_kr ; pad]
__device__ __nv_bfloat16 g_wdkv2[2][512L * 2048];
__device__ __nv_bfloat16 g_wqr2[2][1024L * 512];
__device__ __nv_bfloat16 g_wuqT2[2][2048L * 512];     // Wuq_flat^T
__device__ __nv_bfloat16 g_wuk2[2][2048L * 512];
__device__ __nv_bfloat16 g_wuvT2[2][512L * 2048];     // Wuv_flat^T
__device__ __nv_bfloat16 g_wo2[2][2048L * 2048];
__device__ __nv_bfloat16 g_mt2[2][2048L * 512];       // M^T = Wo @ Wuv
__device__ __nv_bfloat16 g_cqx2[2][4096L * 640];      // [c_q | c_kr | pad]
__device__ float         g_cqx_f[4096L * 640];
__device__ float         g_cqr[4096L * 1024];
__device__ __nv_bfloat16 g_qh2[2][64L * 1024 * 192];  // per-head [q_c | q_r]
__device__ __nv_bfloat16 g_kh2[2][64L * 1024 * 192];  // per-head [k_c | k_r]
__device__ __nv_bfloat16 g_kcat2[2][4096L * 512];     // c_kv
__device__ __nv_bfloat16 g_vt2[2][64L * 128 * 1024];  // V^T per (b,h)

// ---------------- PTX helpers ---------------------------------------------------
__device__ __forceinline__ uint32_t elect1() {
    uint32_t p;
    asm volatile("{\n\t.reg .pred p;\n\telect.sync _|p, 0xFFFFFFFF;\n\t"
                 "selp.b32 %0, 1, 0, p;\n\t}" : "=r"(p));
    return p;
}
__device__ __forceinline__ uint32_t s2u(const void* p) {
    uint32_t a;
    asm("{ .reg .u64 t; cvta.to.shared.u64 t, %1; cvt.u32.u64 %0, t; }" : "=r"(a) : "l"(p));
    return a;
}
#define TC_ALLOC(sm, n)  asm volatile("tcgen05.alloc.cta_group::1.sync.aligned.shared::cta.b32 [%0], %1;" :: "r"(sm), "r"(n) : "memory")
#define TC_DEALLOC(t, n) asm volatile("tcgen05.dealloc.cta_group::1.sync.aligned.b32 %0, %1;" :: "r"(t), "r"(n))
#define TC_RELINQ()      asm volatile("tcgen05.relinquish_alloc_permit.cta_group::1.sync.aligned;")
#define TC_COMMIT(mb)    asm volatile("tcgen05.commit.cta_group::1.mbarrier::arrive::one.shared::cluster.b64 [%0];" :: "r"(mb) : "memory")
#define TC_FENCE_AFTER() asm volatile("tcgen05.fence::after_thread_sync;" ::: "memory")
#define TC_FENCE_BEFORE() asm volatile("tcgen05.fence::before_thread_sync;" ::: "memory")
#define TC_WAIT_LD()     asm volatile("tcgen05.wait::ld.sync.aligned;" ::: "memory")
#define TC_WAIT_ST()     asm volatile("tcgen05.wait::st.sync.aligned;" ::: "memory")
#define FENCE_PROXY()    asm volatile("fence.proxy.async.shared::cta;" ::: "memory")
#define MB_INIT(mb, c)   asm volatile("mbarrier.init.shared.b64 [%0], %1;" :: "r"(mb), "r"(c) : "memory")
#define MB_WAIT(mb, ph) do { \
    asm volatile("{\n\t.reg .pred P1;\n\tWL_%=:\n\t" \
        "mbarrier.try_wait.parity.acquire.cta.shared::cta.b64 P1, [%0], %1, 0x989680;\n\t" \
        "@P1 bra.uni WD_%=;\n\tbra.uni WL_%=;\n\tWD_%=:\n\t}" \
        :: "r"(mb), "r"((uint32_t)(ph)) : "memory"); \
} while (0)
#define CP16(dst, src)   asm volatile("cp.async.cg.shared.global [%0], [%1], 16;" :: "r"(dst), "l"(src))
#define CP_COMMIT()      asm volatile("cp.async.commit_group;")
#define CP_WAIT(n)       asm volatile("cp.async.wait_group %0;" :: "n"(n))

#define TCLD32(r, a) \
    asm volatile("tcgen05.ld.sync.aligned.32x32b.x32.b32 " \
        "{%0,%1,%2,%3,%4,%5,%6,%7,%8,%9,%10,%11,%12,%13,%14,%15," \
        "%16,%17,%18,%19,%20,%21,%22,%23,%24,%25,%26,%27,%28,%29,%30,%31}, [%32];" \
        : "=r"((r)[0]),"=r"((r)[1]),"=r"((r)[2]),"=r"((r)[3]),"=r"((r)[4]),"=r"((r)[5]), \
          "=r"((r)[6]),"=r"((r)[7]),"=r"((r)[8]),"=r"((r)[9]),"=r"((r)[10]),"=r"((r)[11]), \
          "=r"((r)[12]),"=r"((r)[13]),"=r"((r)[14]),"=r"((r)[15]),"=r"((r)[16]),"=r"((r)[17]), \
          "=r"((r)[18]),"=r"((r)[19]),"=r"((r)[20]),"=r"((r)[21]),"=r"((r)[22]),"=r"((r)[23]), \
          "=r"((r)[24]),"=r"((r)[25]),"=r"((r)[26]),"=r"((r)[27]),"=r"((r)[28]),"=r"((r)[29]), \
          "=r"((r)[30]),"=r"((r)[31]) : "r"(a))

#define TCST32(a, r) \
    asm volatile("tcgen05.st.sync.aligned.32x32b.x32.b32 [%0], " \
        "{%1,%2,%3,%4,%5,%6,%7,%8,%9,%10,%11,%12,%13,%14,%15,%16," \
        "%17,%18,%19,%20,%21,%22,%23,%24,%25,%26,%27,%28,%29,%30,%31,%32};" \
        :: "r"(a), \
          "r"((r)[0]),"r"((r)[1]),"r"((r)[2]),"r"((r)[3]),"r"((r)[4]),"r"((r)[5]), \
          "r"((r)[6]),"r"((r)[7]),"r"((r)[8]),"r"((r)[9]),"r"((r)[10]),"r"((r)[11]), \
          "r"((r)[12]),"r"((r)[13]),"r"((r)[14]),"r"((r)[15]),"r"((r)[16]),"r"((r)[17]), \
          "r"((r)[18]),"r"((r)[19]),"r"((r)[20]),"r"((r)[21]),"r"((r)[22]),"r"((r)[23]), \
          "r"((r)[24]),"r"((r)[25]),"r"((r)[26]),"r"((r)[27]),"r"((r)[28]),"r"((r)[29]), \
          "r"((r)[30]),"r"((r)[31]) : "memory")

#if HAS_TC
__device__ __forceinline__ void mma_bf16_ss(uint32_t d, uint64_t a, uint64_t b,
                                            uint32_t idesc, bool en) {
    uint32_t e = en ? 1u : 0u;
    asm volatile("{\n\t.reg .pred p;\n\tsetp.ne.u32 p, %5, 0;\n\t"
        "tcgen05.mma.cta_group::1.kind::f16 [%0], %1, %2, %3, {%4, %4, %4, %4}, p;\n\t}"
        :: "r"(d), "l"(a), "l"(b), "r"(idesc), "r"(0u), "r"(e) : "memory");
}
#endif

// idesc: dtype F32, atype/btype BF16, N=128, M=128
#define IDESC 0x8200490u
#define DESC_BASE ((2ULL << 61) | (1ULL << 46) | (64ULL << 32) | (1ULL << 16))
__device__ __forceinline__ uint64_t mkdesc(uint32_t addr) {
    return DESC_BASE | ((uint64_t)(addr >> 4) & 0x3FFF);
}
__device__ __forceinline__ uint32_t sw128(uint32_t b) { return b ^ ((b >> 3) & 0x70); }

__device__ __forceinline__ void bsplit(float v, __nv_bfloat16& h, __nv_bfloat16& l) {
    h = __float2bfloat16_rn(v);
    l = __float2bfloat16_rn(v - __bfloat162float(h));
}

// ---------------- tcgen05 GEMM (unchanged from R9, verified) --------------------
#define SM_DATA 1024
#define PLANE_B 16384
#define STAGE_B (4 * PLANE_B)
#define GSMEM (SM_DATA + 2 * STAGE_B)

template <int MODE, bool WF32, bool WB16, bool HEADC>
__global__ void __launch_bounds__(256, 1) gemm_t5(
        const __nv_bfloat16* __restrict__ A, long long aPl,
        const __nv_bfloat16* __restrict__ B, long long bPl,
        float* __restrict__ Cf, __nv_bfloat16* __restrict__ Cb, long long cPl,
        int K, int lda, int ldb, int ldc,
        long long sAq, long long sAr, long long sBq, long long sBr,
        long long sCq, long long sCr, int zdiv, long long sHC) {
#if HAS_TC
    const int m0 = blockIdx.y * 128;
    const int n0 = blockIdx.x * 128;
    if (MODE == 1 && n0 > m0) return;

    const int z = blockIdx.z;
    const int zq = z / zdiv, zr = z % zdiv;
    A += (long long)zq * sAq + (long long)zr * sAr;
    B += (long long)zq * sBq + (long long)zr * sBr;
    if (WF32) Cf += (long long)zq * sCq + (long long)zr * sCr + (HEADC ? (long long)blockIdx.x * sHC : 0);
    if (WB16) Cb += (long long)zq * sCq + (long long)zr * sCr + (HEADC ? (long long)blockIdx.x * sHC : 0);

    const int Keff = (MODE == 2) ? ((m0 + 128 < K) ? m0 + 128 : K) : K;
    const int nt = Keff >> 6;

    extern __shared__ __align__(1024) char smem[];
    const uint32_t smb = s2u(smem);
    const uint32_t mb0 = smb + 16, mb1 = smb + 24;

    const int tid = threadIdx.x;
    const int warp = tid >> 5;
    const int lane = tid & 31;

    if (warp == 0) TC_ALLOC(smb, 128);
    if (tid == 0) { MB_INIT(mb0, 1); MB_INIT(mb1, 1); }
    __syncthreads();
    uint32_t tmem;
    asm volatile("ld.shared.b32 %0, [%1];" : "=r"(tmem) : "r"(smb));

    auto issue_load = [&](int t) {
        const uint32_t st = smb + SM_DATA + (t & 1) * STAGE_B;
        const int k0 = t << 6;
#pragma unroll
        for (int i = 0; i < 16; i++) {
            int idx = tid + i * 256;
            int plane = idx >> 10;
            int c = idx & 1023;
            int r = c >> 3, cc = c & 7;
            uint32_t dst = st + plane * PLANE_B + sw128(r * 128 + cc * 16);
            const __nv_bfloat16* src;
            if (plane < 2) src = A + (long long)plane * aPl + (long long)(m0 + r) * lda + k0 + cc * 8;
            else           src = B + (long long)(plane - 2) * bPl + (long long)(n0 + r) * ldb + k0 + cc * 8;
            CP16(dst, src);
        }
        CP_COMMIT();
    };

    issue_load(0);
    if (nt > 1) issue_load(1);

    int ph0 = 0, ph1 = 0;
    for (int t = 0; t < nt; t++) {
        const int s = t & 1;
        if (t + 1 < nt) CP_WAIT(1); else CP_WAIT(0);
        __syncthreads();
        FENCE_PROXY();
        if (warp == 0 && elect1()) {
            const uint32_t st = smb + SM_DATA + s * STAGE_B;
            uint64_t dAh = mkdesc(st);
            uint64_t dAl = mkdesc(st + PLANE_B);
            uint64_t dBh = mkdesc(st + 2 * PLANE_B);
            uint64_t dBl = mkdesc(st + 3 * PLANE_B);
#pragma unroll
            for (int k = 0; k < 4; k++)
                mma_bf16_ss(tmem, dAh + 2 * k, dBh + 2 * k, IDESC, !(t == 0 && k == 0));
#pragma unroll
            for (int k = 0; k < 4; k++)
                mma_bf16_ss(tmem, dAh + 2 * k, dBl + 2 * k, IDESC, true);
#pragma unroll
            for (int k = 0; k < 4; k++)
                mma_bf16_ss(tmem, dAl + 2 * k, dBh + 2 * k, IDESC, true);
            TC_COMMIT(s ? mb1 : mb0);
        }
        if (t + 2 < nt) {
            if (s) { MB_WAIT(mb1, ph1); ph1 ^= 1; }
            else   { MB_WAIT(mb0, ph0); ph0 ^= 1; }
            issue_load(t + 2);
        }
    }
    if (nt >= 2) {
        const int s = (nt - 2) & 1;
        if (s) { MB_WAIT(mb1, ph1); ph1 ^= 1; }
        else   { MB_WAIT(mb0, ph0); ph0 ^= 1; }
    }
    {
        const int s = (nt - 1) & 1;
        if (s) { MB_WAIT(mb1, ph1); ph1 ^= 1; }
        else   { MB_WAIT(mb0, ph0); ph0 ^= 1; }
    }
    TC_FENCE_AFTER();

    {
        const int row = m0 + (warp & 3) * 32 + lane;
        const int cb = (warp >> 2) * 64;
        uint32_t dr[32];
#pragma unroll
        for (int half = 0; half < 2; half++) {
            TCLD32(dr, tmem + cb + half * 32);
            TC_WAIT_LD();
            const int coff = (HEADC ? 0 : n0) + cb + half * 32;
#pragma unroll
            for (int c = 0; c < 32; c++) {
                float v = __uint_as_float(dr[c]);
                if (WF32) Cf[(long long)row * ldc + coff + c] = v;
                if (WB16) {
                    __nv_bfloat16 h, l; bsplit(v, h, l);
                    Cb[(long long)row * ldc + coff + c] = h;
                    Cb[(long long)row * ldc + coff + c + cPl] = l;
                }
            }
        }
    }
    __syncthreads();
    if (warp == 0) { TC_RELINQ(); TC_DEALLOC(tmem, 128); }
#endif
}

// ---------------- fused flash attention (replaces logits+softmax+PV) ------------
// One CTA per (b, h, m-tile of 128 rows). S in TMEM cols 0-127, O in 128-255.
// K/V stream via 2-slot cp.async ring; Q resident; P hi/lo in smem.
#define FQOFF 2048
#define FRING (FQOFF + 6 * 16384)     // 100352
#define FPOFF (FRING + 2 * 32768)     // 165888
#define FSMEM (FPOFF + 4 * 16384)     // 231424

__global__ void __launch_bounds__(256, 1) flash_attn(
        const __nv_bfloat16* __restrict__ qh, const __nv_bfloat16* __restrict__ kh,
        const __nv_bfloat16* __restrict__ vt, float* __restrict__ out) {
#if HAS_TC
    const int mt = blockIdx.x, h = blockIdx.y, b = blockIdx.z;
    const int ntile = mt + 1, m0 = mt * 128;
    const int S = 5 * ntile;
    const long long QKPL = 64LL * 1024 * 192;
    const long long VPL  = 64LL * 128 * 1024;
    const __nv_bfloat16* Qb = qh + (long long)(b * 16 + h) * (1024LL * 192);
    const __nv_bfloat16* Kb = kh + (long long)(b * 16 + h) * (1024LL * 192);
    const __nv_bfloat16* Vb = vt + (long long)(b * 16 + h) * (128LL * 1024);

    extern __shared__ __align__(1024) char smem[];
    const uint32_t smb = s2u(smem);
    const uint32_t mb = smb + 16;
    float* ex = (float*)(smem + 32);   // [8][32]

    const int tid = threadIdx.x, warp = tid >> 5, lane = tid & 31;
    const int rg = warp & 3, ch = warp >> 2;
    const int row = rg * 32 + lane;    // local row (== TMEM lane of this warp's subpartition)

    if (warp == 0) TC_ALLOC(smb, 256);
    if (tid == 0) MB_INIT(mb, 1);
    __syncthreads();
    uint32_t tmem;
    asm volatile("ld.shared.b32 %0, [%1];" : "=r"(tmem) : "r"(smb));
    const uint32_t tS = tmem, tO = tmem + 128;

    // Q: 3 chunks x hi/lo resident
    {
#pragma unroll
        for (int i = 0; i < 24; i++) {
            int idx = tid + i * 256;
            int cp = idx >> 10;                 // chunk*2 + plane
            int c = cp >> 1, pl = cp & 1;
            int cidx = idx & 1023, rr = cidx >> 3, cc = cidx & 7;
            const __nv_bfloat16* src = Qb + (long long)pl * QKPL +
                (long long)(m0 + rr) * 192 + c * 64 + cc * 8;
            CP16(smb + FQOFF + cp * 16384 + sw128(rr * 128 + cc * 16), src);
        }
        CP_COMMIT();
    }
    auto issue_slot = [&](int s) {
        int t = s / 5, r = s % 5;
        uint32_t dst = smb + FRING + (s & 1) * 32768;
#pragma unroll
        for (int i = 0; i < 8; i++) {
            int idx = tid + i * 256;
            int pl = idx >> 10, cidx = idx & 1023, rr = cidx >> 3, cc = cidx & 7;
            const __nv_bfloat16* src;
            if (r < 3)
                src = Kb + (long long)pl * QKPL + (long long)(t * 128 + rr) * 192 + r * 64 + cc * 8;
            else
                src = Vb + (long long)pl * VPL + (long long)rr * 1024 + t * 128 + (r - 3) * 64 + cc * 8;
            CP16(dst + pl * 16384 + sw128(rr * 128 + cc * 16), src);
        }
        CP_COMMIT();
    };
    issue_slot(0);
    if (S > 1) issue_slot(1);

    float m_old = -INFINITY, lsum = 0.0f;
    int ph = 0, sc = 0;

    for (int t = 0; t < ntile; t++) {
        // ---- QK: 3 K-chunks of 64 ----
        for (int c = 0; c < 3; c++) {
            if (sc + 1 < S) { CP_WAIT(1); } else { CP_WAIT(0); }
            __syncthreads();
            FENCE_PROXY();
            if (warp == 0 && elect1()) {
                uint32_t st = smb + FRING + (sc & 1) * 32768;
                uint64_t dQh = mkdesc(smb + FQOFF + (c * 2 + 0) * 16384);
                uint64_t dQl = mkdesc(smb + FQOFF + (c * 2 + 1) * 16384);
                uint64_t dKh = mkdesc(st);
                uint64_t dKl = mkdesc(st + 16384);
#pragma unroll
                for (int k = 0; k < 4; k++)
                    mma_bf16_ss(tS, dQh + 2 * k, dKh + 2 * k, IDESC, !(c == 0 && k == 0));
#pragma unroll
                for (int k = 0; k < 4; k++)
                    mma_bf16_ss(tS, dQh + 2 * k, dKl + 2 * k, IDESC, true);
#pragma unroll
                for (int k = 0; k < 4; k++)
                    mma_bf16_ss(tS, dQl + 2 * k, dKh + 2 * k, IDESC, true);
                TC_COMMIT(mb);
            }
            MB_WAIT(mb, ph); ph ^= 1;
            if (sc + 2 < S) issue_slot(sc + 2);
            sc++;
        }
        // ---- online softmax ----
        TC_FENCE_AFTER();
        float sv[64];
        {
            uint32_t r0[32], r1[32];
            TCLD32(r0, tS + ch * 64);
            TCLD32(r1, tS + ch * 64 + 32);
            TC_WAIT_LD();
            const float scale = 0.07216878364870323f;
#pragma unroll
            for (int j = 0; j < 32; j++) {
                sv[j] = __uint_as_float(r0[j]) * scale;
                sv[32 + j] = __uint_as_float(r1[j]) * scale;
            }
        }
        if (t == mt) {
#pragma unroll
            for (int j = 0; j < 64; j++)
                if (ch * 64 + j > row) sv[j] = -INFINITY;
        }
        float pmax = -INFINITY;
#pragma unroll
        for (int j = 0; j < 64; j++) pmax = fmaxf(pmax, sv[j]);
        __syncthreads();
        ex[warp * 32 + lane] = pmax;
        __syncthreads();
        float m_new = fmaxf(m_old, fmaxf(pmax, ex[(warp ^ 4) * 32 + lane]));
        float alpha = __expf(m_old - m_new);
        bool norescale = (t == 0) || __all_sync(0xffffffffu, m_new == m_old);
        float psum = 0.0f;
#pragma unroll
        for (int j = 0; j < 64; j++) { sv[j] = __expf(sv[j] - m_new); psum += sv[j]; }
        __syncthreads();
        ex[warp * 32 + lane] = psum;
        __syncthreads();
        lsum = lsum * alpha + psum + ex[(warp ^ 4) * 32 + lane];
        m_old = m_new;
        // write P (chunk = ch) hi/lo planes
        {
            uint32_t baseh = smb + FPOFF + (ch * 2 + 0) * 16384;
            uint32_t basel = smb + FPOFF + (ch * 2 + 1) * 16384;
#pragma unroll
            for (int jj = 0; jj < 32; jj++) {
                float a = sv[2 * jj], bq = sv[2 * jj + 1];
                __nv_bfloat16 ah, al, bh, bl;
                bsplit(a, ah, al); bsplit(bq, bh, bl);
                uint32_t hi = ((uint32_t)__bfloat16_as_ushort(bh) << 16) | __bfloat16_as_ushort(ah);
                uint32_t lo = ((uint32_t)__bfloat16_as_ushort(bl) << 16) | __bfloat16_as_ushort(al);
                uint32_t off = sw128(row * 128 + 4 * jj);
                asm volatile("st.shared.b32 [%0], %1;" :: "r"(baseh + off), "r"(hi));
                asm volatile("st.shared.b32 [%0], %1;" :: "r"(basel + off), "r"(lo));
            }
        }
        // O rescale (only when row max changed)
        if (!norescale) {
            uint32_t r0[32], r1[32];
            TCLD32(r0, tO + ch * 64);
            TCLD32(r1, tO + ch * 64 + 32);
            TC_WAIT_LD();
#pragma unroll
            for (int j = 0; j < 32; j++) {
                r0[j] = __float_as_uint(__uint_as_float(r0[j]) * alpha);
                r1[j] = __float_as_uint(__uint_as_float(r1[j]) * alpha);
            }
            TCST32(tO + ch * 64, r0);
            TCST32(tO + ch * 64 + 32, r1);
            TC_WAIT_ST();
        }
        FENCE_PROXY();
        TC_FENCE_BEFORE();
        __syncthreads();
        // ---- PV: 2 V-chunks of 64 (n-dim) ----
        for (int vc = 0; vc < 2; vc++) {
            if (sc + 1 < S) { CP_WAIT(1); } else { CP_WAIT(0); }
            __syncthreads();
            FENCE_PROXY();
            if (warp == 0 && elect1()) {
                TC_FENCE_AFTER();
                uint32_t st = smb + FRING + (sc & 1) * 32768;
                uint64_t dPh = mkdesc(smb + FPOFF + (vc * 2 + 0) * 16384);
                uint64_t dPl = mkdesc(smb + FPOFF + (vc * 2 + 1) * 16384);
                uint64_t dVh = mkdesc(st);
                uint64_t dVl = mkdesc(st + 16384);
#pragma unroll
                for (int k = 0; k < 4; k++)
                    mma_bf16_ss(tO, dPh + 2 * k, dVh + 2 * k, IDESC, !(t == 0 && vc == 0 && k == 0));
#pragma unroll
                for (int k = 0; k < 4; k++)
                    mma_bf16_ss(tO, dPh + 2 * k, dVl + 2 * k, IDESC, true);
#pragma unroll
                for (int k = 0; k < 4; k++)
                    mma_bf16_ss(tO, dPl + 2 * k, dVh + 2 * k, IDESC, true);
                TC_COMMIT(mb);
            }
            MB_WAIT(mb, ph); ph ^= 1;
            if (sc + 2 < S) issue_slot(sc + 2);
            sc++;
        }
    }
    // ---- epilogue: out = O / l ----
    TC_FENCE_AFTER();
    {
        uint32_t r0[32], r1[32];
        TCLD32(r0, tO + ch * 64);
        TCLD32(r1, tO + ch * 64 + 32);
        TC_WAIT_LD();
        float inv = 1.0f / lsum;
        float* op = out + ((long long)(b * 1024 + m0 + row)) * 2048 + h * 128 + ch * 64;
#pragma unroll
        for (int j = 0; j < 8; j++) {
            float4 v = make_float4(__uint_as_float(r0[4*j]) * inv, __uint_as_float(r0[4*j+1]) * inv,
                                   __uint_as_float(r0[4*j+2]) * inv, __uint_as_float(r0[4*j+3]) * inv);
            *reinterpret_cast<float4*>(op + 4 * j) = v;
            float4 w = make_float4(__uint_as_float(r1[4*j]) * inv, __uint_as_float(r1[4*j+1]) * inv,
                                   __uint_as_float(r1[4*j+2]) * inv, __uint_as_float(r1[4*j+3]) * inv);
            *reinterpret_cast<float4*>(op + 32 + 4 * j) = w;
        }
    }
    __syncthreads();
    if (warp == 0) { TC_RELINQ(); TC_DEALLOC(tmem, 256); }
#endif
}

// ---------------- prep kernels ---------------------------------------------------
__global__ void split_copy(const float* __restrict__ in, __nv_bfloat16* __restrict__ out,
                           long long oPl, int n) {
    int i = blockIdx.x * blockDim.x + threadIdx.x;
    if (i >= n) return;
    __nv_bfloat16 h, l; bsplit(in[i], h, l);
    out[i] = h; out[i + oPl] = l;
}

__global__ void transpose_split(const float* __restrict__ in, __nv_bfloat16* __restrict__ out,
                                long long oPl, int R, int C) {
    __shared__ float tile[32][33];
    int bx = blockIdx.x * 32, by = blockIdx.y * 32;
    int tx = threadIdx.x, ty = threadIdx.y;
#pragma unroll
    for (int i = 0; i < 4; i++)
        tile[ty + i * 8][tx] = in[(long long)(by + ty + i * 8) * C + bx + tx];
    __syncthreads();
#pragma unroll
    for (int i = 0; i < 4; i++) {
        int c = bx + ty + i * 8, r = by + tx;
        __nv_bfloat16 h, l; bsplit(tile[tx][ty + i * 8], h, l);
        out[(long long)c * R + r] = h;
        out[(long long)c * R + r + oPl] = l;
    }
}

__global__ void build_wcat_split(const float* __restrict__ Wdq, const float* __restrict__ Wkr,
                                 __nv_bfloat16* __restrict__ out, long long oPl) {
    int i = blockIdx.x * blockDim.x + threadIdx.x;
    if (i >= 640 * 2048) return;
    int row = i >> 11;
    float v = 0.0f;
    if (row < 512) v = Wdq[i];
    else if (row < 576) v = Wkr[(row - 512) * 2048 + (i & 2047)];
    __nv_bfloat16 h, l; bsplit(v, h, l);
    out[i] = h; out[i + oPl] = l;
}

// ---------------- rope ----------------------------------------------------------
__global__ void rope_q_kernel(const float* __restrict__ cqr, const float* __restrict__ fc,
                              const float* __restrict__ fs, __nv_bfloat16* __restrict__ qh,
                              long long qPl) {
    int idx = blockIdx.x * blockDim.x + threadIdx.x;
    if (idx >= 4 * 1024 * 16 * 32) return;
    int j = idx & 31;
    int h = (idx >> 5) & 15;
    int t = (idx >> 9) & 1023;
    int b = idx >> 19;
    long long src = (((long long)(b * 1024 + t)) * 1024) + h * 64 + 2 * j;
    float re = cqr[src], im = cqr[src + 1];
    float c = fc[t * 32 + j], s = fs[t * 32 + j];
    float o0 = re * c - im * s, o1 = re * s + im * c;
    long long dst = (((long long)(b * 16 + h)) * 1024 + t) * 192 + 128 + 2 * j;
    __nv_bfloat16 h0, l0, h1, l1; bsplit(o0, h0, l0); bsplit(o1, h1, l1);
    qh[dst] = h0; qh[dst + qPl] = l0;
    qh[dst + 1] = h1; qh[dst + 1 + qPl] = l1;
}

__global__ void rope_k_kernel(const float* __restrict__ cqx_f, const float* __restrict__ fc,
                              const float* __restrict__ fs, __nv_bfloat16* __restrict__ kh,
                              long long kPl) {
    int idx = blockIdx.x * blockDim.x + threadIdx.x;
    if (idx >= 4 * 1024 * 32) return;
    int j = idx & 31;
    int t = (idx >> 5) & 1023;
    int b = idx >> 15;
    long long src = ((long long)(b * 1024 + t)) * 640 + 512 + 2 * j;
    float re = cqx_f[src], im = cqx_f[src + 1];
    float c = fc[t * 32 + j], s = fs[t * 32 + j];
    float o0 = re * c - im * s, o1 = re * s + im * c;
    __nv_bfloat16 h0, l0, h1, l1; bsplit(o0, h0, l0); bsplit(o1, h1, l1);
#pragma unroll
    for (int h = 0; h < 16; h++) {
        long long dst = (((long long)(b * 16 + h)) * 1024 + t) * 192 + 128 + 2 * j;
        kh[dst] = h0; kh[dst + kPl] = l0;
        kh[dst + 1] = h1; kh[dst + 1 + kPl] = l1;
    }
}

// ---------------- launcher -------------------------------------------------------
extern "C" void kernel_launch(void* const* d_in, const int* in_sizes, int n_in,
                              void* d_out, int out_size) {
    (void)in_sizes; (void)n_in; (void)out_size;
    const float* x     = (const float*)d_in[0];
    const float* W_dq  = (const float*)d_in[1];
    const float* W_uq  = (const float*)d_in[2];
    const float* W_dkv = (const float*)d_in[3];
    const float* W_uk  = (const float*)d_in[4];
    const float* W_uv  = (const float*)d_in[5];
    const float* W_o   = (const float*)d_in[6];
    const float* W_qr  = (const float*)d_in[7];
    const float* W_kr  = (const float*)d_in[8];
    const float* fc    = (const float*)d_in[9];
    const float* fs    = (const float*)d_in[10];
    float* out = (float*)d_out;

    __nv_bfloat16 *x2, *wcat2, *wdkv2, *wqr2, *wuqT2, *wuk2, *wuvT2, *wo2, *mt2;
    __nv_bfloat16 *cqx2, *qh2, *kh2, *kcat2, *vt2;
    float *cqx_f, *cqr;
    cudaGetSymbolAddress((void**)&x2,     g_x2);
    cudaGetSymbolAddress((void**)&wcat2,  g_wcat2);
    cudaGetSymbolAddress((void**)&wdkv2,  g_wdkv2);
    cudaGetSymbolAddress((void**)&wqr2,   g_wqr2);
    cudaGetSymbolAddress((void**)&wuqT2,  g_wuqT2);
    cudaGetSymbolAddress((void**)&wuk2,   g_wuk2);
    cudaGetSymbolAddress((void**)&wuvT2,  g_wuvT2);
    cudaGetSymbolAddress((void**)&wo2,    g_wo2);
    cudaGetSymbolAddress((void**)&mt2,    g_mt2);
    cudaGetSymbolAddress((void**)&cqx2,   g_cqx2);
    cudaGetSymbolAddress((void**)&cqx_f,  g_cqx_f);
    cudaGetSymbolAddress((void**)&cqr,    g_cqr);
    cudaGetSymbolAddress((void**)&qh2,    g_qh2);
    cudaGetSymbolAddress((void**)&kh2,    g_kh2);
    cudaGetSymbolAddress((void**)&kcat2,  g_kcat2);
    cudaGetSymbolAddress((void**)&vt2,    g_vt2);

    const long long XPL   = 4096LL * 2048;
    const long long WCPL  = 640LL * 2048;
    const long long WDPL  = 512LL * 2048;
    const long long WQRPL = 1024LL * 512;
    const long long WUQPL = 2048LL * 512;
    const long long WUKPL = 2048LL * 512;
    const long long WUVPL = 512LL * 2048;
    const long long WOPL  = 2048LL * 2048;
    const long long MTPL  = 2048LL * 512;
    const long long CQXPL = 4096LL * 640;
    const long long HPL   = 64LL * 1024 * 192;
    const long long KCPL  = 4096LL * 512;
    const long long VTPL  = 64LL * 128 * 1024;
    const long long HZ    = 1024LL * 192;
    const long long VTZ   = 128LL * 1024;

    cudaFuncSetAttribute(gemm_t5<0, true,  true,  false>, cudaFuncAttributeMaxDynamicSharedMemorySize, GSMEM);
    cudaFuncSetAttribute(gemm_t5<0, false, true,  false>, cudaFuncAttributeMaxDynamicSharedMemorySize, GSMEM);
    cudaFuncSetAttribute(gemm_t5<0, true,  false, false>, cudaFuncAttributeMaxDynamicSharedMemorySize, GSMEM);
    cudaFuncSetAttribute(gemm_t5<0, false, true,  true >, cudaFuncAttributeMaxDynamicSharedMemorySize, GSMEM);
    cudaFuncSetAttribute(flash_attn, cudaFuncAttributeMaxDynamicSharedMemorySize, FSMEM);

    dim3 blk(256);

    // --- prep: split / transpose ---
    split_copy<<<(8388608 + 255) / 256, 256>>>(x,     x2,    XPL,   8388608);
    split_copy<<<(1048576 + 255) / 256, 256>>>(W_dkv, wdkv2, WDPL,  1048576);
    split_copy<<<(524288  + 255) / 256, 256>>>(W_qr,  wqr2,  WQRPL, 524288);
    split_copy<<<(1048576 + 255) / 256, 256>>>(W_uk,  wuk2,  WUKPL, 1048576);
    split_copy<<<(4194304 + 255) / 256, 256>>>(W_o,   wo2,   WOPL,  4194304);
    transpose_split<<<dim3(64, 16), dim3(32, 8)>>>(W_uq, wuqT2, WUQPL, 512, 2048);
    transpose_split<<<dim3(16, 64), dim3(32, 8)>>>(W_uv, wuvT2, WUVPL, 2048, 512);
    build_wcat_split<<<(640 * 2048 + 255) / 256, 256>>>(W_dq, W_kr, wcat2, WCPL);

    // 1) cqx (4096x640) = x @ Wcat^T      [f32 + planes]
    gemm_t5<0, true, true, false><<<dim3(5, 32, 1), blk, GSMEM>>>(
        x2, XPL, wcat2, WCPL, cqx_f, cqx2, CQXPL,
        2048, 2048, 2048, 640, 0, 0, 0, 0, 0, 0, 1, 0);

    // 2) c_kv (4096x512) = x @ W_dkv^T    [planes]
    gemm_t5<0, false, true, false><<<dim3(4, 32, 1), blk, GSMEM>>>(
        x2, XPL, wdkv2, WDPL, nullptr, kcat2, KCPL,
        2048, 2048, 2048, 512, 0, 0, 0, 0, 0, 0, 1, 0);

    // 3) MT (2048x512) = Wo @ WuvT^T      [planes]
    gemm_t5<0, false, true, false><<<dim3(4, 16, 1), blk, GSMEM>>>(
        wo2, WOPL, wuvT2, WUVPL, nullptr, mt2, MTPL,
        2048, 2048, 2048, 512, 0, 0, 0, 0, 0, 0, 1, 0);

    // 4) c_qr (4096x1024) = c_q @ W_qr^T  [f32]
    gemm_t5<0, true, false, false><<<dim3(8, 32, 1), blk, GSMEM>>>(
        cqx2, CQXPL, wqr2, WQRPL, cqr, nullptr, 0,
        512, 640, 512, 1024, 0, 0, 0, 0, 0, 0, 1, 0);

    // 5) q per head: qh[:, 0:128] = c_q[b] @ WuqT^T  (head-sliced C)
    gemm_t5<0, false, true, true><<<dim3(16, 8, 4), blk, GSMEM>>>(
        cqx2, CQXPL, wuqT2, WUQPL, nullptr, qh2, HPL,
        512, 640, 512, 192,
        1024LL * 640, 0, 0, 0, 16LL * HZ, 0, 1, HZ);

    // 6) k per head: kh[:, 0:128] = c_kv[b] @ W_uk^T
    gemm_t5<0, false, true, true><<<dim3(16, 8, 4), blk, GSMEM>>>(
        kcat2, KCPL, wuk2, WUKPL, nullptr, kh2, HPL,
        512, 512, 512, 192,
        1024LL * 512, 0, 0, 0, 16LL * HZ, 0, 1, HZ);

    // 7) rope tails (split-write)
    rope_q_kernel<<<8192, 256>>>(cqr, fc, fs, qh2, HPL);
    rope_k_kernel<<<512, 256>>>(cqx_f, fc, fs, kh2, HPL);

    // 8) VT[b,h] (128x1024) = MT[h-slice] @ c_kv[b]^T   [planes]
    gemm_t5<0, false, true, false><<<dim3(8, 1, 64), blk, GSMEM>>>(
        mt2, MTPL, kcat2, KCPL, nullptr, vt2, VTPL,
        512, 512, 512, 1024,
        0, 128LL * 512, 1024LL * 512, 0, 16LL * VTZ, VTZ, 16, 0);

    // 9) fused flash attention: logits + softmax + PV -> out
    flash_attn<<<dim3(8, 16, 4), blk, FSMEM>>>(qh2, kh2, vt2, out);
}

// round 11
// speedup vs baseline: 2.8636x; 2.3976x over previous
#include <cuda_runtime.h>
#include <cuda_bf16.h>
#include <math.h>
#include <stdint.h>

// B=4, T=1024, C=2048, NH=16, HS=128, NLQ=512, NLKV=512, DHR=64
// scale = 1/sqrt(192)

#if !defined(__CUDA_ARCH__) || defined(__CUDA_ARCH_SPECIFIC__) || \
    defined(__CUDA_ARCH_FEAT_SM103_ALL) || defined(__CUDA_ARCH_FEAT_SM100_ALL) || \
    defined(__CUDA_ARCH_FEAT_SM101_ALL)
#define HAS_TC 1
#else
#define HAS_TC 0
#endif

// ---------------- scratch (device globals; [2][..] = bf16 hi/lo planes) --------
__device__ __nv_bfloat16 g_x2[2][4096L * 2048];
__device__ __nv_bfloat16 g_wcat2[2][640L * 2048];     // [W_dq ; W_kr ; pad]
__device__ __nv_bfloat16 g_wdkv2[2][512L * 2048];
__device__ __nv_bfloat16 g_wqr2[2][1024L * 512];
__device__ __nv_bfloat16 g_wuqT2[2][2048L * 512];     // Wuq_flat^T
__device__ __nv_bfloat16 g_wuk2[2][2048L * 512];
__device__ __nv_bfloat16 g_wuvT2[2][512L * 2048];     // Wuv_flat^T
__device__ __nv_bfloat16 g_wo2[2][2048L * 2048];
__device__ __nv_bfloat16 g_mt2[2][2048L * 512];       // M^T = Wo @ Wuv
__device__ __nv_bfloat16 g_cqx2[2][4096L * 640];      // [c_q | c_kr | pad]
__device__ float         g_cqx_f[4096L * 640];
__device__ float         g_cqr[4096L * 1024];
__device__ __nv_bfloat16 g_qh2[2][64L * 1024 * 192];  // per-head [q_c | q_r]
__device__ __nv_bfloat16 g_kh2[2][64L * 1024 * 192];  // per-head [k_c | k_r]
__device__ __nv_bfloat16 g_kcat2[2][4096L * 512];     // c_kv
__device__ __nv_bfloat16 g_vt2[2][64L * 128 * 1024];  // V^T per (b,h)

// ---------------- PTX helpers ---------------------------------------------------
__device__ __forceinline__ uint32_t elect1() {
    uint32_t p;
    asm volatile("{\n\t.reg .pred p;\n\telect.sync _|p, 0xFFFFFFFF;\n\t"
                 "selp.b32 %0, 1, 0, p;\n\t}" : "=r"(p));
    return p;
}
__device__ __forceinline__ uint32_t s2u(const void* p) {
    uint32_t a;
    asm("{ .reg .u64 t; cvta.to.shared.u64 t, %1; cvt.u32.u64 %0, t; }" : "=r"(a) : "l"(p));
    return a;
}
#define TC_ALLOC(sm, n)  asm volatile("tcgen05.alloc.cta_group::1.sync.aligned.shared::cta.b32 [%0], %1;" :: "r"(sm), "r"(n) : "memory")
#define TC_DEALLOC(t, n) asm volatile("tcgen05.dealloc.cta_group::1.sync.aligned.b32 %0, %1;" :: "r"(t), "r"(n))
#define TC_RELINQ()      asm volatile("tcgen05.relinquish_alloc_permit.cta_group::1.sync.aligned;")
#define TC_COMMIT(mb)    asm volatile("tcgen05.commit.cta_group::1.mbarrier::arrive::one.shared::cluster.b64 [%0];" :: "r"(mb) : "memory")
#define TC_FENCE_AFTER() asm volatile("tcgen05.fence::after_thread_sync;" ::: "memory")
#define TC_FENCE_BEFORE() asm volatile("tcgen05.fence::before_thread_sync;" ::: "memory")
#define TC_WAIT_LD()     asm volatile("tcgen05.wait::ld.sync.aligned;" ::: "memory")
#define TC_WAIT_ST()     asm volatile("tcgen05.wait::st.sync.aligned;" ::: "memory")
#define FENCE_PROXY()    asm volatile("fence.proxy.async.shared::cta;" ::: "memory")
#define MB_INIT(mb, c)   asm volatile("mbarrier.init.shared.b64 [%0], %1;" :: "r"(mb), "r"(c) : "memory")
#define MB_WAIT(mb, ph) do { \
    asm volatile("{\n\t.reg .pred P1;\n\tWL_%=:\n\t" \
        "mbarrier.try_wait.parity.acquire.cta.shared::cta.b64 P1, [%0], %1, 0x989680;\n\t" \
        "@P1 bra.uni WD_%=;\n\tbra.uni WL_%=;\n\tWD_%=:\n\t}" \
        :: "r"(mb), "r"((uint32_t)(ph)) : "memory"); \
} while (0)
#define CP16(dst, src)   asm volatile("cp.async.cg.shared.global [%0], [%1], 16;" :: "r"(dst), "l"(src))
#define CP_COMMIT()      asm volatile("cp.async.commit_group;")
#define CP_WAIT(n)       asm volatile("cp.async.wait_group %0;" :: "n"(n))

#define TCLD32(r, a) \
    asm volatile("tcgen05.ld.sync.aligned.32x32b.x32.b32 " \
        "{%0,%1,%2,%3,%4,%5,%6,%7,%8,%9,%10,%11,%12,%13,%14,%15," \
        "%16,%17,%18,%19,%20,%21,%22,%23,%24,%25,%26,%27,%28,%29,%30,%31}, [%32];" \
        : "=r"((r)[0]),"=r"((r)[1]),"=r"((r)[2]),"=r"((r)[3]),"=r"((r)[4]),"=r"((r)[5]), \
          "=r"((r)[6]),"=r"((r)[7]),"=r"((r)[8]),"=r"((r)[9]),"=r"((r)[10]),"=r"((r)[11]), \
          "=r"((r)[12]),"=r"((r)[13]),"=r"((r)[14]),"=r"((r)[15]),"=r"((r)[16]),"=r"((r)[17]), \
          "=r"((r)[18]),"=r"((r)[19]),"=r"((r)[20]),"=r"((r)[21]),"=r"((r)[22]),"=r"((r)[23]), \
          "=r"((r)[24]),"=r"((r)[25]),"=r"((r)[26]),"=r"((r)[27]),"=r"((r)[28]),"=r"((r)[29]), \
          "=r"((r)[30]),"=r"((r)[31]) : "r"(a))

#define TCST32(a, r) \
    asm volatile("tcgen05.st.sync.aligned.32x32b.x32.b32 [%0], " \
        "{%1,%2,%3,%4,%5,%6,%7,%8,%9,%10,%11,%12,%13,%14,%15,%16," \
        "%17,%18,%19,%20,%21,%22,%23,%24,%25,%26,%27,%28,%29,%30,%31,%32};" \
        :: "r"(a), \
          "r"((r)[0]),"r"((r)[1]),"r"((r)[2]),"r"((r)[3]),"r"((r)[4]),"r"((r)[5]), \
          "r"((r)[6]),"r"((r)[7]),"r"((r)[8]),"r"((r)[9]),"r"((r)[10]),"r"((r)[11]), \
          "r"((r)[12]),"r"((r)[13]),"r"((r)[14]),"r"((r)[15]),"r"((r)[16]),"r"((r)[17]), \
          "r"((r)[18]),"r"((r)[19]),"r"((r)[20]),"r"((r)[21]),"r"((r)[22]),"r"((r)[23]), \
          "r"((r)[24]),"r"((r)[25]),"r"((r)[26]),"r"((r)[27]),"r"((r)[28]),"r"((r)[29]), \
          "r"((r)[30]),"r"((r)[31]) : "memory")

#if HAS_TC
__device__ __forceinline__ void mma_bf16_ss(uint32_t d, uint64_t a, uint64_t b,
                                            uint32_t idesc, bool en) {
    uint32_t e = en ? 1u : 0u;
    asm volatile("{\n\t.reg .pred p;\n\tsetp.ne.u32 p, %5, 0;\n\t"
        "tcgen05.mma.cta_group::1.kind::f16 [%0], %1, %2, %3, {%4, %4, %4, %4}, p;\n\t}"
        :: "r"(d), "l"(a), "l"(b), "r"(idesc), "r"(0u), "r"(e) : "memory");
}
#endif

// idesc: dtype F32, atype/btype BF16, N=128, M=128
#define IDESC 0x8200490u
#define DESC_BASE ((2ULL << 61) | (1ULL << 46) | (64ULL << 32) | (1ULL << 16))
__device__ __forceinline__ uint64_t mkdesc(uint32_t addr) {
    return DESC_BASE | ((uint64_t)(addr >> 4) & 0x3FFF);
}
__device__ __forceinline__ uint32_t sw128(uint32_t b) { return b ^ ((b >> 3) & 0x70); }

__device__ __forceinline__ void bsplit(float v, __nv_bfloat16& h, __nv_bfloat16& l) {
    h = __float2bfloat16_rn(v);
    l = __float2bfloat16_rn(v - __bfloat162float(h));
}

// ---------------- tcgen05 GEMM v2: 3-buffer lagged pipeline + coalesced epi -----
// D = A @ B^T (A: MxK, B: NxK, both K-major), bf16 2-term split, fp32 TMEM accum.
// Tile 128x128, K-chunk 64, 256 threads, 1 CTA/SM.
#define SM_DATA 1024
#define PLANE_B 16384
#define STAGE_B (4 * PLANE_B)              // 64KB: Ah, Al, Bh, Bl
#define GSMEM (SM_DATA + 3 * STAGE_B)      // 197632 B

template <bool WF32, bool WB16, bool HEADC>
__global__ void __launch_bounds__(256, 1) gemm_t5(
        const __nv_bfloat16* __restrict__ A, long long aPl,
        const __nv_bfloat16* __restrict__ B, long long bPl,
        float* __restrict__ Cf, __nv_bfloat16* __restrict__ Cb, long long cPl,
        int K, int lda, int ldb, int ldc,
        long long sAq, long long sAr, long long sBq, long long sBr,
        long long sCq, long long sCr, int zdiv, long long sHC) {
#if HAS_TC
    const int m0 = blockIdx.y * 128;
    const int n0 = blockIdx.x * 128;

    const int z = blockIdx.z;
    const int zq = z / zdiv, zr = z % zdiv;
    A += (long long)zq * sAq + (long long)zr * sAr;
    B += (long long)zq * sBq + (long long)zr * sBr;
    if (WF32) Cf += (long long)zq * sCq + (long long)zr * sCr + (HEADC ? (long long)blockIdx.x * sHC : 0);
    if (WB16) Cb += (long long)zq * sCq + (long long)zr * sCr + (HEADC ? (long long)blockIdx.x * sHC : 0);

    const int nt = K >> 6;

    extern __shared__ __align__(1024) char smem[];
    const uint32_t smb = s2u(smem);

    const int tid = threadIdx.x;
    const int warp = tid >> 5;
    const int lane = tid & 31;

    if (warp == 0) TC_ALLOC(smb, 128);
    if (tid == 0) { MB_INIT(smb + 16, 1); MB_INIT(smb + 24, 1); MB_INIT(smb + 32, 1); }
    __syncthreads();
    uint32_t tmem;
    asm volatile("ld.shared.b32 %0, [%1];" : "=r"(tmem) : "r"(smb));

    auto issue_load = [&](int t) {
        const uint32_t st = smb + SM_DATA + (t % 3) * STAGE_B;
        const int k0 = t << 6;
#pragma unroll
        for (int i = 0; i < 16; i++) {
            int idx = tid + i * 256;
            int plane = idx >> 10;
            int c = idx & 1023;
            int r = c >> 3, cc = c & 7;
            uint32_t dst = st + plane * PLANE_B + sw128(r * 128 + cc * 16);
            const __nv_bfloat16* src;
            if (plane < 2) src = A + (long long)plane * aPl + (long long)(m0 + r) * lda + k0 + cc * 8;
            else           src = B + (long long)(plane - 2) * bPl + (long long)(n0 + r) * ldb + k0 + cc * 8;
            CP16(dst, src);
        }
        CP_COMMIT();
    };

    issue_load(0);
    if (nt > 1) issue_load(1);

    for (int t = 0; t < nt; t++) {
        if (t + 1 < nt) CP_WAIT(1); else CP_WAIT(0);
        __syncthreads();
        FENCE_PROXY();
        if (warp == 0 && elect1()) {
            const uint32_t st = smb + SM_DATA + (t % 3) * STAGE_B;
            uint64_t dAh = mkdesc(st);
            uint64_t dAl = mkdesc(st + PLANE_B);
            uint64_t dBh = mkdesc(st + 2 * PLANE_B);
            uint64_t dBl = mkdesc(st + 3 * PLANE_B);
#pragma unroll
            for (int k = 0; k < 4; k++)
                mma_bf16_ss(tmem, dAh + 2 * k, dBh + 2 * k, IDESC, !(t == 0 && k == 0));
#pragma unroll
            for (int k = 0; k < 4; k++)
                mma_bf16_ss(tmem, dAh + 2 * k, dBl + 2 * k, IDESC, true);
#pragma unroll
            for (int k = 0; k < 4; k++)
                mma_bf16_ss(tmem, dAl + 2 * k, dBh + 2 * k, IDESC, true);
            TC_COMMIT(smb + 16 + 8 * (t % 3));
        }
        // lagged wait: free buffer of chunk t-1 (MMA t already queued behind it)
        if (t >= 1) {
            int w = t - 1;
            MB_WAIT(smb + 16 + 8 * (w % 3), (w / 3) & 1);
        }
        if (t + 2 < nt) issue_load(t + 2);
    }
    {
        int w = nt - 1;
        MB_WAIT(smb + 16 + 8 * (w % 3), (w / 3) & 1);
    }
    TC_FENCE_AFTER();

    // ---- epilogue: TMEM -> regs -> smem (stride 129) -> coalesced gmem ----
    float* et = (float*)(smem + SM_DATA);   // 128 x 129 f32 = 66048 B (reuses stages)
    __syncthreads();
    {
        const int lrow = (warp & 3) * 32 + lane;
        const int cb = (warp >> 2) * 64;
        uint32_t dr[32];
#pragma unroll
        for (int half = 0; half < 2; half++) {
            TCLD32(dr, tmem + cb + half * 32);
            TC_WAIT_LD();
            float* p = et + lrow * 129 + cb + half * 32;
#pragma unroll
            for (int c = 0; c < 32; c++) p[c] = __uint_as_float(dr[c]);
        }
    }
    __syncthreads();
    {
        const int colbase = HEADC ? 0 : n0;
#pragma unroll
        for (int i = 0; i < 16; i++) {
            int idx = tid + i * 256;             // 0..4095 quads
            int r = idx >> 5, q = idx & 31;
            const float* p = et + r * 129 + q * 4;
            float4 v = make_float4(p[0], p[1], p[2], p[3]);
            long long off = (long long)(m0 + r) * ldc + colbase + q * 4;
            if (WF32) *reinterpret_cast<float4*>(&Cf[off]) = v;
            if (WB16) {
                __nv_bfloat16 hx, lx, hy, ly, hz, lz, hw, lw;
                bsplit(v.x, hx, lx); bsplit(v.y, hy, ly);
                bsplit(v.z, hz, lz); bsplit(v.w, hw, lw);
                uint2 hi = make_uint2(
                    (uint32_t)__bfloat16_as_ushort(hx) | ((uint32_t)__bfloat16_as_ushort(hy) << 16),
                    (uint32_t)__bfloat16_as_ushort(hz) | ((uint32_t)__bfloat16_as_ushort(hw) << 16));
                uint2 lo = make_uint2(
                    (uint32_t)__bfloat16_as_ushort(lx) | ((uint32_t)__bfloat16_as_ushort(ly) << 16),
                    (uint32_t)__bfloat16_as_ushort(lz) | ((uint32_t)__bfloat16_as_ushort(lw) << 16));
                *reinterpret_cast<uint2*>(&Cb[off]) = hi;
                *reinterpret_cast<uint2*>(&Cb[off + cPl]) = lo;
            }
        }
    }
    __syncthreads();
    if (warp == 0) { TC_RELINQ(); TC_DEALLOC(tmem, 128); }
#endif
}

// ---------------- fused flash attention (unchanged from R10, verified) ----------
#define FQOFF 2048
#define FRING (FQOFF + 6 * 16384)     // 100352
#define FPOFF (FRING + 2 * 32768)     // 165888
#define FSMEM (FPOFF + 4 * 16384)     // 231424

__global__ void __launch_bounds__(256, 1) flash_attn(
        const __nv_bfloat16* __restrict__ qh, const __nv_bfloat16* __restrict__ kh,
        const __nv_bfloat16* __restrict__ vt, float* __restrict__ out) {
#if HAS_TC
    const int mt = blockIdx.x, h = blockIdx.y, b = blockIdx.z;
    const int ntile = mt + 1, m0 = mt * 128;
    const int S = 5 * ntile;
    const long long QKPL = 64LL * 1024 * 192;
    const long long VPL  = 64LL * 128 * 1024;
    const __nv_bfloat16* Qb = qh + (long long)(b * 16 + h) * (1024LL * 192);
    const __nv_bfloat16* Kb = kh + (long long)(b * 16 + h) * (1024LL * 192);
    const __nv_bfloat16* Vb = vt + (long long)(b * 16 + h) * (128LL * 1024);

    extern __shared__ __align__(1024) char smem[];
    const uint32_t smb = s2u(smem);
    const uint32_t mb = smb + 16;
    float* ex = (float*)(smem + 32);

    const int tid = threadIdx.x, warp = tid >> 5, lane = tid & 31;
    const int rg = warp & 3, ch = warp >> 2;
    const int row = rg * 32 + lane;

    if (warp == 0) TC_ALLOC(smb, 256);
    if (tid == 0) MB_INIT(mb, 1);
    __syncthreads();
    uint32_t tmem;
    asm volatile("ld.shared.b32 %0, [%1];" : "=r"(tmem) : "r"(smb));
    const uint32_t tS = tmem, tO = tmem + 128;

    {
#pragma unroll
        for (int i = 0; i < 24; i++) {
            int idx = tid + i * 256;
            int cp = idx >> 10;
            int c = cp >> 1, pl = cp & 1;
            int cidx = idx & 1023, rr = cidx >> 3, cc = cidx & 7;
            const __nv_bfloat16* src = Qb + (long long)pl * QKPL +
                (long long)(m0 + rr) * 192 + c * 64 + cc * 8;
            CP16(smb + FQOFF + cp * 16384 + sw128(rr * 128 + cc * 16), src);
        }
        CP_COMMIT();
    }
    auto issue_slot = [&](int s) {
        int t = s / 5, r = s % 5;
        uint32_t dst = smb + FRING + (s & 1) * 32768;
#pragma unroll
        for (int i = 0; i < 8; i++) {
            int idx = tid + i * 256;
            int pl = idx >> 10, cidx = idx & 1023, rr = cidx >> 3, cc = cidx & 7;
            const __nv_bfloat16* src;
            if (r < 3)
                src = Kb + (long long)pl * QKPL + (long long)(t * 128 + rr) * 192 + r * 64 + cc * 8;
            else
                src = Vb + (long long)pl * VPL + (long long)rr * 1024 + t * 128 + (r - 3) * 64 + cc * 8;
            CP16(dst + pl * 16384 + sw128(rr * 128 + cc * 16), src);
        }
        CP_COMMIT();
    };
    issue_slot(0);
    if (S > 1) issue_slot(1);

    float m_old = -INFINITY, lsum = 0.0f;
    int ph = 0, sc = 0;

    for (int t = 0; t < ntile; t++) {
        for (int c = 0; c < 3; c++) {
            if (sc + 1 < S) { CP_WAIT(1); } else { CP_WAIT(0); }
            __syncthreads();
            FENCE_PROXY();
            if (warp == 0 && elect1()) {
                uint32_t st = smb + FRING + (sc & 1) * 32768;
                uint64_t dQh = mkdesc(smb + FQOFF + (c * 2 + 0) * 16384);
                uint64_t dQl = mkdesc(smb + FQOFF + (c * 2 + 1) * 16384);
                uint64_t dKh = mkdesc(st);
                uint64_t dKl = mkdesc(st + 16384);
#pragma unroll
                for (int k = 0; k < 4; k++)
                    mma_bf16_ss(tS, dQh + 2 * k, dKh + 2 * k, IDESC, !(c == 0 && k == 0));
#pragma unroll
                for (int k = 0; k < 4; k++)
                    mma_bf16_ss(tS, dQh + 2 * k, dKl + 2 * k, IDESC, true);
#pragma unroll
                for (int k = 0; k < 4; k++)
                    mma_bf16_ss(tS, dQl + 2 * k, dKh + 2 * k, IDESC, true);
                TC_COMMIT(mb);
            }
            MB_WAIT(mb, ph); ph ^= 1;
            if (sc + 2 < S) issue_slot(sc + 2);
            sc++;
        }
        TC_FENCE_AFTER();
        float sv[64];
        {
            uint32_t r0[32], r1[32];
            TCLD32(r0, tS + ch * 64);
            TCLD32(r1, tS + ch * 64 + 32);
            TC_WAIT_LD();
            const float scale = 0.07216878364870323f;
#pragma unroll
            for (int j = 0; j < 32; j++) {
                sv[j] = __uint_as_float(r0[j]) * scale;
                sv[32 + j] = __uint_as_float(r1[j]) * scale;
            }
        }
        if (t == mt) {
#pragma unroll
            for (int j = 0; j < 64; j++)
                if (ch * 64 + j > row) sv[j] = -INFINITY;
        }
        float pmax = -INFINITY;
#pragma unroll
        for (int j = 0; j < 64; j++) pmax = fmaxf(pmax, sv[j]);
        __syncthreads();
        ex[warp * 32 + lane] = pmax;
        __syncthreads();
        float m_new = fmaxf(m_old, fmaxf(pmax, ex[(warp ^ 4) * 32 + lane]));
        float alpha = __expf(m_old - m_new);
        bool norescale = (t == 0) || __all_sync(0xffffffffu, m_new == m_old);
        float psum = 0.0f;
#pragma unroll
        for (int j = 0; j < 64; j++) { sv[j] = __expf(sv[j] - m_new); psum += sv[j]; }
        __syncthreads();
        ex[warp * 32 + lane] = psum;
        __syncthreads();
        lsum = lsum * alpha + psum + ex[(warp ^ 4) * 32 + lane];
        m_old = m_new;
        {
            uint32_t baseh = smb + FPOFF + (ch * 2 + 0) * 16384;
            uint32_t basel = smb + FPOFF + (ch * 2 + 1) * 16384;
#pragma unroll
            for (int jj = 0; jj < 32; jj++) {
                float a = sv[2 * jj], bq = sv[2 * jj + 1];
                __nv_bfloat16 ah, al, bh, bl;
                bsplit(a, ah, al); bsplit(bq, bh, bl);
                uint32_t hi = ((uint32_t)__bfloat16_as_ushort(bh) << 16) | __bfloat16_as_ushort(ah);
                uint32_t lo = ((uint32_t)__bfloat16_as_ushort(bl) << 16) | __bfloat16_as_ushort(al);
                uint32_t off = sw128(row * 128 + 4 * jj);
                asm volatile("st.shared.b32 [%0], %1;" :: "r"(baseh + off), "r"(hi));
                asm volatile("st.shared.b32 [%0], %1;" :: "r"(basel + off), "r"(lo));
            }
        }
        if (!norescale) {
            uint32_t r0[32], r1[32];
            TCLD32(r0, tO + ch * 64);
            TCLD32(r1, tO + ch * 64 + 32);
            TC_WAIT_LD();
#pragma unroll
            for (int j = 0; j < 32; j++) {
                r0[j] = __float_as_uint(__uint_as_float(r0[j]) * alpha);
                r1[j] = __float_as_uint(__uint_as_float(r1[j]) * alpha);
            }
            TCST32(tO + ch * 64, r0);
            TCST32(tO + ch * 64 + 32, r1);
            TC_WAIT_ST();
        }
        FENCE_PROXY();
        TC_FENCE_BEFORE();
        __syncthreads();
        for (int vc = 0; vc < 2; vc++) {
            if (sc + 1 < S) { CP_WAIT(1); } else { CP_WAIT(0); }
            __syncthreads();
            FENCE_PROXY();
            if (warp == 0 && elect1()) {
                TC_FENCE_AFTER();
                uint32_t st = smb + FRING + (sc & 1) * 32768;
                uint64_t dPh = mkdesc(smb + FPOFF + (vc * 2 + 0) * 16384);
                uint64_t dPl = mkdesc(smb + FPOFF + (vc * 2 + 1) * 16384);
                uint64_t dVh = mkdesc(st);
                uint64_t dVl = mkdesc(st + 16384);
#pragma unroll
                for (int k = 0; k < 4; k++)
                    mma_bf16_ss(tO, dPh + 2 * k, dVh + 2 * k, IDESC, !(t == 0 && vc == 0 && k == 0));
#pragma unroll
                for (int k = 0; k < 4; k++)
                    mma_bf16_ss(tO, dPh + 2 * k, dVl + 2 * k, IDESC, true);
#pragma unroll
                for (int k = 0; k < 4; k++)
                    mma_bf16_ss(tO, dPl + 2 * k, dVh + 2 * k, IDESC, true);
                TC_COMMIT(mb);
            }
            MB_WAIT(mb, ph); ph ^= 1;
            if (sc + 2 < S) issue_slot(sc + 2);
            sc++;
        }
    }
    TC_FENCE_AFTER();
    {
        uint32_t r0[32], r1[32];
        TCLD32(r0, tO + ch * 64);
        TCLD32(r1, tO + ch * 64 + 32);
        TC_WAIT_LD();
        float inv = 1.0f / lsum;
        float* op = out + ((long long)(b * 1024 + m0 + row)) * 2048 + h * 128 + ch * 64;
#pragma unroll
        for (int j = 0; j < 8; j++) {
            float4 v = make_float4(__uint_as_float(r0[4*j]) * inv, __uint_as_float(r0[4*j+1]) * inv,
                                   __uint_as_float(r0[4*j+2]) * inv, __uint_as_float(r0[4*j+3]) * inv);
            *reinterpret_cast<float4*>(op + 4 * j) = v;
            float4 w = make_float4(__uint_as_float(r1[4*j]) * inv, __uint_as_float(r1[4*j+1]) * inv,
                                   __uint_as_float(r1[4*j+2]) * inv, __uint_as_float(r1[4*j+3]) * inv);
            *reinterpret_cast<float4*>(op + 32 + 4 * j) = w;
        }
    }
    __syncthreads();
    if (warp == 0) { TC_RELINQ(); TC_DEALLOC(tmem, 256); }
#endif
}

// ---------------- prep kernels ---------------------------------------------------
__global__ void split_copy(const float* __restrict__ in, __nv_bfloat16* __restrict__ out,
                           long long oPl, int n) {
    int i = blockIdx.x * blockDim.x + threadIdx.x;
    if (i >= n) return;
    __nv_bfloat16 h, l; bsplit(in[i], h, l);
    out[i] = h; out[i + oPl] = l;
}

__global__ void transpose_split(const float* __restrict__ in, __nv_bfloat16* __restrict__ out,
                                long long oPl, int R, int C) {
    __shared__ float tile[32][33];
    int bx = blockIdx.x * 32, by = blockIdx.y * 32;
    int tx = threadIdx.x, ty = threadIdx.y;
#pragma unroll
    for (int i = 0; i < 4; i++)
        tile[ty + i * 8][tx] = in[(long long)(by + ty + i * 8) * C + bx + tx];
    __syncthreads();
#pragma unroll
    for (int i = 0; i < 4; i++) {
        int c = bx + ty + i * 8, r = by + tx;
        __nv_bfloat16 h, l; bsplit(tile[tx][ty + i * 8], h, l);
        out[(long long)c * R + r] = h;
        out[(long long)c * R + r + oPl] = l;
    }
}

__global__ void build_wcat_split(const float* __restrict__ Wdq, const float* __restrict__ Wkr,
                                 __nv_bfloat16* __restrict__ out, long long oPl) {
    int i = blockIdx.x * blockDim.x + threadIdx.x;
    if (i >= 640 * 2048) return;
    int row = i >> 11;
    float v = 0.0f;
    if (row < 512) v = Wdq[i];
    else if (row < 576) v = Wkr[(row - 512) * 2048 + (i & 2047)];
    __nv_bfloat16 h, l; bsplit(v, h, l);
    out[i] = h; out[i + oPl] = l;
}

// ---------------- rope ----------------------------------------------------------
__global__ void rope_q_kernel(const float* __restrict__ cqr, const float* __restrict__ fc,
                              const float* __restrict__ fs, __nv_bfloat16* __restrict__ qh,
                              long long qPl) {
    int idx = blockIdx.x * blockDim.x + threadIdx.x;
    if (idx >= 4 * 1024 * 16 * 32) return;
    int j = idx & 31;
    int h = (idx >> 5) & 15;
    int t = (idx >> 9) & 1023;
    int b = idx >> 19;
    long long src = (((long long)(b * 1024 + t)) * 1024) + h * 64 + 2 * j;
    float re = cqr[src], im = cqr[src + 1];
    float c = fc[t * 32 + j], s = fs[t * 32 + j];
    float o0 = re * c - im * s, o1 = re * s + im * c;
    long long dst = (((long long)(b * 16 + h)) * 1024 + t) * 192 + 128 + 2 * j;
    __nv_bfloat16 h0, l0, h1, l1; bsplit(o0, h0, l0); bsplit(o1, h1, l1);
    qh[dst] = h0; qh[dst + qPl] = l0;
    qh[dst + 1] = h1; qh[dst + 1 + qPl] = l1;
}

__global__ void rope_k_kernel(const float* __restrict__ cqx_f, const float* __restrict__ fc,
                              const float* __restrict__ fs, __nv_bfloat16* __restrict__ kh,
                              long long kPl) {
    int idx = blockIdx.x * blockDim.x + threadIdx.x;
    if (idx >= 4 * 1024 * 32) return;
    int j = idx & 31;
    int t = (idx >> 5) & 1023;
    int b = idx >> 15;
    long long src = ((long long)(b * 1024 + t)) * 640 + 512 + 2 * j;
    float re = cqx_f[src], im = cqx_f[src + 1];
    float c = fc[t * 32 + j], s = fs[t * 32 + j];
    float o0 = re * c - im * s, o1 = re * s + im * c;
    __nv_bfloat16 h0, l0, h1, l1; bsplit(o0, h0, l0); bsplit(o1, h1, l1);
#pragma unroll
    for (int h = 0; h < 16; h++) {
        long long dst = (((long long)(b * 16 + h)) * 1024 + t) * 192 + 128 + 2 * j;
        kh[dst] = h0; kh[dst + kPl] = l0;
        kh[dst + 1] = h1; kh[dst + 1 + kPl] = l1;
    }
}

// ---------------- launcher -------------------------------------------------------
extern "C" void kernel_launch(void* const* d_in, const int* in_sizes, int n_in,
                              void* d_out, int out_size) {
    (void)in_sizes; (void)n_in; (void)out_size;
    const float* x     = (const float*)d_in[0];
    const float* W_dq  = (const float*)d_in[1];
    const float* W_uq  = (const float*)d_in[2];
    const float* W_dkv = (const float*)d_in[3];
    const float* W_uk  = (const float*)d_in[4];
    const float* W_uv  = (const float*)d_in[5];
    const float* W_o   = (const float*)d_in[6];
    const float* W_qr  = (const float*)d_in[7];
    const float* W_kr  = (const float*)d_in[8];
    const float* fc    = (const float*)d_in[9];
    const float* fs    = (const float*)d_in[10];
    float* out = (float*)d_out;

    __nv_bfloat16 *x2, *wcat2, *wdkv2, *wqr2, *wuqT2, *wuk2, *wuvT2, *wo2, *mt2;
    __nv_bfloat16 *cqx2, *qh2, *kh2, *kcat2, *vt2;
    float *cqx_f, *cqr;
    cudaGetSymbolAddress((void**)&x2,     g_x2);
    cudaGetSymbolAddress((void**)&wcat2,  g_wcat2);
    cudaGetSymbolAddress((void**)&wdkv2,  g_wdkv2);
    cudaGetSymbolAddress((void**)&wqr2,   g_wqr2);
    cudaGetSymbolAddress((void**)&wuqT2,  g_wuqT2);
    cudaGetSymbolAddress((void**)&wuk2,   g_wuk2);
    cudaGetSymbolAddress((void**)&wuvT2,  g_wuvT2);
    cudaGetSymbolAddress((void**)&wo2,    g_wo2);
    cudaGetSymbolAddress((void**)&mt2,    g_mt2);
    cudaGetSymbolAddress((void**)&cqx2,   g_cqx2);
    cudaGetSymbolAddress((void**)&cqx_f,  g_cqx_f);
    cudaGetSymbolAddress((void**)&cqr,    g_cqr);
    cudaGetSymbolAddress((void**)&qh2,    g_qh2);
    cudaGetSymbolAddress((void**)&kh2,    g_kh2);
    cudaGetSymbolAddress((void**)&kcat2,  g_kcat2);
    cudaGetSymbolAddress((void**)&vt2,    g_vt2);

    const long long XPL   = 4096LL * 2048;
    const long long WCPL  = 640LL * 2048;
    const long long WDPL  = 512LL * 2048;
    const long long WQRPL = 1024LL * 512;
    const long long WUQPL = 2048LL * 512;
    const long long WUKPL = 2048LL * 512;
    const long long WUVPL = 512LL * 2048;
    const long long WOPL  = 2048LL * 2048;
    const long long MTPL  = 2048LL * 512;
    const long long CQXPL = 4096LL * 640;
    const long long HPL   = 64LL * 1024 * 192;
    const long long KCPL  = 4096LL * 512;
    const long long VTPL  = 64LL * 128 * 1024;
    const long long HZ    = 1024LL * 192;
    const long long VTZ   = 128LL * 1024;

    cudaFuncSetAttribute(gemm_t5<true,  true,  false>, cudaFuncAttributeMaxDynamicSharedMemorySize, GSMEM);
    cudaFuncSetAttribute(gemm_t5<false, true,  false>, cudaFuncAttributeMaxDynamicSharedMemorySize, GSMEM);
    cudaFuncSetAttribute(gemm_t5<true,  false, false>, cudaFuncAttributeMaxDynamicSharedMemorySize, GSMEM);
    cudaFuncSetAttribute(gemm_t5<false, true,  true >, cudaFuncAttributeMaxDynamicSharedMemorySize, GSMEM);
    cudaFuncSetAttribute(flash_attn, cudaFuncAttributeMaxDynamicSharedMemorySize, FSMEM);

    dim3 blk(256);

    // --- prep: split / transpose ---
    split_copy<<<(8388608 + 255) / 256, 256>>>(x,     x2,    XPL,   8388608);
    split_copy<<<(1048576 + 255) / 256, 256>>>(W_dkv, wdkv2, WDPL,  1048576);
    split_copy<<<(524288  + 255) / 256, 256>>>(W_qr,  wqr2,  WQRPL, 524288);
    split_copy<<<(1048576 + 255) / 256, 256>>>(W_uk,  wuk2,  WUKPL, 1048576);
    split_copy<<<(4194304 + 255) / 256, 256>>>(W_o,   wo2,   WOPL,  4194304);
    transpose_split<<<dim3(64, 16), dim3(32, 8)>>>(W_uq, wuqT2, WUQPL, 512, 2048);
    transpose_split<<<dim3(16, 64), dim3(32, 8)>>>(W_uv, wuvT2, WUVPL, 2048, 512);
    build_wcat_split<<<(640 * 2048 + 255) / 256, 256>>>(W_dq, W_kr, wcat2, WCPL);

    // 1) cqx (4096x640) = x @ Wcat^T      [f32 + planes]
    gemm_t5<true, true, false><<<dim3(5, 32, 1), blk, GSMEM>>>(
        x2, XPL, wcat2, WCPL, cqx_f, cqx2, CQXPL,
        2048, 2048, 2048, 640, 0, 0, 0, 0, 0, 0, 1, 0);

    // 2) c_kv (4096x512) = x @ W_dkv^T    [planes]
    gemm_t5<false, true, false><<<dim3(4, 32, 1), blk, GSMEM>>>(
        x2, XPL, wdkv2, WDPL, nullptr, kcat2, KCPL,
        2048, 2048, 2048, 512, 0, 0, 0, 0, 0, 0, 1, 0);

    // 3) MT (2048x512) = Wo @ WuvT^T      [planes]
    gemm_t5<false, true, false><<<dim3(4, 16, 1), blk, GSMEM>>>(
        wo2, WOPL, wuvT2, WUVPL, nullptr, mt2, MTPL,
        2048, 2048, 2048, 512, 0, 0, 0, 0, 0, 0, 1, 0);

    // 4) c_qr (4096x1024) = c_q @ W_qr^T  [f32]
    gemm_t5<true, false, false><<<dim3(8, 32, 1), blk, GSMEM>>>(
        cqx2, CQXPL, wqr2, WQRPL, cqr, nullptr, 0,
        512, 640, 512, 1024, 0, 0, 0, 0, 0, 0, 1, 0);

    // 5) q per head: qh[:, 0:128] = c_q[b] @ WuqT^T  (head-sliced C)
    gemm_t5<false, true, true><<<dim3(16, 8, 4), blk, GSMEM>>>(
        cqx2, CQXPL, wuqT2, WUQPL, nullptr, qh2, HPL,
        512, 640, 512, 192,
        1024LL * 640, 0, 0, 0, 16LL * HZ, 0, 1, HZ);

    // 6) k per head: kh[:, 0:128] = c_kv[b] @ W_uk^T
    gemm_t5<false, true, true><<<dim3(16, 8, 4), blk, GSMEM>>>(
        kcat2, KCPL, wuk2, WUKPL, nullptr, kh2, HPL,
        512, 512, 512, 192,
        1024LL * 512, 0, 0, 0, 16LL * HZ, 0, 1, HZ);

    // 7) rope tails (split-write)
    rope_q_kernel<<<8192, 256>>>(cqr, fc, fs, qh2, HPL);
    rope_k_kernel<<<512, 256>>>(cqx_f, fc, fs, kh2, HPL);

    // 8) VT[b,h] (128x1024) = MT[h-slice] @ c_kv[b]^T   [planes]
    gemm_t5<false, true, false><<<dim3(8, 1, 64), blk, GSMEM>>>(
        mt2, MTPL, kcat2, KCPL, nullptr, vt2, VTPL,
        512, 512, 512, 1024,
        0, 128LL * 512, 1024LL * 512, 0, 16LL * VTZ, VTZ, 16, 0);

    // 9) fused flash attention: logits + softmax + PV -> out
    flash_attn<<<dim3(8, 16, 4), blk, FSMEM>>>(qh2, kh2, vt2, out);
}

// round 12
// speedup vs baseline: 2.9503x; 1.0303x over previous
#include <cuda_runtime.h>
#include <cuda_bf16.h>
#include <math.h>
#include <stdint.h>

// B=4, T=1024, C=2048, NH=16, HS=128, NLQ=512, NLKV=512, DHR=64
// scale = 1/sqrt(192)

#if !defined(__CUDA_ARCH__) || defined(__CUDA_ARCH_SPECIFIC__) || \
    defined(__CUDA_ARCH_FEAT_SM103_ALL) || defined(__CUDA_ARCH_FEAT_SM100_ALL) || \
    defined(__CUDA_ARCH_FEAT_SM101_ALL)
#define HAS_TC 1
#else
#define HAS_TC 0
#endif

// ---------------- scratch (device globals; [2][..] = bf16 hi/lo planes) --------
__device__ __nv_bfloat16 g_x2[2][4096L * 2048];
__device__ __nv_bfloat16 g_wca2[2][1280L * 2048];     // [W_dq;W_kr;W_dkv;pad]
__device__ __nv_bfloat16 g_wqr2[2][1024L * 512];
__device__ __nv_bfloat16 g_wuqT2[2][2048L * 512];     // Wuq_flat^T
__device__ __nv_bfloat16 g_wuk2[2][2048L * 512];
__device__ __nv_bfloat16 g_wuvT2[2][512L * 2048];     // Wuv_flat^T
__device__ __nv_bfloat16 g_wo2[2][2048L * 2048];
__device__ __nv_bfloat16 g_mt2[2][2048L * 512];       // M^T = Wo @ Wuv
__device__ __nv_bfloat16 g_cqkv2[2][4096L * 1280];    // [c_q | c_kr | c_kv | pad]
__device__ float         g_cqkv_f[4096L * 1280];
__device__ float         g_cqr[4096L * 1024];
__device__ __nv_bfloat16 g_qh2[2][64L * 1024 * 192];  // per-head [q_c | q_r]
__device__ __nv_bfloat16 g_kh2[2][64L * 1024 * 192];  // per-head [k_c | k_r]
__device__ __nv_bfloat16 g_vt2[2][64L * 128 * 1024];  // V^T per (b,h)

// ---------------- PTX helpers ---------------------------------------------------
__device__ __forceinline__ uint32_t elect1() {
    uint32_t p;
    asm volatile("{\n\t.reg .pred p;\n\telect.sync _|p, 0xFFFFFFFF;\n\t"
                 "selp.b32 %0, 1, 0, p;\n\t}" : "=r"(p));
    return p;
}
__device__ __forceinline__ uint32_t s2u(const void* p) {
    uint32_t a;
    asm("{ .reg .u64 t; cvta.to.shared.u64 t, %1; cvt.u32.u64 %0, t; }" : "=r"(a) : "l"(p));
    return a;
}
#define TC_ALLOC(sm, n)  asm volatile("tcgen05.alloc.cta_group::1.sync.aligned.shared::cta.b32 [%0], %1;" :: "r"(sm), "r"(n) : "memory")
#define TC_DEALLOC(t, n) asm volatile("tcgen05.dealloc.cta_group::1.sync.aligned.b32 %0, %1;" :: "r"(t), "r"(n))
#define TC_RELINQ()      asm volatile("tcgen05.relinquish_alloc_permit.cta_group::1.sync.aligned;")
#define TC_COMMIT(mb)    asm volatile("tcgen05.commit.cta_group::1.mbarrier::arrive::one.shared::cluster.b64 [%0];" :: "r"(mb) : "memory")
#define TC_FENCE_AFTER() asm volatile("tcgen05.fence::after_thread_sync;" ::: "memory")
#define TC_FENCE_BEFORE() asm volatile("tcgen05.fence::before_thread_sync;" ::: "memory")
#define TC_WAIT_LD()     asm volatile("tcgen05.wait::ld.sync.aligned;" ::: "memory")
#define TC_WAIT_ST()     asm volatile("tcgen05.wait::st.sync.aligned;" ::: "memory")
#define FENCE_PROXY()    asm volatile("fence.proxy.async.shared::cta;" ::: "memory")
#define MB_INIT(mb, c)   asm volatile("mbarrier.init.shared.b64 [%0], %1;" :: "r"(mb), "r"(c) : "memory")
#define MB_WAIT(mb, ph) do { \
    asm volatile("{\n\t.reg .pred P1;\n\tWL_%=:\n\t" \
        "mbarrier.try_wait.parity.acquire.cta.shared::cta.b64 P1, [%0], %1, 0x989680;\n\t" \
        "@P1 bra.uni WD_%=;\n\tbra.uni WL_%=;\n\tWD_%=:\n\t}" \
        :: "r"(mb), "r"((uint32_t)(ph)) : "memory"); \
} while (0)
#define CP16(dst, src)   asm volatile("cp.async.cg.shared.global [%0], [%1], 16;" :: "r"(dst), "l"(src))
#define CP_COMMIT()      asm volatile("cp.async.commit_group;")
#define CP_WAIT(n)       asm volatile("cp.async.wait_group %0;" :: "n"(n))

#define TCLD32(r, a) \
    asm volatile("tcgen05.ld.sync.aligned.32x32b.x32.b32 " \
        "{%0,%1,%2,%3,%4,%5,%6,%7,%8,%9,%10,%11,%12,%13,%14,%15," \
        "%16,%17,%18,%19,%20,%21,%22,%23,%24,%25,%26,%27,%28,%29,%30,%31}, [%32];" \
        : "=r"((r)[0]),"=r"((r)[1]),"=r"((r)[2]),"=r"((r)[3]),"=r"((r)[4]),"=r"((r)[5]), \
          "=r"((r)[6]),"=r"((r)[7]),"=r"((r)[8]),"=r"((r)[9]),"=r"((r)[10]),"=r"((r)[11]), \
          "=r"((r)[12]),"=r"((r)[13]),"=r"((r)[14]),"=r"((r)[15]),"=r"((r)[16]),"=r"((r)[17]), \
          "=r"((r)[18]),"=r"((r)[19]),"=r"((r)[20]),"=r"((r)[21]),"=r"((r)[22]),"=r"((r)[23]), \
          "=r"((r)[24]),"=r"((r)[25]),"=r"((r)[26]),"=r"((r)[27]),"=r"((r)[28]),"=r"((r)[29]), \
          "=r"((r)[30]),"=r"((r)[31]) : "r"(a))

#define TCST32(a, r) \
    asm volatile("tcgen05.st.sync.aligned.32x32b.x32.b32 [%0], " \
        "{%1,%2,%3,%4,%5,%6,%7,%8,%9,%10,%11,%12,%13,%14,%15,%16," \
        "%17,%18,%19,%20,%21,%22,%23,%24,%25,%26,%27,%28,%29,%30,%31,%32};" \
        :: "r"(a), \
          "r"((r)[0]),"r"((r)[1]),"r"((r)[2]),"r"((r)[3]),"r"((r)[4]),"r"((r)[5]), \
          "r"((r)[6]),"r"((r)[7]),"r"((r)[8]),"r"((r)[9]),"r"((r)[10]),"r"((r)[11]), \
          "r"((r)[12]),"r"((r)[13]),"r"((r)[14]),"r"((r)[15]),"r"((r)[16]),"r"((r)[17]), \
          "r"((r)[18]),"r"((r)[19]),"r"((r)[20]),"r"((r)[21]),"r"((r)[22]),"r"((r)[23]), \
          "r"((r)[24]),"r"((r)[25]),"r"((r)[26]),"r"((r)[27]),"r"((r)[28]),"r"((r)[29]), \
          "r"((r)[30]),"r"((r)[31]) : "memory")

#if HAS_TC
__device__ __forceinline__ void mma_bf16_ss(uint32_t d, uint64_t a, uint64_t b,
                                            uint32_t idesc, bool en) {
    uint32_t e = en ? 1u : 0u;
    asm volatile("{\n\t.reg .pred p;\n\tsetp.ne.u32 p, %5, 0;\n\t"
        "tcgen05.mma.cta_group::1.kind::f16 [%0], %1, %2, %3, {%4, %4, %4, %4}, p;\n\t}"
        :: "r"(d), "l"(a), "l"(b), "r"(idesc), "r"(0u), "r"(e) : "memory");
}
#endif

// idesc: dtype F32, a/b BF16, M=128; N=128 -> 0x8200490, N=256 -> 0x8400490
#define IDESC128 0x8200490u
#define IDESC256 0x8400490u
#define DESC_BASE ((2ULL << 61) | (1ULL << 46) | (64ULL << 32) | (1ULL << 16))
__device__ __forceinline__ uint64_t mkdesc(uint32_t addr) {
    return DESC_BASE | ((uint64_t)(addr >> 4) & 0x3FFF);
}
__device__ __forceinline__ uint32_t sw128(uint32_t b) { return b ^ ((b >> 3) & 0x70); }

__device__ __forceinline__ void bsplit(float v, __nv_bfloat16& h, __nv_bfloat16& l) {
    h = __float2bfloat16_rn(v);
    l = __float2bfloat16_rn(v - __bfloat162float(h));
}

// ---------------- tcgen05 GEMM v3: persistent, NT=128/256 tiles -----------------
// D = A @ B^T (A: MxK row-tiles of 128, B: NxK tiles of NT, K-major).
// bf16 2-term split (3 MMAs/product), fp32 TMEM accum, lagged mbarrier pipeline.
#define GSMEM 197632

template <int NT, bool WF32, bool WB16, bool HEADC>
__global__ void __launch_bounds__(256, 1) gemm_t6(
        const __nv_bfloat16* __restrict__ A, long long aPl,
        const __nv_bfloat16* __restrict__ B, long long bPl,
        float* __restrict__ Cf, __nv_bfloat16* __restrict__ Cb, long long cPl,
        int K, int lda, int ldb, int ldc,
        long long sAq, long long sAr, long long sBq, long long sBr,
        long long sCq, long long sCr, int zdiv, long long sHC,
        int tx, int ty, int tz) {
#if HAS_TC
    constexpr int S = (NT == 128) ? 3 : 2;            // pipeline stages
    constexpr int PB = NT * 128;                      // B plane bytes
    constexpr int STG = 2 * 16384 + 2 * PB;           // stage bytes
    constexpr int BPC = NT * 8;                       // B chunks per plane
    constexpr int ITER = (2048 + 2 * BPC) / 256;      // CP16s per thread
    constexpr uint32_t ID = (NT == 128) ? IDESC128 : IDESC256;

    extern __shared__ __align__(1024) char smem[];
    const uint32_t smb = s2u(smem);
    const uint32_t mb0 = smb + 16, mb1 = smb + 24, mb2 = smb + 32;

    const int tid = threadIdx.x;
    const int warp = tid >> 5;
    const int lane = tid & 31;
    const int WT = tx * ty * tz;
    const int nt = K >> 6;

    if (warp == 0) TC_ALLOC(smb, NT);
    if (tid == 0) { MB_INIT(mb0, 1); MB_INIT(mb1, 1); MB_INIT(mb2, 1); }
    __syncthreads();
    uint32_t tmem;
    asm volatile("ld.shared.b32 %0, [%1];" : "=r"(tmem) : "r"(smb));

    int ph0 = 0, ph1 = 0, ph2 = 0;

    for (int w = blockIdx.x; w < WT; w += gridDim.x) {
        const int xt = w % tx;
        const int rw = w / tx;
        const int yt = rw % ty;
        const int z  = rw / ty;
        const int m0 = yt * 128, n0 = xt * NT;
        const int zq = z / zdiv, zr = z % zdiv;
        const __nv_bfloat16* Ab = A + (long long)zq * sAq + (long long)zr * sAr;
        const __nv_bfloat16* Bb = B + (long long)zq * sBq + (long long)zr * sBr;
        const long long cbase = (long long)zq * sCq + (long long)zr * sCr +
                                (HEADC ? (long long)xt * (NT / 128) * sHC : 0);

        auto issue_load = [&](int c) {
            const uint32_t st = smb + 1024 + (c % S) * STG;
            const int k0 = c << 6;
#pragma unroll
            for (int i = 0; i < ITER; i++) {
                int idx = tid + i * 256;
                if (idx < 2048) {
                    int plane = idx >> 10, cc = idx & 1023;
                    int r = cc >> 3, cq = cc & 7;
                    CP16(st + plane * 16384 + sw128(r * 128 + cq * 16),
                         Ab + (long long)plane * aPl + (long long)(m0 + r) * lda + k0 + cq * 8);
                } else {
                    int j = idx - 2048;
                    int plane = j / BPC, cc = j % BPC;
                    int r = cc >> 3, cq = cc & 7;
                    CP16(st + 32768 + plane * PB + sw128(r * 128 + cq * 16),
                         Bb + (long long)plane * bPl + (long long)(n0 + r) * ldb + k0 + cq * 8);
                }
            }
            CP_COMMIT();
        };
        auto waitmma = [&](int j) {
            int bsel = j % 3;
            if (bsel == 0)      { MB_WAIT(mb0, ph0); ph0 ^= 1; }
            else if (bsel == 1) { MB_WAIT(mb1, ph1); ph1 ^= 1; }
            else                { MB_WAIT(mb2, ph2); ph2 ^= 1; }
        };

        for (int c = 0; c < S - 1 && c < nt; c++) issue_load(c);

        for (int c = 0; c < nt; c++) {
            if (c + 1 < nt) { CP_WAIT(S - 2); } else { CP_WAIT(0); }
            __syncthreads();
            FENCE_PROXY();
            if (warp == 0 && elect1()) {
                const uint32_t st = smb + 1024 + (c % S) * STG;
                uint64_t dAh = mkdesc(st);
                uint64_t dAl = mkdesc(st + 16384);
                uint64_t dBh = mkdesc(st + 32768);
                uint64_t dBl = mkdesc(st + 32768 + PB);
#pragma unroll
                for (int k = 0; k < 4; k++)
                    mma_bf16_ss(tmem, dAh + 2 * k, dBh + 2 * k, ID, !(c == 0 && k == 0));
#pragma unroll
                for (int k = 0; k < 4; k++)
                    mma_bf16_ss(tmem, dAh + 2 * k, dBl + 2 * k, ID, true);
#pragma unroll
                for (int k = 0; k < 4; k++)
                    mma_bf16_ss(tmem, dAl + 2 * k, dBh + 2 * k, ID, true);
                int bsel = c % 3;
                TC_COMMIT(smb + 16 + 8 * bsel);
            }
            if (c >= 1) waitmma(c - 1);
            if (c + S - 1 < nt) issue_load(c + S - 1);
        }
        waitmma(nt - 1);
        CP_WAIT(0);
        __syncthreads();
        TC_FENCE_AFTER();

        // epilogue: TMEM -> regs -> smem (stride NT+4) -> coalesced gmem
        float* et = (float*)(smem + 1024);
        {
            const int lrow = (warp & 3) * 32 + lane;
            const int cb = (warp >> 2) * (NT / 2);
            uint32_t dr[32];
#pragma unroll
            for (int half = 0; half < NT / 64; half++) {
                TCLD32(dr, tmem + cb + half * 32);
                TC_WAIT_LD();
                float* p = et + lrow * (NT + 4) + cb + half * 32;
#pragma unroll
                for (int cc = 0; cc < 32; cc++) p[cc] = __uint_as_float(dr[cc]);
            }
        }
        __syncthreads();
        {
#pragma unroll
            for (int i = 0; i < NT / 8; i++) {
                int idx = tid + i * 256;
                int r = idx / (NT / 4), q = idx % (NT / 4);
                int col4 = q * 4;
                const float* p = et + r * (NT + 4) + col4;
                float4 v = make_float4(p[0], p[1], p[2], p[3]);
                long long hoff = (HEADC && col4 >= 128) ? sHC : 0;
                int col = HEADC ? (col4 & 127) : (n0 + col4);
                long long off = cbase + hoff + (long long)(m0 + r) * ldc + col;
                if (WF32) *reinterpret_cast<float4*>(&Cf[off]) = v;
                if (WB16) {
                    __nv_bfloat16 hx, lx, hy, ly, hz, lz, hw, lw;
                    bsplit(v.x, hx, lx); bsplit(v.y, hy, ly);
                    bsplit(v.z, hz, lz); bsplit(v.w, hw, lw);
                    uint2 hi = make_uint2(
                        (uint32_t)__bfloat16_as_ushort(hx) | ((uint32_t)__bfloat16_as_ushort(hy) << 16),
                        (uint32_t)__bfloat16_as_ushort(hz) | ((uint32_t)__bfloat16_as_ushort(hw) << 16));
                    uint2 lo = make_uint2(
                        (uint32_t)__bfloat16_as_ushort(lx) | ((uint32_t)__bfloat16_as_ushort(ly) << 16),
                        (uint32_t)__bfloat16_as_ushort(lz) | ((uint32_t)__bfloat16_as_ushort(lw) << 16));
                    *reinterpret_cast<uint2*>(&Cb[off]) = hi;
                    *reinterpret_cast<uint2*>(&Cb[off + cPl]) = lo;
                }
            }
        }
        __syncthreads();
    }
    if (warp == 0) { TC_RELINQ(); TC_DEALLOC(tmem, NT); }
#endif
}

// ---------------- fused flash attention (persistent, boustrophedon) -------------
#define FQOFF 2048
#define FRING (FQOFF + 6 * 16384)
#define FPOFF (FRING + 2 * 32768)
#define FSMEM (FPOFF + 4 * 16384)     // 231424

__global__ void __launch_bounds__(256, 1) flash_attn(
        const __nv_bfloat16* __restrict__ qh, const __nv_bfloat16* __restrict__ kh,
        const __nv_bfloat16* __restrict__ vt, float* __restrict__ out) {
#if HAS_TC
    const long long QKPL = 64LL * 1024 * 192;
    const long long VPL  = 64LL * 128 * 1024;

    extern __shared__ __align__(1024) char smem[];
    const uint32_t smb = s2u(smem);
    const uint32_t mb = smb + 16;
    float* ex = (float*)(smem + 32);

    const int tid = threadIdx.x, warp = tid >> 5, lane = tid & 31;
    const int ch = warp >> 2;
    const int row = (warp & 3) * 32 + lane;
    const int bx = blockIdx.x;

    if (warp == 0) TC_ALLOC(smb, 256);
    if (tid == 0) MB_INIT(mb, 1);
    __syncthreads();
    uint32_t tmem;
    asm volatile("ld.shared.b32 %0, [%1];" : "=r"(tmem) : "r"(smb));
    const uint32_t tS = tmem, tO = tmem + 128;

    int ph = 0;

    for (int p = 0; p < 4; p++) {
        int item = p * 148 + ((p & 1) ? (147 - bx) : bx);
        if (item >= 512) continue;
        const int mt = 7 - (item >> 6);
        const int h = item & 15;
        const int b = (item >> 4) & 3;
        const int ntile = mt + 1, m0 = mt * 128;
        const int S = 5 * ntile;
        const __nv_bfloat16* Qb = qh + (long long)(b * 16 + h) * (1024LL * 192);
        const __nv_bfloat16* Kb = kh + (long long)(b * 16 + h) * (1024LL * 192);
        const __nv_bfloat16* Vb = vt + (long long)(b * 16 + h) * (128LL * 1024);

        {
#pragma unroll
            for (int i = 0; i < 24; i++) {
                int idx = tid + i * 256;
                int cp = idx >> 10;
                int c = cp >> 1, pl = cp & 1;
                int cidx = idx & 1023, rr = cidx >> 3, cc = cidx & 7;
                const __nv_bfloat16* src = Qb + (long long)pl * QKPL +
                    (long long)(m0 + rr) * 192 + c * 64 + cc * 8;
                CP16(smb + FQOFF + cp * 16384 + sw128(rr * 128 + cc * 16), src);
            }
            CP_COMMIT();
        }
        auto issue_slot = [&](int s) {
            int t = s / 5, r = s % 5;
            uint32_t dst = smb + FRING + (s & 1) * 32768;
#pragma unroll
            for (int i = 0; i < 8; i++) {
                int idx = tid + i * 256;
                int pl = idx >> 10, cidx = idx & 1023, rr = cidx >> 3, cc = cidx & 7;
                const __nv_bfloat16* src;
                if (r < 3)
                    src = Kb + (long long)pl * QKPL + (long long)(t * 128 + rr) * 192 + r * 64 + cc * 8;
                else
                    src = Vb + (long long)pl * VPL + (long long)rr * 1024 + t * 128 + (r - 3) * 64 + cc * 8;
                CP16(dst + pl * 16384 + sw128(rr * 128 + cc * 16), src);
            }
            CP_COMMIT();
        };
        issue_slot(0);
        if (S > 1) issue_slot(1);

        float m_old = -INFINITY, lsum = 0.0f;
        int sc = 0;

        for (int t = 0; t < ntile; t++) {
            for (int c = 0; c < 3; c++) {
                if (sc + 1 < S) { CP_WAIT(1); } else { CP_WAIT(0); }
                __syncthreads();
                FENCE_PROXY();
                if (warp == 0 && elect1()) {
                    uint32_t st = smb + FRING + (sc & 1) * 32768;
                    uint64_t dQh = mkdesc(smb + FQOFF + (c * 2 + 0) * 16384);
                    uint64_t dQl = mkdesc(smb + FQOFF + (c * 2 + 1) * 16384);
                    uint64_t dKh = mkdesc(st);
                    uint64_t dKl = mkdesc(st + 16384);
#pragma unroll
                    for (int k = 0; k < 4; k++)
                        mma_bf16_ss(tS, dQh + 2 * k, dKh + 2 * k, IDESC128, !(c == 0 && k == 0));
#pragma unroll
                    for (int k = 0; k < 4; k++)
                        mma_bf16_ss(tS, dQh + 2 * k, dKl + 2 * k, IDESC128, true);
#pragma unroll
                    for (int k = 0; k < 4; k++)
                        mma_bf16_ss(tS, dQl + 2 * k, dKh + 2 * k, IDESC128, true);
                    TC_COMMIT(mb);
                }
                MB_WAIT(mb, ph); ph ^= 1;
                if (sc + 2 < S) issue_slot(sc + 2);
                sc++;
            }
            TC_FENCE_AFTER();
            float sv[64];
            {
                uint32_t r0[32], r1[32];
                TCLD32(r0, tS + ch * 64);
                TCLD32(r1, tS + ch * 64 + 32);
                TC_WAIT_LD();
                const float scale = 0.07216878364870323f;
#pragma unroll
                for (int j = 0; j < 32; j++) {
                    sv[j] = __uint_as_float(r0[j]) * scale;
                    sv[32 + j] = __uint_as_float(r1[j]) * scale;
                }
            }
            if (t == mt) {
#pragma unroll
                for (int j = 0; j < 64; j++)
                    if (ch * 64 + j > row) sv[j] = -INFINITY;
            }
            float pmax = -INFINITY;
#pragma unroll
            for (int j = 0; j < 64; j++) pmax = fmaxf(pmax, sv[j]);
            __syncthreads();
            ex[warp * 32 + lane] = pmax;
            __syncthreads();
            float m_new = fmaxf(m_old, fmaxf(pmax, ex[(warp ^ 4) * 32 + lane]));
            float alpha = __expf(m_old - m_new);
            bool norescale = (t == 0) || __all_sync(0xffffffffu, m_new == m_old);
            float psum = 0.0f;
#pragma unroll
            for (int j = 0; j < 64; j++) { sv[j] = __expf(sv[j] - m_new); psum += sv[j]; }
            __syncthreads();
            ex[warp * 32 + lane] = psum;
            __syncthreads();
            lsum = lsum * alpha + psum + ex[(warp ^ 4) * 32 + lane];
            m_old = m_new;
            {
                uint32_t baseh = smb + FPOFF + (ch * 2 + 0) * 16384;
                uint32_t basel = smb + FPOFF + (ch * 2 + 1) * 16384;
#pragma unroll
                for (int jj = 0; jj < 32; jj++) {
                    float a = sv[2 * jj], bq = sv[2 * jj + 1];
                    __nv_bfloat16 ah, al, bh, bl;
                    bsplit(a, ah, al); bsplit(bq, bh, bl);
                    uint32_t hi = ((uint32_t)__bfloat16_as_ushort(bh) << 16) | __bfloat16_as_ushort(ah);
                    uint32_t lo = ((uint32_t)__bfloat16_as_ushort(bl) << 16) | __bfloat16_as_ushort(al);
                    uint32_t off = sw128(row * 128 + 4 * jj);
                    asm volatile("st.shared.b32 [%0], %1;" :: "r"(baseh + off), "r"(hi));
                    asm volatile("st.shared.b32 [%0], %1;" :: "r"(basel + off), "r"(lo));
                }
            }
            if (!norescale) {
                uint32_t r0[32], r1[32];
                TCLD32(r0, tO + ch * 64);
                TCLD32(r1, tO + ch * 64 + 32);
                TC_WAIT_LD();
#pragma unroll
                for (int j = 0; j < 32; j++) {
                    r0[j] = __float_as_uint(__uint_as_float(r0[j]) * alpha);
                    r1[j] = __float_as_uint(__uint_as_float(r1[j]) * alpha);
                }
                TCST32(tO + ch * 64, r0);
                TCST32(tO + ch * 64 + 32, r1);
                TC_WAIT_ST();
            }
            FENCE_PROXY();
            TC_FENCE_BEFORE();
            __syncthreads();
            for (int vc = 0; vc < 2; vc++) {
                if (sc + 1 < S) { CP_WAIT(1); } else { CP_WAIT(0); }
                __syncthreads();
                FENCE_PROXY();
                if (warp == 0 && elect1()) {
                    TC_FENCE_AFTER();
                    uint32_t st = smb + FRING + (sc & 1) * 32768;
                    uint64_t dPh = mkdesc(smb + FPOFF + (vc * 2 + 0) * 16384);
                    uint64_t dPl = mkdesc(smb + FPOFF + (vc * 2 + 1) * 16384);
                    uint64_t dVh = mkdesc(st);
                    uint64_t dVl = mkdesc(st + 16384);
#pragma unroll
                    for (int k = 0; k < 4; k++)
                        mma_bf16_ss(tO, dPh + 2 * k, dVh + 2 * k, IDESC128, !(t == 0 && vc == 0 && k == 0));
#pragma unroll
                    for (int k = 0; k < 4; k++)
                        mma_bf16_ss(tO, dPh + 2 * k, dVl + 2 * k, IDESC128, true);
#pragma unroll
                    for (int k = 0; k < 4; k++)
                        mma_bf16_ss(tO, dPl + 2 * k, dVh + 2 * k, IDESC128, true);
                    TC_COMMIT(mb);
                }
                MB_WAIT(mb, ph); ph ^= 1;
                if (sc + 2 < S) issue_slot(sc + 2);
                sc++;
            }
        }
        TC_FENCE_AFTER();
        {
            uint32_t r0[32], r1[32];
            TCLD32(r0, tO + ch * 64);
            TCLD32(r1, tO + ch * 64 + 32);
            TC_WAIT_LD();
            float inv = 1.0f / lsum;
            float* op = out + ((long long)(b * 1024 + m0 + row)) * 2048 + h * 128 + ch * 64;
#pragma unroll
            for (int j = 0; j < 8; j++) {
                float4 v = make_float4(__uint_as_float(r0[4*j]) * inv, __uint_as_float(r0[4*j+1]) * inv,
                                       __uint_as_float(r0[4*j+2]) * inv, __uint_as_float(r0[4*j+3]) * inv);
                *reinterpret_cast<float4*>(op + 4 * j) = v;
                float4 w = make_float4(__uint_as_float(r1[4*j]) * inv, __uint_as_float(r1[4*j+1]) * inv,
                                       __uint_as_float(r1[4*j+2]) * inv, __uint_as_float(r1[4*j+3]) * inv);
                *reinterpret_cast<float4*>(op + 32 + 4 * j) = w;
            }
        }
        __syncthreads();
    }
    if (warp == 0) { TC_RELINQ(); TC_DEALLOC(tmem, 256); }
#endif
}

// ---------------- prep kernels ---------------------------------------------------
__global__ void split_copy(const float* __restrict__ in, __nv_bfloat16* __restrict__ out,
                           long long oPl, int n) {
    int i = blockIdx.x * blockDim.x + threadIdx.x;
    if (i >= n) return;
    __nv_bfloat16 h, l; bsplit(in[i], h, l);
    out[i] = h; out[i + oPl] = l;
}

// wqr + wuk + wo in one launch
__global__ void split_misc(const float* __restrict__ wqr, const float* __restrict__ wuk,
                           const float* __restrict__ wo,
                           __nv_bfloat16* __restrict__ oqr, __nv_bfloat16* __restrict__ ouk,
                           __nv_bfloat16* __restrict__ owo,
                           long long pqr, long long puk, long long pwo) {
    int i = blockIdx.x * blockDim.x + threadIdx.x;
    if (i >= 5767168) return;
    float v; __nv_bfloat16* dst; long long pl; int j;
    if (i < 524288)       { j = i;           v = wqr[j]; dst = oqr; pl = pqr; }
    else if (i < 1572864) { j = i - 524288;  v = wuk[j]; dst = ouk; pl = puk; }
    else                  { j = i - 1572864; v = wo[j];  dst = owo; pl = pwo; }
    __nv_bfloat16 h, l; bsplit(v, h, l);
    dst[j] = h; dst[j + pl] = l;
}

__global__ void transpose_split(const float* __restrict__ in, __nv_bfloat16* __restrict__ out,
                                long long oPl, int R, int C) {
    __shared__ float tile[32][33];
    int bx = blockIdx.x * 32, by = blockIdx.y * 32;
    int tx = threadIdx.x, ty = threadIdx.y;
#pragma unroll
    for (int i = 0; i < 4; i++)
        tile[ty + i * 8][tx] = in[(long long)(by + ty + i * 8) * C + bx + tx];
    __syncthreads();
#pragma unroll
    for (int i = 0; i < 4; i++) {
        int c = bx + ty + i * 8, r = by + tx;
        __nv_bfloat16 h, l; bsplit(tile[tx][ty + i * 8], h, l);
        out[(long long)c * R + r] = h;
        out[(long long)c * R + r + oPl] = l;
    }
}

// Wall = [W_dq(512) ; W_kr(64) ; W_dkv(512) ; zero(192)]  (1280 x 2048)
__global__ void build_wcatall(const float* __restrict__ Wdq, const float* __restrict__ Wkr,
                              const float* __restrict__ Wdkv,
                              __nv_bfloat16* __restrict__ out, long long oPl) {
    int i = blockIdx.x * blockDim.x + threadIdx.x;
    if (i >= 1280 * 2048) return;
    int row = i >> 11, col = i & 2047;
    float v = 0.0f;
    if (row < 512)       v = Wdq[row * 2048 + col];
    else if (row < 576)  v = Wkr[(row - 512) * 2048 + col];
    else if (row < 1088) v = Wdkv[(row - 576) * 2048 + col];
    __nv_bfloat16 h, l; bsplit(v, h, l);
    out[i] = h; out[i + oPl] = l;
}

// ---------------- rope ----------------------------------------------------------
__global__ void rope_q_kernel(const float* __restrict__ cqr, const float* __restrict__ fc,
                              const float* __restrict__ fs, __nv_bfloat16* __restrict__ qh,
                              long long qPl) {
    int idx = blockIdx.x * blockDim.x + threadIdx.x;
    if (idx >= 4 * 1024 * 16 * 32) return;
    int j = idx & 31;
    int h = (idx >> 5) & 15;
    int t = (idx >> 9) & 1023;
    int b = idx >> 19;
    long long src = (((long long)(b * 1024 + t)) * 1024) + h * 64 + 2 * j;
    float re = cqr[src], im = cqr[src + 1];
    float c = fc[t * 32 + j], s = fs[t * 32 + j];
    float o0 = re * c - im * s, o1 = re * s + im * c;
    long long dst = (((long long)(b * 16 + h)) * 1024 + t) * 192 + 128 + 2 * j;
    __nv_bfloat16 h0, l0, h1, l1; bsplit(o0, h0, l0); bsplit(o1, h1, l1);
    qh[dst] = h0; qh[dst + qPl] = l0;
    qh[dst + 1] = h1; qh[dst + 1 + qPl] = l1;
}

__global__ void rope_k_kernel(const float* __restrict__ cqkv_f, const float* __restrict__ fc,
                              const float* __restrict__ fs, __nv_bfloat16* __restrict__ kh,
                              long long kPl) {
    int idx = blockIdx.x * blockDim.x + threadIdx.x;
    if (idx >= 4 * 1024 * 32) return;
    int j = idx & 31;
    int t = (idx >> 5) & 1023;
    int b = idx >> 15;
    long long src = ((long long)(b * 1024 + t)) * 1280 + 512 + 2 * j;
    float re = cqkv_f[src], im = cqkv_f[src + 1];
    float c = fc[t * 32 + j], s = fs[t * 32 + j];
    float o0 = re * c - im * s, o1 = re * s + im * c;
    __nv_bfloat16 h0, l0, h1, l1; bsplit(o0, h0, l0); bsplit(o1, h1, l1);
#pragma unroll
    for (int h = 0; h < 16; h++) {
        long long dst = (((long long)(b * 16 + h)) * 1024 + t) * 192 + 128 + 2 * j;
        kh[dst] = h0; kh[dst + kPl] = l0;
        kh[dst + 1] = h1; kh[dst + 1 + kPl] = l1;
    }
}

// ---------------- launcher -------------------------------------------------------
extern "C" void kernel_launch(void* const* d_in, const int* in_sizes, int n_in,
                              void* d_out, int out_size) {
    (void)in_sizes; (void)n_in; (void)out_size;
    const float* x     = (const float*)d_in[0];
    const float* W_dq  = (const float*)d_in[1];
    const float* W_uq  = (const float*)d_in[2];
    const float* W_dkv = (const float*)d_in[3];
    const float* W_uk  = (const float*)d_in[4];
    const float* W_uv  = (const float*)d_in[5];
    const float* W_o   = (const float*)d_in[6];
    const float* W_qr  = (const float*)d_in[7];
    const float* W_kr  = (const float*)d_in[8];
    const float* fc    = (const float*)d_in[9];
    const float* fs    = (const float*)d_in[10];
    float* out = (float*)d_out;

    __nv_bfloat16 *x2, *wca2, *wqr2, *wuqT2, *wuk2, *wuvT2, *wo2, *mt2;
    __nv_bfloat16 *cqkv2, *qh2, *kh2, *vt2;
    float *cqkv_f, *cqr;
    cudaGetSymbolAddress((void**)&x2,     g_x2);
    cudaGetSymbolAddress((void**)&wca2,   g_wca2);
    cudaGetSymbolAddress((void**)&wqr2,   g_wqr2);
    cudaGetSymbolAddress((void**)&wuqT2,  g_wuqT2);
    cudaGetSymbolAddress((void**)&wuk2,   g_wuk2);
    cudaGetSymbolAddress((void**)&wuvT2,  g_wuvT2);
    cudaGetSymbolAddress((void**)&wo2,    g_wo2);
    cudaGetSymbolAddress((void**)&mt2,    g_mt2);
    cudaGetSymbolAddress((void**)&cqkv2,  g_cqkv2);
    cudaGetSymbolAddress((void**)&cqkv_f, g_cqkv_f);
    cudaGetSymbolAddress((void**)&cqr,    g_cqr);
    cudaGetSymbolAddress((void**)&qh2,    g_qh2);
    cudaGetSymbolAddress((void**)&kh2,    g_kh2);
    cudaGetSymbolAddress((void**)&vt2,    g_vt2);

    const long long XPL    = 4096LL * 2048;
    const long long WCAPL  = 1280LL * 2048;
    const long long WQRPL  = 1024LL * 512;
    const long long WUQPL  = 2048LL * 512;
    const long long WUKPL  = 2048LL * 512;
    const long long WUVPL  = 512LL * 2048;
    const long long WOPL   = 2048LL * 2048;
    const long long MTPL   = 2048LL * 512;
    const long long CQKVPL = 4096LL * 1280;
    const long long HPL    = 64LL * 1024 * 192;
    const long long VTPL   = 64LL * 128 * 1024;
    const long long HZ     = 1024LL * 192;
    const long long VTZ    = 128LL * 1024;

    cudaFuncSetAttribute(gemm_t6<256, true,  true,  false>, cudaFuncAttributeMaxDynamicSharedMemorySize, GSMEM);
    cudaFuncSetAttribute(gemm_t6<128, false, true,  false>, cudaFuncAttributeMaxDynamicSharedMemorySize, GSMEM);
    cudaFuncSetAttribute(gemm_t6<256, true,  false, false>, cudaFuncAttributeMaxDynamicSharedMemorySize, GSMEM);
    cudaFuncSetAttribute(gemm_t6<256, false, true,  true >, cudaFuncAttributeMaxDynamicSharedMemorySize, GSMEM);
    cudaFuncSetAttribute(gemm_t6<256, false, true,  false>, cudaFuncAttributeMaxDynamicSharedMemorySize, GSMEM);
    cudaFuncSetAttribute(flash_attn, cudaFuncAttributeMaxDynamicSharedMemorySize, FSMEM);

    dim3 blk(256);

    // --- prep ---
    split_copy<<<(8388608 + 255) / 256, 256>>>(x, x2, XPL, 8388608);
    split_misc<<<(5767168 + 255) / 256, 256>>>(W_qr, W_uk, W_o, wqr2, wuk2, wo2,
                                               WQRPL, WUKPL, WOPL);
    transpose_split<<<dim3(64, 16), dim3(32, 8)>>>(W_uq, wuqT2, WUQPL, 512, 2048);
    transpose_split<<<dim3(16, 64), dim3(32, 8)>>>(W_uv, wuvT2, WUVPL, 2048, 512);
    build_wcatall<<<(1280 * 2048 + 255) / 256, 256>>>(W_dq, W_kr, W_dkv, wca2, WCAPL);

    // 1) cqkv (4096x1280) = x @ Wall^T   [f32 + planes]  (c_q|c_kr|c_kv)
    gemm_t6<256, true, true, false><<<148, blk, GSMEM>>>(
        x2, XPL, wca2, WCAPL, cqkv_f, cqkv2, CQKVPL,
        2048, 2048, 2048, 1280, 0, 0, 0, 0, 0, 0, 1, 0, 5, 32, 1);

    // 2) MT (2048x512) = Wo @ WuvT^T     [planes]
    gemm_t6<128, false, true, false><<<64, blk, GSMEM>>>(
        wo2, WOPL, wuvT2, WUVPL, nullptr, mt2, MTPL,
        2048, 2048, 2048, 512, 0, 0, 0, 0, 0, 0, 1, 0, 4, 16, 1);

    // 3) c_qr (4096x1024) = c_q @ W_qr^T [f32]
    gemm_t6<256, true, false, false><<<128, blk, GSMEM>>>(
        cqkv2, CQKVPL, wqr2, WQRPL, cqr, nullptr, 0,
        512, 1280, 512, 1024, 0, 0, 0, 0, 0, 0, 1, 0, 4, 32, 1);

    // 4) q per head: qh[:, 0:128] = c_q[b] @ WuqT^T  (2 heads per N-tile)
    gemm_t6<256, false, true, true><<<148, blk, GSMEM>>>(
        cqkv2, CQKVPL, wuqT2, WUQPL, nullptr, qh2, HPL,
        512, 1280, 512, 192,
        1024LL * 1280, 0, 0, 0, 16LL * HZ, 0, 1, HZ, 8, 8, 4);

    // 5) k per head: kh[:, 0:128] = c_kv[b] @ W_uk^T
    gemm_t6<256, false, true, true><<<148, blk, GSMEM>>>(
        cqkv2 + 576, CQKVPL, wuk2, WUKPL, nullptr, kh2, HPL,
        512, 1280, 512, 192,
        1024LL * 1280, 0, 0, 0, 16LL * HZ, 0, 1, HZ, 8, 8, 4);

    // 6) rope tails
    rope_q_kernel<<<8192, 256>>>(cqr, fc, fs, qh2, HPL);
    rope_k_kernel<<<512, 256>>>(cqkv_f, fc, fs, kh2, HPL);

    // 7) VT[b,h] (128x1024) = MT[h-slice] @ c_kv[b]^T   [planes]
    gemm_t6<256, false, true, false><<<148, blk, GSMEM>>>(
        mt2, MTPL, cqkv2 + 576, CQKVPL, nullptr, vt2, VTPL,
        512, 512, 1280, 1024,
        0, 128LL * 512, 1024LL * 1280, 0, 16LL * VTZ, VTZ, 16, 0, 4, 1, 64);

    // 8) fused flash attention (persistent, longest tiles first)
    flash_attn<<<148, blk, FSMEM>>>(qh2, kh2, vt2, out);
}

// round 13
// speedup vs baseline: 3.0317x; 1.0276x over previous
#include <cuda_runtime.h>
#include <cuda_bf16.h>
#include <math.h>
#include <stdint.h>

// B=4, T=1024, C=2048, NH=16, HS=128, NLQ=512, NLKV=512, DHR=64

#if !defined(__CUDA_ARCH__) || defined(__CUDA_ARCH_SPECIFIC__) || \
    defined(__CUDA_ARCH_FEAT_SM103_ALL) || defined(__CUDA_ARCH_FEAT_SM100_ALL) || \
    defined(__CUDA_ARCH_FEAT_SM101_ALL)
#define HAS_TC 1
#else
#define HAS_TC 0
#endif

// ---------------- scratch --------------------------------------------------------
__device__ __nv_bfloat16 g_x2[2][4096L * 2048];
__device__ __nv_bfloat16 g_wca2[2][1280L * 2048];     // [W_dq;W_kr;W_dkv;pad]
__device__ __nv_bfloat16 g_wqr2[2][1024L * 512];
__device__ __nv_bfloat16 g_wuqT2[2][2048L * 512];
__device__ __nv_bfloat16 g_wuk2[2][2048L * 512];
__device__ __nv_bfloat16 g_wuvT2[2][512L * 2048];
__device__ __nv_bfloat16 g_wo2[2][2048L * 2048];
__device__ __nv_bfloat16 g_mt2[2][2048L * 512];
__device__ __nv_bfloat16 g_cqkv2[2][4096L * 1280];
__device__ float         g_cqkv_f[4096L * 1280];
__device__ float         g_cqr[4096L * 1024];
__device__ __nv_bfloat16 g_qh2[2][64L * 1024 * 192];
__device__ __nv_bfloat16 g_kh2[2][64L * 1024 * 192];
__device__ __nv_bfloat16 g_vt2[2][64L * 128 * 1024];

// ---------------- PTX helpers ---------------------------------------------------
__device__ __forceinline__ uint32_t elect1() {
    uint32_t p;
    asm volatile("{\n\t.reg .pred p;\n\telect.sync _|p, 0xFFFFFFFF;\n\t"
                 "selp.b32 %0, 1, 0, p;\n\t}" : "=r"(p));
    return p;
}
__device__ __forceinline__ uint32_t s2u(const void* p) {
    uint32_t a;
    asm("{ .reg .u64 t; cvta.to.shared.u64 t, %1; cvt.u32.u64 %0, t; }" : "=r"(a) : "l"(p));
    return a;
}
#define TC_ALLOC(sm, n)  asm volatile("tcgen05.alloc.cta_group::1.sync.aligned.shared::cta.b32 [%0], %1;" :: "r"(sm), "r"(n) : "memory")
#define TC_DEALLOC(t, n) asm volatile("tcgen05.dealloc.cta_group::1.sync.aligned.b32 %0, %1;" :: "r"(t), "r"(n))
#define TC_RELINQ()      asm volatile("tcgen05.relinquish_alloc_permit.cta_group::1.sync.aligned;")
#define TC_COMMIT(mb)    asm volatile("tcgen05.commit.cta_group::1.mbarrier::arrive::one.shared::cluster.b64 [%0];" :: "r"(mb) : "memory")
#define TC_FENCE_AFTER() asm volatile("tcgen05.fence::after_thread_sync;" ::: "memory")
#define TC_FENCE_BEFORE() asm volatile("tcgen05.fence::before_thread_sync;" ::: "memory")
#define TC_WAIT_LD()     asm volatile("tcgen05.wait::ld.sync.aligned;" ::: "memory")
#define TC_WAIT_ST()     asm volatile("tcgen05.wait::st.sync.aligned;" ::: "memory")
#define FENCE_PROXY()    asm volatile("fence.proxy.async.shared::cta;" ::: "memory")
#define MB_INIT(mb, c)   asm volatile("mbarrier.init.shared.b64 [%0], %1;" :: "r"(mb), "r"(c) : "memory")
#define MB_WAIT(mb, ph) do { \
    asm volatile("{\n\t.reg .pred P1;\n\tWL_%=:\n\t" \
        "mbarrier.try_wait.parity.acquire.cta.shared::cta.b64 P1, [%0], %1, 0x989680;\n\t" \
        "@P1 bra.uni WD_%=;\n\tbra.uni WL_%=;\n\tWD_%=:\n\t}" \
        :: "r"(mb), "r"((uint32_t)(ph)) : "memory"); \
} while (0)
#define CP16(dst, src)   asm volatile("cp.async.cg.shared.global [%0], [%1], 16;" :: "r"(dst), "l"(src))
#define CP_COMMIT()      asm volatile("cp.async.commit_group;")
#define CP_WAIT(n)       asm volatile("cp.async.wait_group %0;" :: "n"(n))

#define TCLD32(r, a) \
    asm volatile("tcgen05.ld.sync.aligned.32x32b.x32.b32 " \
        "{%0,%1,%2,%3,%4,%5,%6,%7,%8,%9,%10,%11,%12,%13,%14,%15," \
        "%16,%17,%18,%19,%20,%21,%22,%23,%24,%25,%26,%27,%28,%29,%30,%31}, [%32];" \
        : "=r"((r)[0]),"=r"((r)[1]),"=r"((r)[2]),"=r"((r)[3]),"=r"((r)[4]),"=r"((r)[5]), \
          "=r"((r)[6]),"=r"((r)[7]),"=r"((r)[8]),"=r"((r)[9]),"=r"((r)[10]),"=r"((r)[11]), \
          "=r"((r)[12]),"=r"((r)[13]),"=r"((r)[14]),"=r"((r)[15]),"=r"((r)[16]),"=r"((r)[17]), \
          "=r"((r)[18]),"=r"((r)[19]),"=r"((r)[20]),"=r"((r)[21]),"=r"((r)[22]),"=r"((r)[23]), \
          "=r"((r)[24]),"=r"((r)[25]),"=r"((r)[26]),"=r"((r)[27]),"=r"((r)[28]),"=r"((r)[29]), \
          "=r"((r)[30]),"=r"((r)[31]) : "r"(a))

#define TCST32(a, r) \
    asm volatile("tcgen05.st.sync.aligned.32x32b.x32.b32 [%0], " \
        "{%1,%2,%3,%4,%5,%6,%7,%8,%9,%10,%11,%12,%13,%14,%15,%16," \
        "%17,%18,%19,%20,%21,%22,%23,%24,%25,%26,%27,%28,%29,%30,%31,%32};" \
        :: "r"(a), \
          "r"((r)[0]),"r"((r)[1]),"r"((r)[2]),"r"((r)[3]),"r"((r)[4]),"r"((r)[5]), \
          "r"((r)[6]),"r"((r)[7]),"r"((r)[8]),"r"((r)[9]),"r"((r)[10]),"r"((r)[11]), \
          "r"((r)[12]),"r"((r)[13]),"r"((r)[14]),"r"((r)[15]),"r"((r)[16]),"r"((r)[17]), \
          "r"((r)[18]),"r"((r)[19]),"r"((r)[20]),"r"((r)[21]),"r"((r)[22]),"r"((r)[23]), \
          "r"((r)[24]),"r"((r)[25]),"r"((r)[26]),"r"((r)[27]),"r"((r)[28]),"r"((r)[29]), \
          "r"((r)[30]),"r"((r)[31]) : "memory")

#if HAS_TC
__device__ __forceinline__ void mma_bf16_ss(uint32_t d, uint64_t a, uint64_t b,
                                            uint32_t idesc, bool en) {
    uint32_t e = en ? 1u : 0u;
    asm volatile("{\n\t.reg .pred p;\n\tsetp.ne.u32 p, %5, 0;\n\t"
        "tcgen05.mma.cta_group::1.kind::f16 [%0], %1, %2, %3, {%4, %4, %4, %4}, p;\n\t}"
        :: "r"(d), "l"(a), "l"(b), "r"(idesc), "r"(0u), "r"(e) : "memory");
}
#endif

#define IDESC128 0x8200490u
#define IDESC256 0x8400490u
#define DESC_BASE ((2ULL << 61) | (1ULL << 46) | (64ULL << 32) | (1ULL << 16))
__device__ __forceinline__ uint64_t mkdesc(uint32_t addr) {
    return DESC_BASE | ((uint64_t)(addr >> 4) & 0x3FFF);
}
__device__ __forceinline__ uint32_t sw128(uint32_t b) { return b ^ ((b >> 3) & 0x70); }

__device__ __forceinline__ void bsplit(float v, __nv_bfloat16& h, __nv_bfloat16& l) {
    h = __float2bfloat16_rn(v);
    l = __float2bfloat16_rn(v - __bfloat162float(h));
}

// ---------------- tcgen05 GEMM v4: persistent + cross-tile prefetch -------------
#define ET_OFF 197632
#define ET_STRIDE 68
#define GSMEM 232448

template <int NT, bool WF32, bool WB16, bool HEADC>
__global__ void __launch_bounds__(256, 1) gemm_t6(
        const __nv_bfloat16* __restrict__ A, long long aPl,
        const __nv_bfloat16* __restrict__ B, long long bPl,
        float* __restrict__ Cf, __nv_bfloat16* __restrict__ Cb, long long cPl,
        int K, int lda, int ldb, int ldc,
        long long sAq, long long sAr, long long sBq, long long sBr,
        long long sCq, long long sCr, int zdiv, long long sHC,
        int tx, int ty, int tz) {
#if HAS_TC
    constexpr int S = (NT == 128) ? 3 : 2;
    constexpr int PB = NT * 128;
    constexpr int STG = 2 * 16384 + 2 * PB;
    constexpr int BPC = NT * 8;
    constexpr int ITER = (2048 + 2 * BPC) / 256;
    constexpr uint32_t ID = (NT == 128) ? IDESC128 : IDESC256;

    extern __shared__ __align__(1024) char smem[];
    const uint32_t smb = s2u(smem);
    const uint32_t mb0 = smb + 16, mb1 = smb + 24, mb2 = smb + 32;

    const int tid = threadIdx.x;
    const int warp = tid >> 5;
    const int lane = tid & 31;
    const int WT = tx * ty * tz;
    const int nt = K >> 6;

    if (warp == 0) TC_ALLOC(smb, NT);
    if (tid == 0) { MB_INIT(mb0, 1); MB_INIT(mb1, 1); MB_INIT(mb2, 1); }
    __syncthreads();
    uint32_t tmem;
    asm volatile("ld.shared.b32 %0, [%1];" : "=r"(tmem) : "r"(smb));

    int ph0 = 0, ph1 = 0, ph2 = 0;

    auto coords = [&](int w, int& m0, int& n0, const __nv_bfloat16*& Ab,
                      const __nv_bfloat16*& Bb, long long& cbase) {
        const int xt = w % tx;
        const int rw = w / tx;
        const int yt = rw % ty;
        const int z  = rw / ty;
        m0 = yt * 128; n0 = xt * NT;
        const int zq = z / zdiv, zr = z % zdiv;
        Ab = A + (long long)zq * sAq + (long long)zr * sAr;
        Bb = B + (long long)zq * sBq + (long long)zr * sBr;
        cbase = (long long)zq * sCq + (long long)zr * sCr +
                (HEADC ? (long long)xt * (NT / 128) * sHC : 0);
    };

    auto issue_load = [&](int c, const __nv_bfloat16* Ab, const __nv_bfloat16* Bb,
                          int m0, int n0) {
        const uint32_t st = smb + 1024 + (c % S) * STG;
        const int k0 = c << 6;
#pragma unroll
        for (int i = 0; i < ITER; i++) {
            int idx = tid + i * 256;
            if (idx < 2048) {
                int plane = idx >> 10, cc = idx & 1023;
                int r = cc >> 3, cq = cc & 7;
                CP16(st + plane * 16384 + sw128(r * 128 + cq * 16),
                     Ab + (long long)plane * aPl + (long long)(m0 + r) * lda + k0 + cq * 8);
            } else {
                int j = idx - 2048;
                int plane = j / BPC, cc = j % BPC;
                int r = cc >> 3, cq = cc & 7;
                CP16(st + 32768 + plane * PB + sw128(r * 128 + cq * 16),
                     Bb + (long long)plane * bPl + (long long)(n0 + r) * ldb + k0 + cq * 8);
            }
        }
        CP_COMMIT();
    };
    auto waitmma = [&](int j) {
        int bsel = j % 3;
        if (bsel == 0)      { MB_WAIT(mb0, ph0); ph0 ^= 1; }
        else if (bsel == 1) { MB_WAIT(mb1, ph1); ph1 ^= 1; }
        else                { MB_WAIT(mb2, ph2); ph2 ^= 1; }
    };

    int m0, n0; const __nv_bfloat16 *Ab, *Bb; long long cbase;
    int w = blockIdx.x;
    if (w < WT) {                      // prefetch first tile
        coords(w, m0, n0, Ab, Bb, cbase);
        for (int c = 0; c < S - 1 && c < nt; c++) issue_load(c, Ab, Bb, m0, n0);
    }

    for (; w < WT; w += gridDim.x) {
        coords(w, m0, n0, Ab, Bb, cbase);

        for (int c = 0; c < nt; c++) {
            if (c + 1 < nt) { CP_WAIT(S - 2); } else { CP_WAIT(0); }
            __syncthreads();
            FENCE_PROXY();
            if (warp == 0 && elect1()) {
                const uint32_t st = smb + 1024 + (c % S) * STG;
                uint64_t dAh = mkdesc(st);
                uint64_t dAl = mkdesc(st + 16384);
                uint64_t dBh = mkdesc(st + 32768);
                uint64_t dBl = mkdesc(st + 32768 + PB);
#pragma unroll
                for (int k = 0; k < 4; k++)
                    mma_bf16_ss(tmem, dAh + 2 * k, dBh + 2 * k, ID, !(c == 0 && k == 0));
#pragma unroll
                for (int k = 0; k < 4; k++)
                    mma_bf16_ss(tmem, dAh + 2 * k, dBl + 2 * k, ID, true);
#pragma unroll
                for (int k = 0; k < 4; k++)
                    mma_bf16_ss(tmem, dAl + 2 * k, dBh + 2 * k, ID, true);
                TC_COMMIT(smb + 16 + 8 * (c % 3));
            }
            if (c >= 1) waitmma(c - 1);
            if (c + S - 1 < nt) issue_load(c + S - 1, Ab, Bb, m0, n0);
        }
        waitmma(nt - 1);

        // prefetch NEXT tile while epilogue runs
        if (w + gridDim.x < WT) {
            int m0n, n0n; const __nv_bfloat16 *Abn, *Bbn; long long cbn;
            coords(w + gridDim.x, m0n, n0n, Abn, Bbn, cbn);
            for (int c = 0; c < S - 1 && c < nt; c++) issue_load(c, Abn, Bbn, m0n, n0n);
        }

        // epilogue: 64-col passes through dedicated et region
        TC_FENCE_AFTER();
        float* et = (float*)(smem + ET_OFF);
#pragma unroll
        for (int p = 0; p < NT / 64; p++) {
            {
                const int rowg = warp & 3, colh = warp >> 2;
                uint32_t dr[32];
                TCLD32(dr, tmem + p * 64 + colh * 32);
                TC_WAIT_LD();
                float* q = et + (rowg * 32 + lane) * ET_STRIDE + colh * 32;
#pragma unroll
                for (int c = 0; c < 32; c++) q[c] = __uint_as_float(dr[c]);
            }
            __syncthreads();
#pragma unroll
            for (int i = 0; i < 8; i++) {
                int idx = tid + i * 256;          // 0..2047 quads
                int r = idx >> 4, qd = idx & 15;
                int gcol = p * 64 + qd * 4;
                const float* pp = et + r * ET_STRIDE + qd * 4;
                float4 v = make_float4(pp[0], pp[1], pp[2], pp[3]);
                long long hoff = (HEADC && gcol >= 128) ? sHC : 0;
                int col = HEADC ? (gcol & 127) : (n0 + gcol);
                long long off = cbase + hoff + (long long)(m0 + r) * ldc + col;
                if (WF32) *reinterpret_cast<float4*>(&Cf[off]) = v;
                if (WB16) {
                    __nv_bfloat16 hx, lx, hy, ly, hz, lz, hw, lw;
                    bsplit(v.x, hx, lx); bsplit(v.y, hy, ly);
                    bsplit(v.z, hz, lz); bsplit(v.w, hw, lw);
                    uint2 hi = make_uint2(
                        (uint32_t)__bfloat16_as_ushort(hx) | ((uint32_t)__bfloat16_as_ushort(hy) << 16),
                        (uint32_t)__bfloat16_as_ushort(hz) | ((uint32_t)__bfloat16_as_ushort(hw) << 16));
                    uint2 lo = make_uint2(
                        (uint32_t)__bfloat16_as_ushort(lx) | ((uint32_t)__bfloat16_as_ushort(ly) << 16),
                        (uint32_t)__bfloat16_as_ushort(lz) | ((uint32_t)__bfloat16_as_ushort(lw) << 16));
                    *reinterpret_cast<uint2*>(&Cb[off]) = hi;
                    *reinterpret_cast<uint2*>(&Cb[off + cPl]) = lo;
                }
            }
            __syncthreads();
        }
    }
    if (warp == 0) { TC_RELINQ(); TC_DEALLOC(tmem, NT); }
#endif
}

// ---------------- fused flash attention (persistent, boustrophedon) -------------
#define FQOFF 2048
#define FRING (FQOFF + 6 * 16384)
#define FPOFF (FRING + 2 * 32768)
#define FSMEM (FPOFF + 4 * 16384)

__global__ void __launch_bounds__(256, 1) flash_attn(
        const __nv_bfloat16* __restrict__ qh, const __nv_bfloat16* __restrict__ kh,
        const __nv_bfloat16* __restrict__ vt, float* __restrict__ out) {
#if HAS_TC
    const long long QKPL = 64LL * 1024 * 192;
    const long long VPL  = 64LL * 128 * 1024;

    extern __shared__ __align__(1024) char smem[];
    const uint32_t smb = s2u(smem);
    const uint32_t mb = smb + 16;
    float* ex = (float*)(smem + 32);

    const int tid = threadIdx.x, warp = tid >> 5, lane = tid & 31;
    const int ch = warp >> 2;
    const int row = (warp & 3) * 32 + lane;
    const int bx = blockIdx.x;

    if (warp == 0) TC_ALLOC(smb, 256);
    if (tid == 0) MB_INIT(mb, 1);
    __syncthreads();
    uint32_t tmem;
    asm volatile("ld.shared.b32 %0, [%1];" : "=r"(tmem) : "r"(smb));
    const uint32_t tS = tmem, tO = tmem + 128;

    int ph = 0;

    for (int p = 0; p < 4; p++) {
        int item = p * 148 + ((p & 1) ? (147 - bx) : bx);
        if (item >= 512) continue;
        const int mt = 7 - (item >> 6);
        const int h = item & 15;
        const int b = (item >> 4) & 3;
        const int ntile = mt + 1, m0 = mt * 128;
        const int S = 5 * ntile;
        const __nv_bfloat16* Qb = qh + (long long)(b * 16 + h) * (1024LL * 192);
        const __nv_bfloat16* Kb = kh + (long long)(b * 16 + h) * (1024LL * 192);
        const __nv_bfloat16* Vb = vt + (long long)(b * 16 + h) * (128LL * 1024);

        {
#pragma unroll
            for (int i = 0; i < 24; i++) {
                int idx = tid + i * 256;
                int cp = idx >> 10;
                int c = cp >> 1, pl = cp & 1;
                int cidx = idx & 1023, rr = cidx >> 3, cc = cidx & 7;
                const __nv_bfloat16* src = Qb + (long long)pl * QKPL +
                    (long long)(m0 + rr) * 192 + c * 64 + cc * 8;
                CP16(smb + FQOFF + cp * 16384 + sw128(rr * 128 + cc * 16), src);
            }
            CP_COMMIT();
        }
        auto issue_slot = [&](int s) {
            int t = s / 5, r = s % 5;
            uint32_t dst = smb + FRING + (s & 1) * 32768;
#pragma unroll
            for (int i = 0; i < 8; i++) {
                int idx = tid + i * 256;
                int pl = idx >> 10, cidx = idx & 1023, rr = cidx >> 3, cc = cidx & 7;
                const __nv_bfloat16* src;
                if (r < 3)
                    src = Kb + (long long)pl * QKPL + (long long)(t * 128 + rr) * 192 + r * 64 + cc * 8;
                else
                    src = Vb + (long long)pl * VPL + (long long)rr * 1024 + t * 128 + (r - 3) * 64 + cc * 8;
                CP16(dst + pl * 16384 + sw128(rr * 128 + cc * 16), src);
            }
            CP_COMMIT();
        };
        issue_slot(0);
        if (S > 1) issue_slot(1);

        float m_old = -INFINITY, lsum = 0.0f;
        int sc = 0;

        for (int t = 0; t < ntile; t++) {
            for (int c = 0; c < 3; c++) {
                if (sc + 1 < S) { CP_WAIT(1); } else { CP_WAIT(0); }
                __syncthreads();
                FENCE_PROXY();
                if (warp == 0 && elect1()) {
                    uint32_t st = smb + FRING + (sc & 1) * 32768;
                    uint64_t dQh = mkdesc(smb + FQOFF + (c * 2 + 0) * 16384);
                    uint64_t dQl = mkdesc(smb + FQOFF + (c * 2 + 1) * 16384);
                    uint64_t dKh = mkdesc(st);
                    uint64_t dKl = mkdesc(st + 16384);
#pragma unroll
                    for (int k = 0; k < 4; k++)
                        mma_bf16_ss(tS, dQh + 2 * k, dKh + 2 * k, IDESC128, !(c == 0 && k == 0));
#pragma unroll
                    for (int k = 0; k < 4; k++)
                        mma_bf16_ss(tS, dQh + 2 * k, dKl + 2 * k, IDESC128, true);
#pragma unroll
                    for (int k = 0; k < 4; k++)
                        mma_bf16_ss(tS, dQl + 2 * k, dKh + 2 * k, IDESC128, true);
                    TC_COMMIT(mb);
                }
                MB_WAIT(mb, ph); ph ^= 1;
                if (sc + 2 < S) issue_slot(sc + 2);
                sc++;
            }
            TC_FENCE_AFTER();
            float sv[64];
            {
                uint32_t r0[32], r1[32];
                TCLD32(r0, tS + ch * 64);
                TCLD32(r1, tS + ch * 64 + 32);
                TC_WAIT_LD();
                const float scale = 0.07216878364870323f;
#pragma unroll
                for (int j = 0; j < 32; j++) {
                    sv[j] = __uint_as_float(r0[j]) * scale;
                    sv[32 + j] = __uint_as_float(r1[j]) * scale;
                }
            }
            if (t == mt) {
#pragma unroll
                for (int j = 0; j < 64; j++)
                    if (ch * 64 + j > row) sv[j] = -INFINITY;
            }
            float pmax = -INFINITY;
#pragma unroll
            for (int j = 0; j < 64; j++) pmax = fmaxf(pmax, sv[j]);
            __syncthreads();
            ex[warp * 32 + lane] = pmax;
            __syncthreads();
            float m_new = fmaxf(m_old, fmaxf(pmax, ex[(warp ^ 4) * 32 + lane]));
            float alpha = __expf(m_old - m_new);
            bool norescale = (t == 0) || __all_sync(0xffffffffu, m_new == m_old);
            float psum = 0.0f;
#pragma unroll
            for (int j = 0; j < 64; j++) { sv[j] = __expf(sv[j] - m_new); psum += sv[j]; }
            __syncthreads();
            ex[warp * 32 + lane] = psum;
            __syncthreads();
            lsum = lsum * alpha + psum + ex[(warp ^ 4) * 32 + lane];
            m_old = m_new;
            {
                uint32_t baseh = smb + FPOFF + (ch * 2 + 0) * 16384;
                uint32_t basel = smb + FPOFF + (ch * 2 + 1) * 16384;
#pragma unroll
                for (int j = 0; j < 8; j++) {
                    uint32_t h4[4], l4[4];
#pragma unroll
                    for (int q = 0; q < 4; q++) {
                        float a = sv[8 * j + 2 * q], bq = sv[8 * j + 2 * q + 1];
                        __nv_bfloat16 ah, al, bh, bl;
                        bsplit(a, ah, al); bsplit(bq, bh, bl);
                        h4[q] = ((uint32_t)__bfloat16_as_ushort(bh) << 16) | __bfloat16_as_ushort(ah);
                        l4[q] = ((uint32_t)__bfloat16_as_ushort(bl) << 16) | __bfloat16_as_ushort(al);
                    }
                    uint32_t off = sw128(row * 128 + 16 * j);
                    asm volatile("st.shared.v4.b32 [%0], {%1,%2,%3,%4};"
                        :: "r"(baseh + off), "r"(h4[0]), "r"(h4[1]), "r"(h4[2]), "r"(h4[3]) : "memory");
                    asm volatile("st.shared.v4.b32 [%0], {%1,%2,%3,%4};"
                        :: "r"(basel + off), "r"(l4[0]), "r"(l4[1]), "r"(l4[2]), "r"(l4[3]) : "memory");
                }
            }
            if (!norescale) {
                uint32_t r0[32], r1[32];
                TCLD32(r0, tO + ch * 64);
                TCLD32(r1, tO + ch * 64 + 32);
                TC_WAIT_LD();
#pragma unroll
                for (int j = 0; j < 32; j++) {
                    r0[j] = __float_as_uint(__uint_as_float(r0[j]) * alpha);
                    r1[j] = __float_as_uint(__uint_as_float(r1[j]) * alpha);
                }
                TCST32(tO + ch * 64, r0);
                TCST32(tO + ch * 64 + 32, r1);
                TC_WAIT_ST();
            }
            FENCE_PROXY();
            TC_FENCE_BEFORE();
            __syncthreads();
            for (int vc = 0; vc < 2; vc++) {
                if (sc + 1 < S) { CP_WAIT(1); } else { CP_WAIT(0); }
                __syncthreads();
                FENCE_PROXY();
                if (warp == 0 && elect1()) {
                    TC_FENCE_AFTER();
                    uint32_t st = smb + FRING + (sc & 1) * 32768;
                    uint64_t dPh = mkdesc(smb + FPOFF + (vc * 2 + 0) * 16384);
                    uint64_t dPl = mkdesc(smb + FPOFF + (vc * 2 + 1) * 16384);
                    uint64_t dVh = mkdesc(st);
                    uint64_t dVl = mkdesc(st + 16384);
#pragma unroll
                    for (int k = 0; k < 4; k++)
                        mma_bf16_ss(tO, dPh + 2 * k, dVh + 2 * k, IDESC128, !(t == 0 && vc == 0 && k == 0));
#pragma unroll
                    for (int k = 0; k < 4; k++)
                        mma_bf16_ss(tO, dPh + 2 * k, dVl + 2 * k, IDESC128, true);
#pragma unroll
                    for (int k = 0; k < 4; k++)
                        mma_bf16_ss(tO, dPl + 2 * k, dVh + 2 * k, IDESC128, true);
                    TC_COMMIT(mb);
                }
                MB_WAIT(mb, ph); ph ^= 1;
                if (sc + 2 < S) issue_slot(sc + 2);
                sc++;
            }
        }
        TC_FENCE_AFTER();
        {
            uint32_t r0[32], r1[32];
            TCLD32(r0, tO + ch * 64);
            TCLD32(r1, tO + ch * 64 + 32);
            TC_WAIT_LD();
            float inv = 1.0f / lsum;
            float* op = out + ((long long)(b * 1024 + m0 + row)) * 2048 + h * 128 + ch * 64;
#pragma unroll
            for (int j = 0; j < 8; j++) {
                float4 v = make_float4(__uint_as_float(r0[4*j]) * inv, __uint_as_float(r0[4*j+1]) * inv,
                                       __uint_as_float(r0[4*j+2]) * inv, __uint_as_float(r0[4*j+3]) * inv);
                *reinterpret_cast<float4*>(op + 4 * j) = v;
                float4 w = make_float4(__uint_as_float(r1[4*j]) * inv, __uint_as_float(r1[4*j+1]) * inv,
                                       __uint_as_float(r1[4*j+2]) * inv, __uint_as_float(r1[4*j+3]) * inv);
                *reinterpret_cast<float4*>(op + 32 + 4 * j) = w;
            }
        }
        __syncthreads();
    }
    if (warp == 0) { TC_RELINQ(); TC_DEALLOC(tmem, 256); }
#endif
}

// ---------------- consolidated prep ----------------------------------------------
__global__ void prep_all(const float* __restrict__ x, const float* __restrict__ wqr,
                         const float* __restrict__ wuk, const float* __restrict__ wo,
                         const float* __restrict__ Wdq, const float* __restrict__ Wkr,
                         const float* __restrict__ Wdkv,
                         __nv_bfloat16* __restrict__ ox, __nv_bfloat16* __restrict__ oqr,
                         __nv_bfloat16* __restrict__ ouk, __nv_bfloat16* __restrict__ owo,
                         __nv_bfloat16* __restrict__ owca,
                         long long px, long long pqr, long long puk, long long pwo,
                         long long pwca) {
    long long i = (long long)blockIdx.x * blockDim.x + threadIdx.x;
    float v; __nv_bfloat16* dst; long long pl, j;
    if (i < 8388608)       { j = i;            v = x[j];   dst = ox;  pl = px; }
    else if (i < 8912896)  { j = i - 8388608;  v = wqr[j]; dst = oqr; pl = pqr; }
    else if (i < 9961472)  { j = i - 8912896;  v = wuk[j]; dst = ouk; pl = puk; }
    else if (i < 14155776) { j = i - 9961472;  v = wo[j];  dst = owo; pl = pwo; }
    else {
        j = i - 14155776;                       // 1280*2048 wcat
        int row = (int)(j >> 11), col = (int)(j & 2047);
        v = 0.0f;
        if (row < 512)       v = Wdq[row * 2048 + col];
        else if (row < 576)  v = Wkr[(row - 512) * 2048 + col];
        else if (row < 1088) v = Wdkv[(row - 576) * 2048 + col];
        dst = owca; pl = pwca;
    }
    __nv_bfloat16 h, l; bsplit(v, h, l);
    dst[j] = h; dst[j + pl] = l;
}

// merged transposes: blocks 0..1023 = W_uq (512x2048), 1024..2047 = W_uv (2048x512)
__global__ void transpose_all(const float* __restrict__ wuq, const float* __restrict__ wuv,
                              __nv_bfloat16* __restrict__ oq, __nv_bfloat16* __restrict__ ov,
                              long long pq, long long pv) {
    __shared__ float tile[32][33];
    const float* in; __nv_bfloat16* out; long long oPl; int R, C, bx, by;
    int bid = blockIdx.x;
    if (bid < 1024) { in = wuq; out = oq; oPl = pq; R = 512;  C = 2048;
                      bx = (bid & 63) * 32; by = (bid >> 6) * 32; }
    else            { bid -= 1024; in = wuv; out = ov; oPl = pv; R = 2048; C = 512;
                      bx = (bid & 15) * 32; by = (bid >> 4) * 32; }
    int tx = threadIdx.x, ty = threadIdx.y;
#pragma unroll
    for (int i = 0; i < 4; i++)
        tile[ty + i * 8][tx] = in[(long long)(by + ty + i * 8) * C + bx + tx];
    __syncthreads();
#pragma unroll
    for (int i = 0; i < 4; i++) {
        int c = bx + ty + i * 8, r = by + tx;
        __nv_bfloat16 h, l; bsplit(tile[tx][ty + i * 8], h, l);
        out[(long long)c * R + r] = h;
        out[(long long)c * R + r + oPl] = l;
    }
}

// ---------------- rope ----------------------------------------------------------
__global__ void rope_q_kernel(const float* __restrict__ cqr, const float* __restrict__ fc,
                              const float* __restrict__ fs, __nv_bfloat16* __restrict__ qh,
                              long long qPl) {
    int idx = blockIdx.x * blockDim.x + threadIdx.x;
    if (idx >= 4 * 1024 * 16 * 32) return;
    int j = idx & 31;
    int h = (idx >> 5) & 15;
    int t = (idx >> 9) & 1023;
    int b = idx >> 19;
    long long src = (((long long)(b * 1024 + t)) * 1024) + h * 64 + 2 * j;
    float re = cqr[src], im = cqr[src + 1];
    float c = fc[t * 32 + j], s = fs[t * 32 + j];
    float o0 = re * c - im * s, o1 = re * s + im * c;
    long long dst = (((long long)(b * 16 + h)) * 1024 + t) * 192 + 128 + 2 * j;
    __nv_bfloat16 h0, l0, h1, l1; bsplit(o0, h0, l0); bsplit(o1, h1, l1);
    qh[dst] = h0; qh[dst + qPl] = l0;
    qh[dst + 1] = h1; qh[dst + 1 + qPl] = l1;
}

__global__ void rope_k_kernel(const float* __restrict__ cqkv_f, const float* __restrict__ fc,
                              const float* __restrict__ fs, __nv_bfloat16* __restrict__ kh,
                              long long kPl) {
    int idx = blockIdx.x * blockDim.x + threadIdx.x;
    if (idx >= 4 * 1024 * 32) return;
    int j = idx & 31;
    int t = (idx >> 5) & 1023;
    int b = idx >> 15;
    long long src = ((long long)(b * 1024 + t)) * 1280 + 512 + 2 * j;
    float re = cqkv_f[src], im = cqkv_f[src + 1];
    float c = fc[t * 32 + j], s = fs[t * 32 + j];
    float o0 = re * c - im * s, o1 = re * s + im * c;
    __nv_bfloat16 h0, l0, h1, l1; bsplit(o0, h0, l0); bsplit(o1, h1, l1);
#pragma unroll
    for (int h = 0; h < 16; h++) {
        long long dst = (((long long)(b * 16 + h)) * 1024 + t) * 192 + 128 + 2 * j;
        kh[dst] = h0; kh[dst + kPl] = l0;
        kh[dst + 1] = h1; kh[dst + 1 + kPl] = l1;
    }
}

// ---------------- launcher -------------------------------------------------------
extern "C" void kernel_launch(void* const* d_in, const int* in_sizes, int n_in,
                              void* d_out, int out_size) {
    (void)in_sizes; (void)n_in; (void)out_size;
    const float* x     = (const float*)d_in[0];
    const float* W_dq  = (const float*)d_in[1];
    const float* W_uq  = (const float*)d_in[2];
    const float* W_dkv = (const float*)d_in[3];
    const float* W_uk  = (const float*)d_in[4];
    const float* W_uv  = (const float*)d_in[5];
    const float* W_o   = (const float*)d_in[6];
    const float* W_qr  = (const float*)d_in[7];
    const float* W_kr  = (const float*)d_in[8];
    const float* fc    = (const float*)d_in[9];
    const float* fs    = (const float*)d_in[10];
    float* out = (float*)d_out;

    __nv_bfloat16 *x2, *wca2, *wqr2, *wuqT2, *wuk2, *wuvT2, *wo2, *mt2;
    __nv_bfloat16 *cqkv2, *qh2, *kh2, *vt2;
    float *cqkv_f, *cqr;
    cudaGetSymbolAddress((void**)&x2,     g_x2);
    cudaGetSymbolAddress((void**)&wca2,   g_wca2);
    cudaGetSymbolAddress((void**)&wqr2,   g_wqr2);
    cudaGetSymbolAddress((void**)&wuqT2,  g_wuqT2);
    cudaGetSymbolAddress((void**)&wuk2,   g_wuk2);
    cudaGetSymbolAddress((void**)&wuvT2,  g_wuvT2);
    cudaGetSymbolAddress((void**)&wo2,    g_wo2);
    cudaGetSymbolAddress((void**)&mt2,    g_mt2);
    cudaGetSymbolAddress((void**)&cqkv2,  g_cqkv2);
    cudaGetSymbolAddress((void**)&cqkv_f, g_cqkv_f);
    cudaGetSymbolAddress((void**)&cqr,    g_cqr);
    cudaGetSymbolAddress((void**)&qh2,    g_qh2);
    cudaGetSymbolAddress((void**)&kh2,    g_kh2);
    cudaGetSymbolAddress((void**)&vt2,    g_vt2);

    const long long XPL    = 4096LL * 2048;
    const long long WCAPL  = 1280LL * 2048;
    const long long WQRPL  = 1024LL * 512;
    const long long WUQPL  = 2048LL * 512;
    const long long WUKPL  = 2048LL * 512;
    const long long WUVPL  = 512LL * 2048;
    const long long WOPL   = 2048LL * 2048;
    const long long MTPL   = 2048LL * 512;
    const long long CQKVPL = 4096LL * 1280;
    const long long HPL    = 64LL * 1024 * 192;
    const long long VTPL   = 64LL * 128 * 1024;
    const long long HZ     = 1024LL * 192;
    const long long VTZ    = 128LL * 1024;

    cudaFuncSetAttribute(gemm_t6<256, true,  true,  false>, cudaFuncAttributeMaxDynamicSharedMemorySize, GSMEM);
    cudaFuncSetAttribute(gemm_t6<128, false, true,  false>, cudaFuncAttributeMaxDynamicSharedMemorySize, GSMEM);
    cudaFuncSetAttribute(gemm_t6<256, true,  false, false>, cudaFuncAttributeMaxDynamicSharedMemorySize, GSMEM);
    cudaFuncSetAttribute(gemm_t6<256, false, true,  true >, cudaFuncAttributeMaxDynamicSharedMemorySize, GSMEM);
    cudaFuncSetAttribute(gemm_t6<256, false, true,  false>, cudaFuncAttributeMaxDynamicSharedMemorySize, GSMEM);
    cudaFuncSetAttribute(flash_attn, cudaFuncAttributeMaxDynamicSharedMemorySize, FSMEM);

    dim3 blk(256);

    // --- prep (2 launches) ---
    prep_all<<<65536, 256>>>(x, W_qr, W_uk, W_o, W_dq, W_kr, W_dkv,
                             x2, wqr2, wuk2, wo2, wca2,
                             XPL, WQRPL, WUKPL, WOPL, WCAPL);
    transpose_all<<<2048, dim3(32, 8)>>>(W_uq, W_uv, wuqT2, wuvT2, WUQPL, WUVPL);

    // 1) cqkv (4096x1280) = x @ Wall^T   [f32 + planes]
    gemm_t6<256, true, true, false><<<148, blk, GSMEM>>>(
        x2, XPL, wca2, WCAPL, cqkv_f, cqkv2, CQKVPL,
        2048, 2048, 2048, 1280, 0, 0, 0, 0, 0, 0, 1, 0, 5, 32, 1);

    // 2) MT (2048x512) = Wo @ WuvT^T     [planes]
    gemm_t6<128, false, true, false><<<64, blk, GSMEM>>>(
        wo2, WOPL, wuvT2, WUVPL, nullptr, mt2, MTPL,
        2048, 2048, 2048, 512, 0, 0, 0, 0, 0, 0, 1, 0, 4, 16, 1);

    // 3) c_qr (4096x1024) = c_q @ W_qr^T [f32]
    gemm_t6<256, true, false, false><<<128, blk, GSMEM>>>(
        cqkv2, CQKVPL, wqr2, WQRPL, cqr, nullptr, 0,
        512, 1280, 512, 1024, 0, 0, 0, 0, 0, 0, 1, 0, 4, 32, 1);

    // 4) q per head: qh[:, 0:128] = c_q[b] @ WuqT^T
    gemm_t6<256, false, true, true><<<148, blk, GSMEM>>>(
        cqkv2, CQKVPL, wuqT2, WUQPL, nullptr, qh2, HPL,
        512, 1280, 512, 192,
        1024LL * 1280, 0, 0, 0, 16LL * HZ, 0, 1, HZ, 8, 8, 4);

    // 5) k per head: kh[:, 0:128] = c_kv[b] @ W_uk^T
    gemm_t6<256, false, true, true><<<148, blk, GSMEM>>>(
        cqkv2 + 576, CQKVPL, wuk2, WUKPL, nullptr, kh2, HPL,
        512, 1280, 512, 192,
        1024LL * 1280, 0, 0, 0, 16LL * HZ, 0, 1, HZ, 8, 8, 4);

    // 6) rope tails
    rope_q_kernel<<<8192, 256>>>(cqr, fc, fs, qh2, HPL);
    rope_k_kernel<<<512, 256>>>(cqkv_f, fc, fs, kh2, HPL);

    // 7) VT[b,h] (128x1024) = MT[h-slice] @ c_kv[b]^T   [planes]
    gemm_t6<256, false, true, false><<<148, blk, GSMEM>>>(
        mt2, MTPL, cqkv2 + 576, CQKVPL, nullptr, vt2, VTPL,
        512, 512, 1280, 1024,
        0, 128LL * 512, 1024LL * 1280, 0, 16LL * VTZ, VTZ, 16, 0, 4, 1, 64);

    // 8) fused flash attention (persistent, longest tiles first)
    flash_attn<<<148, blk, FSMEM>>>(qh2, kh2, vt2, out);
}

// round 14
// speedup vs baseline: 3.4280x; 1.1307x over previous
#include <cuda_runtime.h>
#include <cuda_bf16.h>
#include <math.h>
#include <stdint.h>

// B=4, T=1024, C=2048, NH=16, HS=128, NLQ=512, NLKV=512, DHR=64

#if !defined(__CUDA_ARCH__) || defined(__CUDA_ARCH_SPECIFIC__) || \
    defined(__CUDA_ARCH_FEAT_SM103_ALL) || defined(__CUDA_ARCH_FEAT_SM100_ALL) || \
    defined(__CUDA_ARCH_FEAT_SM101_ALL)
#define HAS_TC 1
#else
#define HAS_TC 0
#endif

// ---------------- scratch --------------------------------------------------------
__device__ __nv_bfloat16 g_x2[2][4096L * 2048];
__device__ __nv_bfloat16 g_wca2[2][1280L * 2048];     // [W_dq;W_kr;W_dkv;pad]
__device__ __nv_bfloat16 g_wqr2[2][1024L * 512];
__device__ __nv_bfloat16 g_wuqT2[2][2048L * 512];
__device__ __nv_bfloat16 g_wuk2[2][2048L * 512];
__device__ __nv_bfloat16 g_wuvT2[2][512L * 2048];
__device__ __nv_bfloat16 g_wo2[2][2048L * 2048];
__device__ __nv_bfloat16 g_mt2[2][2048L * 512];
__device__ __nv_bfloat16 g_cqkv2[2][4096L * 1280];
__device__ float         g_mtp[2L * 2048 * 512];      // MT split-K partials
__device__ float         g_cqr[4096L * 1024];
__device__ __nv_bfloat16 g_qh2[2][64L * 1024 * 192];
__device__ __nv_bfloat16 g_kh2[2][64L * 1024 * 192];
__device__ __nv_bfloat16 g_vt2[2][64L * 128 * 1024];

// ---------------- PTX helpers ---------------------------------------------------
__device__ __forceinline__ uint32_t elect1() {
    uint32_t p;
    asm volatile("{\n\t.reg .pred p;\n\telect.sync _|p, 0xFFFFFFFF;\n\t"
                 "selp.b32 %0, 1, 0, p;\n\t}" : "=r"(p));
    return p;
}
__device__ __forceinline__ uint32_t s2u(const void* p) {
    uint32_t a;
    asm("{ .reg .u64 t; cvta.to.shared.u64 t, %1; cvt.u32.u64 %0, t; }" : "=r"(a) : "l"(p));
    return a;
}
#define TC_ALLOC(sm, n)  asm volatile("tcgen05.alloc.cta_group::1.sync.aligned.shared::cta.b32 [%0], %1;" :: "r"(sm), "r"(n) : "memory")
#define TC_DEALLOC(t, n) asm volatile("tcgen05.dealloc.cta_group::1.sync.aligned.b32 %0, %1;" :: "r"(t), "r"(n))
#define TC_RELINQ()      asm volatile("tcgen05.relinquish_alloc_permit.cta_group::1.sync.aligned;")
#define TC_COMMIT(mb)    asm volatile("tcgen05.commit.cta_group::1.mbarrier::arrive::one.shared::cluster.b64 [%0];" :: "r"(mb) : "memory")
#define TC_FENCE_AFTER() asm volatile("tcgen05.fence::after_thread_sync;" ::: "memory")
#define TC_FENCE_BEFORE() asm volatile("tcgen05.fence::before_thread_sync;" ::: "memory")
#define TC_WAIT_LD()     asm volatile("tcgen05.wait::ld.sync.aligned;" ::: "memory")
#define TC_WAIT_ST()     asm volatile("tcgen05.wait::st.sync.aligned;" ::: "memory")
#define FENCE_PROXY()    asm volatile("fence.proxy.async.shared::cta;" ::: "memory")
#define MB_INIT(mb, c)   asm volatile("mbarrier.init.shared.b64 [%0], %1;" :: "r"(mb), "r"(c) : "memory")
#define MB_WAIT(mb, ph) do { \
    asm volatile("{\n\t.reg .pred P1;\n\tWL_%=:\n\t" \
        "mbarrier.try_wait.parity.acquire.cta.shared::cta.b64 P1, [%0], %1, 0x989680;\n\t" \
        "@P1 bra.uni WD_%=;\n\tbra.uni WL_%=;\n\tWD_%=:\n\t}" \
        :: "r"(mb), "r"((uint32_t)(ph)) : "memory"); \
} while (0)
#define CP16(dst, src)   asm volatile("cp.async.cg.shared.global [%0], [%1], 16;" :: "r"(dst), "l"(src))
#define CP_COMMIT()      asm volatile("cp.async.commit_group;")
#define CP_WAIT(n)       asm volatile("cp.async.wait_group %0;" :: "n"(n))

#define TCLD32(r, a) \
    asm volatile("tcgen05.ld.sync.aligned.32x32b.x32.b32 " \
        "{%0,%1,%2,%3,%4,%5,%6,%7,%8,%9,%10,%11,%12,%13,%14,%15," \
        "%16,%17,%18,%19,%20,%21,%22,%23,%24,%25,%26,%27,%28,%29,%30,%31}, [%32];" \
        : "=r"((r)[0]),"=r"((r)[1]),"=r"((r)[2]),"=r"((r)[3]),"=r"((r)[4]),"=r"((r)[5]), \
          "=r"((r)[6]),"=r"((r)[7]),"=r"((r)[8]),"=r"((r)[9]),"=r"((r)[10]),"=r"((r)[11]), \
          "=r"((r)[12]),"=r"((r)[13]),"=r"((r)[14]),"=r"((r)[15]),"=r"((r)[16]),"=r"((r)[17]), \
          "=r"((r)[18]),"=r"((r)[19]),"=r"((r)[20]),"=r"((r)[21]),"=r"((r)[22]),"=r"((r)[23]), \
          "=r"((r)[24]),"=r"((r)[25]),"=r"((r)[26]),"=r"((r)[27]),"=r"((r)[28]),"=r"((r)[29]), \
          "=r"((r)[30]),"=r"((r)[31]) : "r"(a))

#define TCST32(a, r) \
    asm volatile("tcgen05.st.sync.aligned.32x32b.x32.b32 [%0], " \
        "{%1,%2,%3,%4,%5,%6,%7,%8,%9,%10,%11,%12,%13,%14,%15,%16," \
        "%17,%18,%19,%20,%21,%22,%23,%24,%25,%26,%27,%28,%29,%30,%31,%32};" \
        :: "r"(a), \
          "r"((r)[0]),"r"((r)[1]),"r"((r)[2]),"r"((r)[3]),"r"((r)[4]),"r"((r)[5]), \
          "r"((r)[6]),"r"((r)[7]),"r"((r)[8]),"r"((r)[9]),"r"((r)[10]),"r"((r)[11]), \
          "r"((r)[12]),"r"((r)[13]),"r"((r)[14]),"r"((r)[15]),"r"((r)[16]),"r"((r)[17]), \
          "r"((r)[18]),"r"((r)[19]),"r"((r)[20]),"r"((r)[21]),"r"((r)[22]),"r"((r)[23]), \
          "r"((r)[24]),"r"((r)[25]),"r"((r)[26]),"r"((r)[27]),"r"((r)[28]),"r"((r)[29]), \
          "r"((r)[30]),"r"((r)[31]) : "memory")

#if HAS_TC
__device__ __forceinline__ void mma_bf16_ss(uint32_t d, uint64_t a, uint64_t b,
                                            uint32_t idesc, bool en) {
    uint32_t e = en ? 1u : 0u;
    asm volatile("{\n\t.reg .pred p;\n\tsetp.ne.u32 p, %5, 0;\n\t"
        "tcgen05.mma.cta_group::1.kind::f16 [%0], %1, %2, %3, {%4, %4, %4, %4}, p;\n\t}"
        :: "r"(d), "l"(a), "l"(b), "r"(idesc), "r"(0u), "r"(e) : "memory");
}
__device__ __forceinline__ void mma_bf16_ts(uint32_t d, uint32_t a, uint64_t b,
                                            uint32_t idesc, bool en) {
    uint32_t e = en ? 1u : 0u;
    asm volatile("{\n\t.reg .pred p;\n\tsetp.ne.u32 p, %5, 0;\n\t"
        "tcgen05.mma.cta_group::1.kind::f16 [%0], [%1], %2, %3, {%4, %4, %4, %4}, p;\n\t}"
        :: "r"(d), "r"(a), "l"(b), "r"(idesc), "r"(0u), "r"(e) : "memory");
}
#endif

#define IDESC128 0x8200490u
#define IDESC256 0x8400490u
#define DESC_BASE ((2ULL << 61) | (1ULL << 46) | (64ULL << 32) | (1ULL << 16))
__device__ __forceinline__ uint64_t mkdesc(uint32_t addr) {
    return DESC_BASE | ((uint64_t)(addr >> 4) & 0x3FFF);
}
__device__ __forceinline__ uint32_t sw128(uint32_t b) { return b ^ ((b >> 3) & 0x70); }

__device__ __forceinline__ void bsplit(float v, __nv_bfloat16& h, __nv_bfloat16& l) {
    h = __float2bfloat16_rn(v);
    l = __float2bfloat16_rn(v - __bfloat162float(h));
}
__device__ __forceinline__ uint32_t bpack(__nv_bfloat16 a, __nv_bfloat16 b) {
    return (uint32_t)__bfloat16_as_ushort(a) | ((uint32_t)__bfloat16_as_ushort(b) << 16);
}

// ---------------- tcgen05 GEMM: persistent + cross-tile prefetch (R13) ----------
#define ET_OFF 197632
#define ET_STRIDE 68
#define GSMEM 232448

template <int NT, bool WF32, bool WB16, bool HEADC>
__global__ void __launch_bounds__(256, 1) gemm_t6(
        const __nv_bfloat16* __restrict__ A, long long aPl,
        const __nv_bfloat16* __restrict__ B, long long bPl,
        float* __restrict__ Cf, __nv_bfloat16* __restrict__ Cb, long long cPl,
        int K, int lda, int ldb, int ldc,
        long long sAq, long long sAr, long long sBq, long long sBr,
        long long sCq, long long sCr, int zdiv, long long sHC,
        int tx, int ty, int tz) {
#if HAS_TC
    constexpr int S = (NT == 128) ? 3 : 2;
    constexpr int PB = NT * 128;
    constexpr int STG = 2 * 16384 + 2 * PB;
    constexpr int BPC = NT * 8;
    constexpr int ITER = (2048 + 2 * BPC) / 256;
    constexpr uint32_t ID = (NT == 128) ? IDESC128 : IDESC256;

    extern __shared__ __align__(1024) char smem[];
    const uint32_t smb = s2u(smem);
    const uint32_t mb0 = smb + 16, mb1 = smb + 24, mb2 = smb + 32;

    const int tid = threadIdx.x;
    const int warp = tid >> 5;
    const int lane = tid & 31;
    const int WT = tx * ty * tz;
    const int nt = K >> 6;

    if (warp == 0) TC_ALLOC(smb, NT);
    if (tid == 0) { MB_INIT(mb0, 1); MB_INIT(mb1, 1); MB_INIT(mb2, 1); }
    __syncthreads();
    uint32_t tmem;
    asm volatile("ld.shared.b32 %0, [%1];" : "=r"(tmem) : "r"(smb));

    int ph0 = 0, ph1 = 0, ph2 = 0;

    auto coords = [&](int w, int& m0, int& n0, const __nv_bfloat16*& Ab,
                      const __nv_bfloat16*& Bb, long long& cbase) {
        const int xt = w % tx;
        const int rw = w / tx;
        const int yt = rw % ty;
        const int z  = rw / ty;
        m0 = yt * 128; n0 = xt * NT;
        const int zq = z / zdiv, zr = z % zdiv;
        Ab = A + (long long)zq * sAq + (long long)zr * sAr;
        Bb = B + (long long)zq * sBq + (long long)zr * sBr;
        cbase = (long long)zq * sCq + (long long)zr * sCr +
                (HEADC ? (long long)xt * (NT / 128) * sHC : 0);
    };

    auto issue_load = [&](int c, const __nv_bfloat16* Ab, const __nv_bfloat16* Bb,
                          int m0, int n0) {
        const uint32_t st = smb + 1024 + (c % S) * STG;
        const int k0 = c << 6;
#pragma unroll
        for (int i = 0; i < ITER; i++) {
            int idx = tid + i * 256;
            if (idx < 2048) {
                int plane = idx >> 10, cc = idx & 1023;
                int r = cc >> 3, cq = cc & 7;
                CP16(st + plane * 16384 + sw128(r * 128 + cq * 16),
                     Ab + (long long)plane * aPl + (long long)(m0 + r) * lda + k0 + cq * 8);
            } else {
                int j = idx - 2048;
                int plane = j / BPC, cc = j % BPC;
                int r = cc >> 3, cq = cc & 7;
                CP16(st + 32768 + plane * PB + sw128(r * 128 + cq * 16),
                     Bb + (long long)plane * bPl + (long long)(n0 + r) * ldb + k0 + cq * 8);
            }
        }
        CP_COMMIT();
    };
    auto waitmma = [&](int j) {
        int bsel = j % 3;
        if (bsel == 0)      { MB_WAIT(mb0, ph0); ph0 ^= 1; }
        else if (bsel == 1) { MB_WAIT(mb1, ph1); ph1 ^= 1; }
        else                { MB_WAIT(mb2, ph2); ph2 ^= 1; }
    };

    int m0, n0; const __nv_bfloat16 *Ab, *Bb; long long cbase;
    int w = blockIdx.x;
    if (w < WT) {
        coords(w, m0, n0, Ab, Bb, cbase);
        for (int c = 0; c < S - 1 && c < nt; c++) issue_load(c, Ab, Bb, m0, n0);
    }

    for (; w < WT; w += gridDim.x) {
        coords(w, m0, n0, Ab, Bb, cbase);

        for (int c = 0; c < nt; c++) {
            if (c + 1 < nt) { CP_WAIT(S - 2); } else { CP_WAIT(0); }
            __syncthreads();
            FENCE_PROXY();
            if (warp == 0 && elect1()) {
                const uint32_t st = smb + 1024 + (c % S) * STG;
                uint64_t dAh = mkdesc(st);
                uint64_t dAl = mkdesc(st + 16384);
                uint64_t dBh = mkdesc(st + 32768);
                uint64_t dBl = mkdesc(st + 32768 + PB);
#pragma unroll
                for (int k = 0; k < 4; k++)
                    mma_bf16_ss(tmem, dAh + 2 * k, dBh + 2 * k, ID, !(c == 0 && k == 0));
#pragma unroll
                for (int k = 0; k < 4; k++)
                    mma_bf16_ss(tmem, dAh + 2 * k, dBl + 2 * k, ID, true);
#pragma unroll
                for (int k = 0; k < 4; k++)
                    mma_bf16_ss(tmem, dAl + 2 * k, dBh + 2 * k, ID, true);
                TC_COMMIT(smb + 16 + 8 * (c % 3));
            }
            if (c >= 1) waitmma(c - 1);
            if (c + S - 1 < nt) issue_load(c + S - 1, Ab, Bb, m0, n0);
        }
        waitmma(nt - 1);

        if (w + gridDim.x < WT) {
            int m0n, n0n; const __nv_bfloat16 *Abn, *Bbn; long long cbn;
            coords(w + gridDim.x, m0n, n0n, Abn, Bbn, cbn);
            for (int c = 0; c < S - 1 && c < nt; c++) issue_load(c, Abn, Bbn, m0n, n0n);
        }

        TC_FENCE_AFTER();
        float* et = (float*)(smem + ET_OFF);
#pragma unroll
        for (int p = 0; p < NT / 64; p++) {
            {
                const int rowg = warp & 3, colh = warp >> 2;
                uint32_t dr[32];
                TCLD32(dr, tmem + p * 64 + colh * 32);
                TC_WAIT_LD();
                float* q = et + (rowg * 32 + lane) * ET_STRIDE + colh * 32;
#pragma unroll
                for (int c = 0; c < 32; c++) q[c] = __uint_as_float(dr[c]);
            }
            __syncthreads();
#pragma unroll
            for (int i = 0; i < 8; i++) {
                int idx = tid + i * 256;
                int r = idx >> 4, qd = idx & 15;
                int gcol = p * 64 + qd * 4;
                const float* pp = et + r * ET_STRIDE + qd * 4;
                float4 v = make_float4(pp[0], pp[1], pp[2], pp[3]);
                long long hoff = (HEADC && gcol >= 128) ? sHC : 0;
                int col = HEADC ? (gcol & 127) : (n0 + gcol);
                long long off = cbase + hoff + (long long)(m0 + r) * ldc + col;
                if (WF32) *reinterpret_cast<float4*>(&Cf[off]) = v;
                if (WB16) {
                    __nv_bfloat16 hx, lx, hy, ly, hz, lz, hw, lw;
                    bsplit(v.x, hx, lx); bsplit(v.y, hy, ly);
                    bsplit(v.z, hz, lz); bsplit(v.w, hw, lw);
                    uint2 hi = make_uint2(bpack(hx, hy), bpack(hz, hw));
                    uint2 lo = make_uint2(bpack(lx, ly), bpack(lz, lw));
                    *reinterpret_cast<uint2*>(&Cb[off]) = hi;
                    *reinterpret_cast<uint2*>(&Cb[off + cPl]) = lo;
                }
            }
            __syncthreads();
        }
    }
    if (warp == 0) { TC_RELINQ(); TC_DEALLOC(tmem, NT); }
#endif
}

// ---------------- flash v2: 3-slot ring, lag-1 waits, P in TMEM -----------------
// TMEM: S cols 0-127, O cols 128-255, P hi 256-319, P lo 320-383 (alloc 512).
#define FQOFF 2048
#define FRING (FQOFF + 6 * 16384)     // 100352
#define FSMEM (FRING + 3 * 32768)     // 198656

__global__ void __launch_bounds__(256, 1) flash_attn(
        const __nv_bfloat16* __restrict__ qh, const __nv_bfloat16* __restrict__ kh,
        const __nv_bfloat16* __restrict__ vt, float* __restrict__ out) {
#if HAS_TC
    const long long QKPL = 64LL * 1024 * 192;
    const long long VPL  = 64LL * 128 * 1024;

    extern __shared__ __align__(1024) char smem[];
    const uint32_t smb = s2u(smem);
    const uint32_t mb0 = smb + 16, mb1 = smb + 24;
    float* ex = (float*)(smem + 32);

    const int tid = threadIdx.x, warp = tid >> 5, lane = tid & 31;
    const int ch = warp >> 2;
    const int row = (warp & 3) * 32 + lane;
    const int bx = blockIdx.x;

    if (warp == 0) TC_ALLOC(smb, 512);
    if (tid == 0) { MB_INIT(mb0, 1); MB_INIT(mb1, 1); }
    __syncthreads();
    uint32_t tmem;
    asm volatile("ld.shared.b32 %0, [%1];" : "=r"(tmem) : "r"(smb));
    const uint32_t tS = tmem, tO = tmem + 128, tP = tmem + 256;

    int ph0 = 0, ph1 = 0;
    auto waitmb = [&](int j) {
        if (j & 1) { MB_WAIT(mb1, ph1); ph1 ^= 1; }
        else       { MB_WAIT(mb0, ph0); ph0 ^= 1; }
    };

    for (int p = 0; p < 4; p++) {
        int item = p * 148 + ((p & 1) ? (147 - bx) : bx);
        if (item >= 512) continue;
        const int mt = 7 - (item >> 6);
        const int h = item & 15;
        const int b = (item >> 4) & 3;
        const int ntile = mt + 1, m0 = mt * 128;
        const int S = 5 * ntile;
        const __nv_bfloat16* Qb = qh + (long long)(b * 16 + h) * (1024LL * 192);
        const __nv_bfloat16* Kb = kh + (long long)(b * 16 + h) * (1024LL * 192);
        const __nv_bfloat16* Vb = vt + (long long)(b * 16 + h) * (128LL * 1024);

        {
#pragma unroll
            for (int i = 0; i < 24; i++) {
                int idx = tid + i * 256;
                int cp = idx >> 10;
                int c = cp >> 1, pl = cp & 1;
                int cidx = idx & 1023, rr = cidx >> 3, cc = cidx & 7;
                const __nv_bfloat16* src = Qb + (long long)pl * QKPL +
                    (long long)(m0 + rr) * 192 + c * 64 + cc * 8;
                CP16(smb + FQOFF + cp * 16384 + sw128(rr * 128 + cc * 16), src);
            }
            CP_COMMIT();
        }
        auto issue_slot = [&](int s) {
            int t = s / 5, r = s % 5;
            uint32_t dst = smb + FRING + (s % 3) * 32768;
#pragma unroll
            for (int i = 0; i < 8; i++) {
                int idx = tid + i * 256;
                int pl = idx >> 10, cidx = idx & 1023, rr = cidx >> 3, cc = cidx & 7;
                const __nv_bfloat16* src;
                if (r < 3)
                    src = Kb + (long long)pl * QKPL + (long long)(t * 128 + rr) * 192 + r * 64 + cc * 8;
                else
                    src = Vb + (long long)pl * VPL + (long long)rr * 1024 + t * 128 + (r - 3) * 64 + cc * 8;
                CP16(dst + pl * 16384 + sw128(rr * 128 + cc * 16), src);
            }
            CP_COMMIT();
        };
        issue_slot(0);
        if (S > 1) issue_slot(1);

        float m_old = -INFINITY, lsum = 0.0f;
        int sc = 0, waited = -1;

        for (int t = 0; t < ntile; t++) {
            // ---- QK chunks (lag-1) ----
            for (int c = 0; c < 3; c++) {
                if (sc + 1 < S) { CP_WAIT(1); } else { CP_WAIT(0); }
                __syncthreads();
                FENCE_PROXY();
                if (warp == 0 && elect1()) {
                    uint32_t st = smb + FRING + (sc % 3) * 32768;
                    uint64_t dQh = mkdesc(smb + FQOFF + (c * 2 + 0) * 16384);
                    uint64_t dQl = mkdesc(smb + FQOFF + (c * 2 + 1) * 16384);
                    uint64_t dKh = mkdesc(st);
                    uint64_t dKl = mkdesc(st + 16384);
#pragma unroll
                    for (int k = 0; k < 4; k++)
                        mma_bf16_ss(tS, dQh + 2 * k, dKh + 2 * k, IDESC128, !(c == 0 && k == 0));
#pragma unroll
                    for (int k = 0; k < 4; k++)
                        mma_bf16_ss(tS, dQh + 2 * k, dKl + 2 * k, IDESC128, true);
#pragma unroll
                    for (int k = 0; k < 4; k++)
                        mma_bf16_ss(tS, dQl + 2 * k, dKh + 2 * k, IDESC128, true);
                    TC_COMMIT((sc & 1) ? mb1 : mb0);
                }
                if (sc - 1 > waited) { waitmb(sc - 1); waited = sc - 1; }
                if (sc + 2 < S) issue_slot(sc + 2);
                sc++;
            }
            // drain last QK before reading S
            if (sc - 1 > waited) { waitmb(sc - 1); waited = sc - 1; }
            TC_FENCE_AFTER();

            float sv[64];
            {
                uint32_t r0[32], r1[32];
                TCLD32(r0, tS + ch * 64);
                TCLD32(r1, tS + ch * 64 + 32);
                TC_WAIT_LD();
                const float scale = 0.07216878364870323f;
#pragma unroll
                for (int j = 0; j < 32; j++) {
                    sv[j] = __uint_as_float(r0[j]) * scale;
                    sv[32 + j] = __uint_as_float(r1[j]) * scale;
                }
            }
            if (t == mt) {
#pragma unroll
                for (int j = 0; j < 64; j++)
                    if (ch * 64 + j > row) sv[j] = -INFINITY;
            }
            float pmax = -INFINITY;
#pragma unroll
            for (int j = 0; j < 64; j++) pmax = fmaxf(pmax, sv[j]);
            __syncthreads();
            ex[warp * 32 + lane] = pmax;
            __syncthreads();
            float m_new = fmaxf(m_old, fmaxf(pmax, ex[(warp ^ 4) * 32 + lane]));
            float alpha = __expf(m_old - m_new);
            bool norescale = (t == 0) || __all_sync(0xffffffffu, m_new == m_old);
            float psum = 0.0f;
#pragma unroll
            for (int j = 0; j < 64; j++) { sv[j] = __expf(sv[j] - m_new); psum += sv[j]; }
            __syncthreads();
            ex[warp * 32 + lane] = psum;
            __syncthreads();
            lsum = lsum * alpha + psum + ex[(warp ^ 4) * 32 + lane];
            m_old = m_new;

            // P -> TMEM (hi cols 256+ch*32, lo 320+ch*32)
            {
                uint32_t hw[32], lw[32];
#pragma unroll
                for (int j = 0; j < 32; j++) {
                    __nv_bfloat16 ah, al, bh, bl;
                    bsplit(sv[2 * j], ah, al);
                    bsplit(sv[2 * j + 1], bh, bl);
                    hw[j] = bpack(ah, bh);
                    lw[j] = bpack(al, bl);
                }
                TCST32(tP + ch * 32, hw);
                TCST32(tP + 64 + ch * 32, lw);
            }
            if (!norescale) {
                uint32_t r0[32], r1[32];
                TCLD32(r0, tO + ch * 64);
                TCLD32(r1, tO + ch * 64 + 32);
                TC_WAIT_LD();
#pragma unroll
                for (int j = 0; j < 32; j++) {
                    r0[j] = __float_as_uint(__uint_as_float(r0[j]) * alpha);
                    r1[j] = __float_as_uint(__uint_as_float(r1[j]) * alpha);
                }
                TCST32(tO + ch * 64, r0);
                TCST32(tO + ch * 64 + 32, r1);
            }
            TC_WAIT_ST();
            FENCE_PROXY();
            TC_FENCE_BEFORE();
            __syncthreads();

            // ---- PV chunks (TS-mode, lag-1) ----
            for (int vc = 0; vc < 2; vc++) {
                if (sc + 1 < S) { CP_WAIT(1); } else { CP_WAIT(0); }
                __syncthreads();
                FENCE_PROXY();
                if (warp == 0 && elect1()) {
                    TC_FENCE_AFTER();
                    uint32_t st = smb + FRING + (sc % 3) * 32768;
                    uint32_t aH = tP + vc * 32;
                    uint32_t aL = tP + 64 + vc * 32;
                    uint64_t dVh = mkdesc(st);
                    uint64_t dVl = mkdesc(st + 16384);
#pragma unroll
                    for (int k = 0; k < 4; k++)
                        mma_bf16_ts(tO, aH + 8 * k, dVh + 2 * k, IDESC128, !(t == 0 && vc == 0 && k == 0));
#pragma unroll
                    for (int k = 0; k < 4; k++)
                        mma_bf16_ts(tO, aH + 8 * k, dVl + 2 * k, IDESC128, true);
#pragma unroll
                    for (int k = 0; k < 4; k++)
                        mma_bf16_ts(tO, aL + 8 * k, dVh + 2 * k, IDESC128, true);
                    TC_COMMIT((sc & 1) ? mb1 : mb0);
                }
                if (sc - 1 > waited) { waitmb(sc - 1); waited = sc - 1; }
                if (sc + 2 < S) issue_slot(sc + 2);
                sc++;
            }
        }
        if (sc - 1 > waited) { waitmb(sc - 1); waited = sc - 1; }
        TC_FENCE_AFTER();
        {
            uint32_t r0[32], r1[32];
            TCLD32(r0, tO + ch * 64);
            TCLD32(r1, tO + ch * 64 + 32);
            TC_WAIT_LD();
            float inv = 1.0f / lsum;
            float* op = out + ((long long)(b * 1024 + m0 + row)) * 2048 + h * 128 + ch * 64;
#pragma unroll
            for (int j = 0; j < 8; j++) {
                float4 v = make_float4(__uint_as_float(r0[4*j]) * inv, __uint_as_float(r0[4*j+1]) * inv,
                                       __uint_as_float(r0[4*j+2]) * inv, __uint_as_float(r0[4*j+3]) * inv);
                *reinterpret_cast<float4*>(op + 4 * j) = v;
                float4 w = make_float4(__uint_as_float(r1[4*j]) * inv, __uint_as_float(r1[4*j+1]) * inv,
                                       __uint_as_float(r1[4*j+2]) * inv, __uint_as_float(r1[4*j+3]) * inv);
                *reinterpret_cast<float4*>(op + 32 + 4 * j) = w;
            }
        }
        __syncthreads();
    }
    if (warp == 0) { TC_RELINQ(); TC_DEALLOC(tmem, 512); }
#endif
}

// ---------------- vectorized prep ------------------------------------------------
__global__ void prep_all4(const float* __restrict__ x, const float* __restrict__ wqr,
                          const float* __restrict__ wuk, const float* __restrict__ wo,
                          const float* __restrict__ Wdq, const float* __restrict__ Wkr,
                          const float* __restrict__ Wdkv,
                          __nv_bfloat16* __restrict__ ox, __nv_bfloat16* __restrict__ oqr,
                          __nv_bfloat16* __restrict__ ouk, __nv_bfloat16* __restrict__ owo,
                          __nv_bfloat16* __restrict__ owca,
                          long long px, long long pqr, long long puk, long long pwo,
                          long long pwca) {
    long long i4 = (long long)blockIdx.x * blockDim.x + threadIdx.x;
    if (i4 >= 4194304) return;
    float4 v; __nv_bfloat16* dst; long long pl, j;
    if (i4 < 2097152)      { j = i4 * 4; v = reinterpret_cast<const float4*>(x)[i4]; dst = ox; pl = px; }
    else if (i4 < 2228224) { long long k = i4 - 2097152; j = k * 4;
                             v = reinterpret_cast<const float4*>(wqr)[k]; dst = oqr; pl = pqr; }
    else if (i4 < 2490368) { long long k = i4 - 2228224; j = k * 4;
                             v = reinterpret_cast<const float4*>(wuk)[k]; dst = ouk; pl = puk; }
    else if (i4 < 3538944) { long long k = i4 - 2490368; j = k * 4;
                             v = reinterpret_cast<const float4*>(wo)[k]; dst = owo; pl = pwo; }
    else {
        long long k = i4 - 3538944; j = k * 4;
        int rw = (int)(j >> 11), col = (int)(j & 2047);
        if (rw < 512)       v = *reinterpret_cast<const float4*>(&Wdq[rw * 2048 + col]);
        else if (rw < 576)  v = *reinterpret_cast<const float4*>(&Wkr[(rw - 512) * 2048 + col]);
        else if (rw < 1088) v = *reinterpret_cast<const float4*>(&Wdkv[(rw - 576) * 2048 + col]);
        else                v = make_float4(0.f, 0.f, 0.f, 0.f);
        dst = owca; pl = pwca;
    }
    __nv_bfloat16 h0, l0, h1, l1, h2, l2, h3, l3;
    bsplit(v.x, h0, l0); bsplit(v.y, h1, l1); bsplit(v.z, h2, l2); bsplit(v.w, h3, l3);
    *reinterpret_cast<uint2*>(&dst[j]) = make_uint2(bpack(h0, h1), bpack(h2, h3));
    *reinterpret_cast<uint2*>(&dst[j + pl]) = make_uint2(bpack(l0, l1), bpack(l2, l3));
}

__global__ void transpose_all(const float* __restrict__ wuq, const float* __restrict__ wuv,
                              __nv_bfloat16* __restrict__ oq, __nv_bfloat16* __restrict__ ov,
                              long long pq, long long pv) {
    __shared__ float tile[32][33];
    const float* in; __nv_bfloat16* out; long long oPl; int R, C, bx, by;
    int bid = blockIdx.x;
    if (bid < 1024) { in = wuq; out = oq; oPl = pq; R = 512;  C = 2048;
                      bx = (bid & 63) * 32; by = (bid >> 6) * 32; }
    else            { bid -= 1024; in = wuv; out = ov; oPl = pv; R = 2048; C = 512;
                      bx = (bid & 15) * 32; by = (bid >> 4) * 32; }
    int tx = threadIdx.x, ty = threadIdx.y;
#pragma unroll
    for (int i = 0; i < 4; i++)
        tile[ty + i * 8][tx] = in[(long long)(by + ty + i * 8) * C + bx + tx];
    __syncthreads();
#pragma unroll
    for (int i = 0; i < 4; i++) {
        int c = bx + ty + i * 8, r = by + tx;
        __nv_bfloat16 h, l; bsplit(tile[tx][ty + i * 8], h, l);
        out[(long long)c * R + r] = h;
        out[(long long)c * R + r + oPl] = l;
    }
}

__global__ void reduce_mt(const float* __restrict__ p, __nv_bfloat16* __restrict__ out,
                          long long oPl) {
    int i = blockIdx.x * blockDim.x + threadIdx.x;
    if (i >= 262144) return;
    float4 a = reinterpret_cast<const float4*>(p)[i];
    float4 b = reinterpret_cast<const float4*>(p + 1048576)[i];
    a.x += b.x; a.y += b.y; a.z += b.z; a.w += b.w;
    __nv_bfloat16 h0, l0, h1, l1, h2, l2, h3, l3;
    bsplit(a.x, h0, l0); bsplit(a.y, h1, l1); bsplit(a.z, h2, l2); bsplit(a.w, h3, l3);
    long long j = (long long)i * 4;
    *reinterpret_cast<uint2*>(&out[j]) = make_uint2(bpack(h0, h1), bpack(h2, h3));
    *reinterpret_cast<uint2*>(&out[j + oPl]) = make_uint2(bpack(l0, l1), bpack(l2, l3));
}

// ---------------- rope ----------------------------------------------------------
__global__ void rope_q_kernel(const float* __restrict__ cqr, const float* __restrict__ fc,
                              const float* __restrict__ fs, __nv_bfloat16* __restrict__ qh,
                              long long qPl) {
    int idx = blockIdx.x * blockDim.x + threadIdx.x;
    if (idx >= 4 * 1024 * 16 * 32) return;
    int j = idx & 31;
    int h = (idx >> 5) & 15;
    int t = (idx >> 9) & 1023;
    int b = idx >> 19;
    long long src = (((long long)(b * 1024 + t)) * 1024) + h * 64 + 2 * j;
    float re = cqr[src], im = cqr[src + 1];
    float c = fc[t * 32 + j], s = fs[t * 32 + j];
    float o0 = re * c - im * s, o1 = re * s + im * c;
    long long dst = (((long long)(b * 16 + h)) * 1024 + t) * 192 + 128 + 2 * j;
    __nv_bfloat16 h0, l0, h1, l1; bsplit(o0, h0, l0); bsplit(o1, h1, l1);
    qh[dst] = h0; qh[dst + qPl] = l0;
    qh[dst + 1] = h1; qh[dst + 1 + qPl] = l1;
}

__global__ void rope_k_kernel(const __nv_bfloat16* __restrict__ cqkv2, long long cPl,
                              const float* __restrict__ fc, const float* __restrict__ fs,
                              __nv_bfloat16* __restrict__ kh, long long kPl) {
    int idx = blockIdx.x * blockDim.x + threadIdx.x;
    if (idx >= 4 * 1024 * 32) return;
    int j = idx & 31;
    int t = (idx >> 5) & 1023;
    int b = idx >> 15;
    long long src = ((long long)(b * 1024 + t)) * 1280 + 512 + 2 * j;
    float re = __bfloat162float(cqkv2[src]) + __bfloat162float(cqkv2[src + cPl]);
    float im = __bfloat162float(cqkv2[src + 1]) + __bfloat162float(cqkv2[src + 1 + cPl]);
    float c = fc[t * 32 + j], s = fs[t * 32 + j];
    float o0 = re * c - im * s, o1 = re * s + im * c;
    __nv_bfloat16 h0, l0, h1, l1; bsplit(o0, h0, l0); bsplit(o1, h1, l1);
#pragma unroll
    for (int h = 0; h < 16; h++) {
        long long dst = (((long long)(b * 16 + h)) * 1024 + t) * 192 + 128 + 2 * j;
        kh[dst] = h0; kh[dst + kPl] = l0;
        kh[dst + 1] = h1; kh[dst + 1 + kPl] = l1;
    }
}

// ---------------- launcher -------------------------------------------------------
extern "C" void kernel_launch(void* const* d_in, const int* in_sizes, int n_in,
                              void* d_out, int out_size) {
    (void)in_sizes; (void)n_in; (void)out_size;
    const float* x     = (const float*)d_in[0];
    const float* W_dq  = (const float*)d_in[1];
    const float* W_uq  = (const float*)d_in[2];
    const float* W_dkv = (const float*)d_in[3];
    const float* W_uk  = (const float*)d_in[4];
    const float* W_uv  = (const float*)d_in[5];
    const float* W_o   = (const float*)d_in[6];
    const float* W_qr  = (const float*)d_in[7];
    const float* W_kr  = (const float*)d_in[8];
    const float* fc    = (const float*)d_in[9];
    const float* fs    = (const float*)d_in[10];
    float* out = (float*)d_out;

    __nv_bfloat16 *x2, *wca2, *wqr2, *wuqT2, *wuk2, *wuvT2, *wo2, *mt2;
    __nv_bfloat16 *cqkv2, *qh2, *kh2, *vt2;
    float *mtp, *cqr;
    cudaGetSymbolAddress((void**)&x2,     g_x2);
    cudaGetSymbolAddress((void**)&wca2,   g_wca2);
    cudaGetSymbolAddress((void**)&wqr2,   g_wqr2);
    cudaGetSymbolAddress((void**)&wuqT2,  g_wuqT2);
    cudaGetSymbolAddress((void**)&wuk2,   g_wuk2);
    cudaGetSymbolAddress((void**)&wuvT2,  g_wuvT2);
    cudaGetSymbolAddress((void**)&wo2,    g_wo2);
    cudaGetSymbolAddress((void**)&mt2,    g_mt2);
    cudaGetSymbolAddress((void**)&cqkv2,  g_cqkv2);
    cudaGetSymbolAddress((void**)&mtp,    g_mtp);
    cudaGetSymbolAddress((void**)&cqr,    g_cqr);
    cudaGetSymbolAddress((void**)&qh2,    g_qh2);
    cudaGetSymbolAddress((void**)&kh2,    g_kh2);
    cudaGetSymbolAddress((void**)&vt2,    g_vt2);

    const long long XPL    = 4096LL * 2048;
    const long long WCAPL  = 1280LL * 2048;
    const long long WQRPL  = 1024LL * 512;
    const long long WUQPL  = 2048LL * 512;
    const long long WUKPL  = 2048LL * 512;
    const long long WUVPL  = 512LL * 2048;
    const long long WOPL   = 2048LL * 2048;
    const long long MTPL   = 2048LL * 512;
    const long long CQKVPL = 4096LL * 1280;
    const long long HPL    = 64LL * 1024 * 192;
    const long long VTPL   = 64LL * 128 * 1024;
    const long long HZ     = 1024LL * 192;
    const long long VTZ    = 128LL * 1024;

    cudaFuncSetAttribute(gemm_t6<256, false, true,  false>, cudaFuncAttributeMaxDynamicSharedMemorySize, GSMEM);
    cudaFuncSetAttribute(gemm_t6<128, true,  false, false>, cudaFuncAttributeMaxDynamicSharedMemorySize, GSMEM);
    cudaFuncSetAttribute(gemm_t6<256, true,  false, false>, cudaFuncAttributeMaxDynamicSharedMemorySize, GSMEM);
    cudaFuncSetAttribute(gemm_t6<256, false, true,  true >, cudaFuncAttributeMaxDynamicSharedMemorySize, GSMEM);
    cudaFuncSetAttribute(flash_attn, cudaFuncAttributeMaxDynamicSharedMemorySize, FSMEM);

    dim3 blk(256);

    // --- prep (2 launches) ---
    prep_all4<<<16384, 256>>>(x, W_qr, W_uk, W_o, W_dq, W_kr, W_dkv,
                              x2, wqr2, wuk2, wo2, wca2,
                              XPL, WQRPL, WUKPL, WOPL, WCAPL);
    transpose_all<<<2048, dim3(32, 8)>>>(W_uq, W_uv, wuqT2, wuvT2, WUQPL, WUVPL);

    // 1) cqkv (4096x1280) = x @ Wall^T   [planes only]
    gemm_t6<256, false, true, false><<<148, blk, GSMEM>>>(
        x2, XPL, wca2, WCAPL, nullptr, cqkv2, CQKVPL,
        2048, 2048, 2048, 1280, 0, 0, 0, 0, 0, 0, 1, 0, 5, 32, 1);

    // 2) MT split-K x2: partials, then reduce -> planes
    gemm_t6<128, true, false, false><<<128, blk, GSMEM>>>(
        wo2, WOPL, wuvT2, WUVPL, mtp, nullptr, 0,
        1024, 2048, 2048, 512,
        0, 1024, 0, 1024, 0, 1048576LL, 2, 0, 4, 16, 2);
    reduce_mt<<<1024, 256>>>(mtp, mt2, MTPL);

    // 3) c_qr (4096x1024) = c_q @ W_qr^T [f32]
    gemm_t6<256, true, false, false><<<128, blk, GSMEM>>>(
        cqkv2, CQKVPL, wqr2, WQRPL, cqr, nullptr, 0,
        512, 1280, 512, 1024, 0, 0, 0, 0, 0, 0, 1, 0, 4, 32, 1);

    // 4) q per head: qh[:, 0:128] = c_q[b] @ WuqT^T
    gemm_t6<256, false, true, true><<<148, blk, GSMEM>>>(
        cqkv2, CQKVPL, wuqT2, WUQPL, nullptr, qh2, HPL,
        512, 1280, 512, 192,
        1024LL * 1280, 0, 0, 0, 16LL * HZ, 0, 1, HZ, 8, 8, 4);

    // 5) k per head: kh[:, 0:128] = c_kv[b] @ W_uk^T
    gemm_t6<256, false, true, true><<<148, blk, GSMEM>>>(
        cqkv2 + 576, CQKVPL, wuk2, WUKPL, nullptr, kh2, HPL,
        512, 1280, 512, 192,
        1024LL * 1280, 0, 0, 0, 16LL * HZ, 0, 1, HZ, 8, 8, 4);

    // 6) rope tails
    rope_q_kernel<<<8192, 256>>>(cqr, fc, fs, qh2, HPL);
    rope_k_kernel<<<512, 256>>>(cqkv2, CQKVPL, fc, fs, kh2, HPL);

    // 7) VT[b,h] (128x1024) = MT[h-slice] @ c_kv[b]^T
    gemm_t6<256, false, true, false><<<148, blk, GSMEM>>>(
        mt2, MTPL, cqkv2 + 576, CQKVPL, nullptr, vt2, VTPL,
        512, 512, 1280, 1024,
        0, 128LL * 512, 1024LL * 1280, 0, 16LL * VTZ, VTZ, 16, 0, 4, 1, 64);

    // 8) fused flash attention
    flash_attn<<<148, blk, FSMEM>>>(qh2, kh2, vt2, out);
}